// round 1
// baseline (speedup 1.0000x reference)
#include <cuda_runtime.h>

typedef unsigned long long ULL;

static constexpr int B_ = 8;
static constexpr int N_ = 2048;
static constexpr int F_ = 64;
static constexpr float ALPHA_ = 0.2f;
static constexpr float NEG_INF_ = -9000000000000000.0f;

static constexpr int TI = 32;   // rows per block (attn)
static constexpr int TJ = 64;   // j-chunk
static constexpr int NTH = 256; // threads per block (attn)
static constexpr int RPW = 4;   // rows per warp

// scratch (no cudaMalloc allowed)
__device__ float g_h[B_ * N_ * F_];
__device__ float g_s1[B_ * N_];
__device__ float g_s2[B_ * N_];

__device__ __forceinline__ ULL pack2(float a, float b) {
    ULL r; asm("mov.b64 %0, {%1,%2};" : "=l"(r) : "f"(a), "f"(b)); return r;
}
__device__ __forceinline__ float2 unpack2(ULL v) {
    float2 r; asm("mov.b64 {%0,%1}, %2;" : "=f"(r.x), "=f"(r.y) : "l"(v)); return r;
}
__device__ __forceinline__ void ffma2(ULL& acc, ULL p, ULL h) {
    asm("fma.rn.f32x2 %0, %1, %2, %0;" : "+l"(acc) : "l"(p), "l"(h));
}
__device__ __forceinline__ ULL fmul2(ULL a, ULL b) {
    ULL r; asm("mul.rn.f32x2 %0, %1, %2;" : "=l"(r) : "l"(a), "l"(b)); return r;
}

// ---------------------------------------------------------------------------
// Kernel 1: h = x @ W ; s1 = h . a1 ; s2 = h . a2
// block = 1024 threads = 16 rows x 64 f
// ---------------------------------------------------------------------------
__global__ void __launch_bounds__(1024) prep_kernel(
    const float* __restrict__ x, const float* __restrict__ W,
    const float* __restrict__ a)
{
    __shared__ float W_s[F_ * F_];
    __shared__ float x_s[16][F_];
    __shared__ float red[16][2][2];

    int t = threadIdx.x;
    int tx = t & 63;
    int ty = t >> 6;
    int row0 = blockIdx.x * 16;
    int row = row0 + ty;

    #pragma unroll
    for (int k = 0; k < 4; ++k) W_s[t + k * 1024] = W[t + k * 1024];
    x_s[ty][tx] = x[(size_t)row * F_ + tx];
    __syncthreads();

    float h = 0.f;
    #pragma unroll
    for (int k = 0; k < F_; ++k) h = fmaf(x_s[ty][k], W_s[k * F_ + tx], h);

    g_h[(size_t)row * F_ + tx] = h;

    float v1 = h * a[tx];
    float v2 = h * a[F_ + tx];
    #pragma unroll
    for (int off = 16; off; off >>= 1) {
        v1 += __shfl_xor_sync(0xffffffffu, v1, off);
        v2 += __shfl_xor_sync(0xffffffffu, v2, off);
    }
    if ((tx & 31) == 0) { red[ty][tx >> 5][0] = v1; red[ty][tx >> 5][1] = v2; }
    __syncthreads();
    if (tx == 0) {
        g_s1[row] = red[ty][0][0] + red[ty][1][0];
        g_s2[row] = red[ty][0][1] + red[ty][1][1];
    }
}

// ---------------------------------------------------------------------------
// Kernel 2: fused masked-softmax attention + h' = att @ h + elu, flash-style.
// Grid: (B*N)/TI blocks, 256 threads = 8 warps x 4 rows each.
// Per j-chunk of 64: lanes compute p (j-parallel, online softmax per row),
// store duplicated-packed p to smem, then rank-64 f32x2 update of fp32 accs.
// ---------------------------------------------------------------------------
__global__ void __launch_bounds__(NTH, 4) attn_kernel(
    const int* __restrict__ adj, float* __restrict__ out)
{
    __shared__ __align__(16) float  h_s[TJ * F_];
    __shared__ float                s2_s[TJ];
    __shared__ __align__(16) float2 pp_s[NTH / 32][TJ][RPW];

    int t = threadIdx.x;
    int w = t >> 5;
    int lane = t & 31;
    int i0 = blockIdx.x * TI;         // global row base; 32 | 2048 so single batch
    int b = i0 >> 11;                 // / 2048
    int ibase = i0 + w * RPW;

    float s1v[RPW], m[RPW], l[RPW];
    ULL acc[RPW];
    #pragma unroll
    for (int r = 0; r < RPW; ++r) {
        s1v[r] = g_s1[ibase + r];
        m[r] = NEG_INF_;
        l[r] = 0.f;
        acc[r] = 0ull;
    }

    const float* hb  = g_h  + (size_t)b * N_ * F_;
    const float* s2b = g_s2 + (size_t)b * N_;

    for (int jc = 0; jc < N_; jc += TJ) {
        __syncthreads();
        {
            const float4* src = reinterpret_cast<const float4*>(hb + (size_t)jc * F_);
            float4* dst = reinterpret_cast<float4*>(h_s);
            #pragma unroll
            for (int k = 0; k < (TJ * F_ / 4) / NTH; ++k)
                dst[t + k * NTH] = src[t + k * NTH];
            if (t < TJ) s2_s[t] = s2b[jc + t];
        }
        __syncthreads();

        float s2a = s2_s[lane];
        float s2c = s2_s[lane + 32];

        #pragma unroll
        for (int r = 0; r < RPW; ++r) {
            const int* ap = adj + (size_t)(ibase + r) * N_ + jc;
            int a0 = ap[lane];
            int a1 = ap[lane + 32];
            float e0 = s1v[r] + s2a;
            e0 = (e0 > 0.f) ? e0 : ALPHA_ * e0;
            e0 = (a0 > 0) ? e0 : NEG_INF_;
            float e1 = s1v[r] + s2c;
            e1 = (e1 > 0.f) ? e1 : ALPHA_ * e1;
            e1 = (a1 > 0) ? e1 : NEG_INF_;

            float cm = fmaxf(e0, e1);
            #pragma unroll
            for (int off = 16; off; off >>= 1)
                cm = fmaxf(cm, __shfl_xor_sync(0xffffffffu, cm, off));

            float mn = fmaxf(m[r], cm);
            float sc = __expf(m[r] - mn);        // m==mn==NEG_INF -> exp(0)=1, later wiped
            float p0 = __expf(e0 - mn);
            float p1 = __expf(e1 - mn);
            float ps = p0 + p1;
            #pragma unroll
            for (int off = 16; off; off >>= 1)
                ps += __shfl_xor_sync(0xffffffffu, ps, off);

            l[r] = l[r] * sc + ps;
            m[r] = mn;
            acc[r] = fmul2(acc[r], pack2(sc, sc));

            pp_s[w][lane][r]      = make_float2(p0, p0);
            pp_s[w][lane + 32][r] = make_float2(p1, p1);
        }
        __syncwarp();

        const ULL* hrow = reinterpret_cast<const ULL*>(h_s);
        const float4* ppf = reinterpret_cast<const float4*>(&pp_s[w][0][0]);
        #pragma unroll 8
        for (int jj = 0; jj < TJ; ++jj) {
            ULL hv = hrow[jj * 32 + lane];          // h[jj][2*lane : 2*lane+1]
            float4 q0 = ppf[jj * 2];                // (p_r0,p_r0,p_r1,p_r1)
            float4 q1 = ppf[jj * 2 + 1];            // (p_r2,p_r2,p_r3,p_r3)
            ffma2(acc[0], pack2(q0.x, q0.y), hv);
            ffma2(acc[1], pack2(q0.z, q0.w), hv);
            ffma2(acc[2], pack2(q1.x, q1.y), hv);
            ffma2(acc[3], pack2(q1.z, q1.w), hv);
        }
    }

    #pragma unroll
    for (int r = 0; r < RPW; ++r) {
        float2 av = unpack2(acc[r]);
        float inv = 1.f / l[r];
        float o0 = av.x * inv;
        float o1 = av.y * inv;
        o0 = (o0 > 0.f) ? o0 : (__expf(o0) - 1.f);
        o1 = (o1 > 0.f) ? o1 : (__expf(o1) - 1.f);
        float2* op = reinterpret_cast<float2*>(out + (size_t)(ibase + r) * F_);
        op[lane] = make_float2(o0, o1);
    }
}

extern "C" void kernel_launch(void* const* d_in, const int* in_sizes, int n_in,
                              void* d_out, int out_size)
{
    const float* x   = (const float*)d_in[0];
    const int*   adj = (const int*)  d_in[1];
    const float* W   = (const float*)d_in[2];
    const float* a   = (const float*)d_in[3];
    float* out = (float*)d_out;

    prep_kernel<<<(B_ * N_) / 16, 1024>>>(x, W, a);
    attn_kernel<<<(B_ * N_) / TI, NTH>>>(adj, out);
}

// round 2
// speedup vs baseline: 1.0021x; 1.0021x over previous
#include <cuda_runtime.h>

typedef unsigned long long ULL;

static constexpr int B_ = 8;
static constexpr int N_ = 2048;
static constexpr int F_ = 64;
static constexpr float ALPHA_ = 0.2f;
static constexpr float NEG_INF_ = -9000000000000000.0f;

static constexpr int TI = 32;   // rows per block (attn)
static constexpr int TJ = 64;   // j-chunk
static constexpr int NTH = 256; // threads per block (attn)
static constexpr int RPW = 4;   // rows per warp

// scratch (no cudaMalloc allowed)
__device__ float g_h[B_ * N_ * F_];
__device__ float g_s1[B_ * N_];
__device__ float g_s2[B_ * N_];

__device__ __forceinline__ ULL pack2(float a, float b) {
    ULL r; asm("mov.b64 %0, {%1,%2};" : "=l"(r) : "f"(a), "f"(b)); return r;
}
__device__ __forceinline__ float2 unpack2(ULL v) {
    float2 r; asm("mov.b64 {%0,%1}, %2;" : "=f"(r.x), "=f"(r.y) : "l"(v)); return r;
}
__device__ __forceinline__ void ffma2(ULL& acc, ULL p, ULL h) {
    asm("fma.rn.f32x2 %0, %1, %2, %0;" : "+l"(acc) : "l"(p), "l"(h));
}
__device__ __forceinline__ ULL fmul2(ULL a, ULL b) {
    ULL r; asm("mul.rn.f32x2 %0, %1, %2;" : "=l"(r) : "l"(a), "l"(b)); return r;
}

// ---------------------------------------------------------------------------
// Kernel 1: h = x @ W ; s1 = h . a1 ; s2 = h . a2
// block = 1024 threads = 16 rows x 64 f
// ---------------------------------------------------------------------------
__global__ void __launch_bounds__(1024) prep_kernel(
    const float* __restrict__ x, const float* __restrict__ W,
    const float* __restrict__ a)
{
    __shared__ float W_s[F_ * F_];
    __shared__ float x_s[16][F_];
    __shared__ float red[16][2][2];

    int t = threadIdx.x;
    int tx = t & 63;
    int ty = t >> 6;
    int row0 = blockIdx.x * 16;
    int row = row0 + ty;

    #pragma unroll
    for (int k = 0; k < 4; ++k) W_s[t + k * 1024] = W[t + k * 1024];
    x_s[ty][tx] = x[(size_t)row * F_ + tx];
    __syncthreads();

    float h = 0.f;
    #pragma unroll
    for (int k = 0; k < F_; ++k) h = fmaf(x_s[ty][k], W_s[k * F_ + tx], h);

    g_h[(size_t)row * F_ + tx] = h;

    float v1 = h * a[tx];
    float v2 = h * a[F_ + tx];
    #pragma unroll
    for (int off = 16; off; off >>= 1) {
        v1 += __shfl_xor_sync(0xffffffffu, v1, off);
        v2 += __shfl_xor_sync(0xffffffffu, v2, off);
    }
    if ((tx & 31) == 0) { red[ty][tx >> 5][0] = v1; red[ty][tx >> 5][1] = v2; }
    __syncthreads();
    if (tx == 0) {
        g_s1[row] = red[ty][0][0] + red[ty][1][0];
        g_s2[row] = red[ty][0][1] + red[ty][1][1];
    }
}

// ---------------------------------------------------------------------------
// Kernel 2: fused masked-softmax attention + h' = att @ h + elu, flash-style.
// Grid: (B*N)/TI blocks, 256 threads = 8 warps x 4 rows each.
// Per j-chunk of 64: lanes compute p (j-parallel, online softmax per row),
// store duplicated-packed p to smem, then rank-64 f32x2 update of fp32 accs.
// ---------------------------------------------------------------------------
__global__ void __launch_bounds__(NTH, 4) attn_kernel(
    const int* __restrict__ adj, float* __restrict__ out)
{
    __shared__ __align__(16) float  h_s[TJ * F_];
    __shared__ float                s2_s[TJ];
    __shared__ __align__(16) float2 pp_s[NTH / 32][TJ][RPW];

    int t = threadIdx.x;
    int w = t >> 5;
    int lane = t & 31;
    int i0 = blockIdx.x * TI;         // global row base; 32 | 2048 so single batch
    int b = i0 >> 11;                 // / 2048
    int ibase = i0 + w * RPW;

    float s1v[RPW], m[RPW], l[RPW];
    ULL acc[RPW];
    #pragma unroll
    for (int r = 0; r < RPW; ++r) {
        s1v[r] = g_s1[ibase + r];
        m[r] = NEG_INF_;
        l[r] = 0.f;
        acc[r] = 0ull;
    }

    const float* hb  = g_h  + (size_t)b * N_ * F_;
    const float* s2b = g_s2 + (size_t)b * N_;

    for (int jc = 0; jc < N_; jc += TJ) {
        __syncthreads();
        {
            const float4* src = reinterpret_cast<const float4*>(hb + (size_t)jc * F_);
            float4* dst = reinterpret_cast<float4*>(h_s);
            #pragma unroll
            for (int k = 0; k < (TJ * F_ / 4) / NTH; ++k)
                dst[t + k * NTH] = src[t + k * NTH];
            if (t < TJ) s2_s[t] = s2b[jc + t];
        }
        __syncthreads();

        float s2a = s2_s[lane];
        float s2c = s2_s[lane + 32];

        #pragma unroll
        for (int r = 0; r < RPW; ++r) {
            const int* ap = adj + (size_t)(ibase + r) * N_ + jc;
            int a0 = ap[lane];
            int a1 = ap[lane + 32];
            float e0 = s1v[r] + s2a;
            e0 = (e0 > 0.f) ? e0 : ALPHA_ * e0;
            e0 = (a0 > 0) ? e0 : NEG_INF_;
            float e1 = s1v[r] + s2c;
            e1 = (e1 > 0.f) ? e1 : ALPHA_ * e1;
            e1 = (a1 > 0) ? e1 : NEG_INF_;

            float cm = fmaxf(e0, e1);
            #pragma unroll
            for (int off = 16; off; off >>= 1)
                cm = fmaxf(cm, __shfl_xor_sync(0xffffffffu, cm, off));

            float mn = fmaxf(m[r], cm);
            float sc = __expf(m[r] - mn);        // m==mn==NEG_INF -> exp(0)=1, later wiped
            float p0 = __expf(e0 - mn);
            float p1 = __expf(e1 - mn);
            float ps = p0 + p1;
            #pragma unroll
            for (int off = 16; off; off >>= 1)
                ps += __shfl_xor_sync(0xffffffffu, ps, off);

            l[r] = l[r] * sc + ps;
            m[r] = mn;
            acc[r] = fmul2(acc[r], pack2(sc, sc));

            pp_s[w][lane][r]      = make_float2(p0, p0);
            pp_s[w][lane + 32][r] = make_float2(p1, p1);
        }
        __syncwarp();

        const ULL* hrow = reinterpret_cast<const ULL*>(h_s);
        const float4* ppf = reinterpret_cast<const float4*>(&pp_s[w][0][0]);
        #pragma unroll 8
        for (int jj = 0; jj < TJ; ++jj) {
            ULL hv = hrow[jj * 32 + lane];          // h[jj][2*lane : 2*lane+1]
            float4 q0 = ppf[jj * 2];                // (p_r0,p_r0,p_r1,p_r1)
            float4 q1 = ppf[jj * 2 + 1];            // (p_r2,p_r2,p_r3,p_r3)
            ffma2(acc[0], pack2(q0.x, q0.y), hv);
            ffma2(acc[1], pack2(q0.z, q0.w), hv);
            ffma2(acc[2], pack2(q1.x, q1.y), hv);
            ffma2(acc[3], pack2(q1.z, q1.w), hv);
        }
    }

    #pragma unroll
    for (int r = 0; r < RPW; ++r) {
        float2 av = unpack2(acc[r]);
        float inv = 1.f / l[r];
        float o0 = av.x * inv;
        float o1 = av.y * inv;
        o0 = (o0 > 0.f) ? o0 : (__expf(o0) - 1.f);
        o1 = (o1 > 0.f) ? o1 : (__expf(o1) - 1.f);
        float2* op = reinterpret_cast<float2*>(out + (size_t)(ibase + r) * F_);
        op[lane] = make_float2(o0, o1);
    }
}

extern "C" void kernel_launch(void* const* d_in, const int* in_sizes, int n_in,
                              void* d_out, int out_size)
{
    const float* x   = (const float*)d_in[0];
    const int*   adj = (const int*)  d_in[1];
    const float* W   = (const float*)d_in[2];
    const float* a   = (const float*)d_in[3];
    float* out = (float*)d_out;

    prep_kernel<<<(B_ * N_) / 16, 1024>>>(x, W, a);
    attn_kernel<<<(B_ * N_) / TI, NTH>>>(adj, out);
}

// round 3
// speedup vs baseline: 1.6651x; 1.6616x over previous
#include <cuda_runtime.h>

typedef unsigned long long ULL;

static constexpr int B_ = 8;
static constexpr int N_ = 2048;
static constexpr int F_ = 64;
static constexpr float ALPHA_ = 0.2f;
static constexpr int SPLITS = 2;          // j-range splits
static constexpr int JS = N_ / SPLITS;    // 1024 j per block
static constexpr int TI = 64;             // rows per block
static constexpr int TJ = 64;             // j chunk

// -------- scratch (no cudaMalloc allowed) --------
__device__ float g_h[B_ * N_ * F_];
__device__ float g_s1[B_ * N_];
__device__ float g_s2[B_ * N_];
__device__ float g_c[B_];
__device__ float g_A [B_ * N_];
__device__ float g_Ap[B_ * N_];
__device__ float g_B [B_ * N_];
__device__ float g_Bp[B_ * N_];
__device__ float g_acc[SPLITS][B_ * N_ * F_];
__device__ float g_l  [SPLITS][B_ * N_];

__device__ __forceinline__ ULL pack2(float a, float b) {
    ULL r; asm("mov.b64 %0, {%1,%2};" : "=l"(r) : "f"(a), "f"(b)); return r;
}
__device__ __forceinline__ float2 unpack2(ULL v) {
    float2 r; asm("mov.b64 {%0,%1}, %2;" : "=f"(r.x), "=f"(r.y) : "l"(v)); return r;
}
__device__ __forceinline__ void ffma2(ULL& acc, ULL p, ULL h) {
    asm("fma.rn.f32x2 %0, %1, %2, %0;" : "+l"(acc) : "l"(p), "l"(h));
}

// ---------------------------------------------------------------------------
// K1: h = x@W ; s1 = h.a1 ; s2 = h.a2   (16 rows x 64 f per 1024-thr block)
// ---------------------------------------------------------------------------
__global__ void __launch_bounds__(1024) prep_kernel(
    const float* __restrict__ x, const float* __restrict__ W,
    const float* __restrict__ a)
{
    __shared__ float W_s[F_ * F_];
    __shared__ float x_s[16][F_];
    __shared__ float red[16][2][2];

    int t = threadIdx.x, tx = t & 63, ty = t >> 6;
    int row = blockIdx.x * 16 + ty;

    #pragma unroll
    for (int k = 0; k < 4; ++k) W_s[t + k * 1024] = W[t + k * 1024];
    x_s[ty][tx] = x[(size_t)row * F_ + tx];
    __syncthreads();

    float h = 0.f;
    #pragma unroll
    for (int k = 0; k < F_; ++k) h = fmaf(x_s[ty][k], W_s[k * F_ + tx], h);
    g_h[(size_t)row * F_ + tx] = h;

    float v1 = h * a[tx];
    float v2 = h * a[F_ + tx];
    #pragma unroll
    for (int off = 16; off; off >>= 1) {
        v1 += __shfl_xor_sync(0xffffffffu, v1, off);
        v2 += __shfl_xor_sync(0xffffffffu, v2, off);
    }
    if ((tx & 31) == 0) { red[ty][tx >> 5][0] = v1; red[ty][tx >> 5][1] = v2; }
    __syncthreads();
    if (tx == 0) {
        g_s1[row] = red[ty][0][0] + red[ty][1][0];
        g_s2[row] = red[ty][0][1] + red[ty][1][1];
    }
}

// K2: per-batch c = max_j s2
__global__ void cmax_kernel() {
    __shared__ float red[8];
    int b = blockIdx.x;
    float m = -3.4e38f;
    for (int i = threadIdx.x; i < N_; i += 256) m = fmaxf(m, g_s2[b * N_ + i]);
    #pragma unroll
    for (int off = 16; off; off >>= 1) m = fmaxf(m, __shfl_xor_sync(0xffffffffu, m, off));
    if ((threadIdx.x & 31) == 0) red[threadIdx.x >> 5] = m;
    __syncthreads();
    if (threadIdx.x == 0) {
        float mm = red[0];
        #pragma unroll
        for (int k = 1; k < 8; ++k) mm = fmaxf(mm, red[k]);
        g_c[b] = mm;
    }
}

// K3: exact lrelu/exp factor arrays
__global__ void factors_kernel() {
    int i = blockIdx.x * 256 + threadIdx.x;
    float c = g_c[i >> 11];
    float u = g_s1[i] + c;
    float m = (u > 0.f) ? u : ALPHA_ * u;     // lrelu(s1+c) >= row max of lrelu(s1+s2)
    g_A [i] = expf(u - m);
    g_Ap[i] = expf(ALPHA_ * u - m);
    float v = g_s2[i] - c;
    g_B [i] = expf(v);
    g_Bp[i] = expf(ALPHA_ * v);
}

// ---------------------------------------------------------------------------
// K4: masked attention partials.  512 blocks = 256 row-tiles x 2 j-splits.
// 256 thr = 8 warps x 8 rows. p = adj ? max(A*B, A'*B') : 0 (exact softmax
// numerator, no rescaling). acc rows paired for MOV-free FFMA2.
// ---------------------------------------------------------------------------
__global__ void __launch_bounds__(256) attn_kernel(const int* __restrict__ adj)
{
    __shared__ __align__(16) float h_s[TJ][F_];
    __shared__ __align__(16) float ps[8][TJ][8];
    __shared__ float Bs[TJ], Bps[TJ];

    int t = threadIdx.x, w = t >> 5, lane = t & 31;
    int tile = blockIdx.x & 255;
    int s = blockIdx.x >> 8;
    int i0 = tile * TI;
    int b = i0 >> 11;
    int ibase = i0 + w * 8;

    float A[8], Ap[8], lp[8];
    ULL acc[4][2];
    #pragma unroll
    for (int r = 0; r < 8; ++r) {
        A[r]  = g_A [ibase + r];
        Ap[r] = g_Ap[ibase + r];
        lp[r] = 0.f;
    }
    #pragma unroll
    for (int k = 0; k < 4; ++k) acc[k][0] = acc[k][1] = 0ull;

    const float* hb  = g_h + (size_t)b * N_ * F_;
    const float* Bb  = g_B  + b * N_;
    const float* Bpb = g_Bp + b * N_;
    int j0 = s * JS;

    for (int jc = j0; jc < j0 + JS; jc += TJ) {
        __syncthreads();
        {   // h tile + B/Bp tile
            const float4* src = (const float4*)(hb + (size_t)jc * F_);
            float4* dst = (float4*)&h_s[0][0];
            #pragma unroll
            for (int k = 0; k < 4; ++k) dst[t + k * 256] = src[t + k * 256];
            if (t < TJ) { Bs[t] = Bb[jc + t]; Bps[t] = Bpb[jc + t]; }
        }
        __syncthreads();

        float B0 = Bs[lane],      Bp0 = Bps[lane];
        float B1 = Bs[lane + 32], Bp1 = Bps[lane + 32];

        // produce p (j-parallel, lane = j)
        #pragma unroll
        for (int r = 0; r < 8; ++r) {
            const int* ap = adj + (size_t)(ibase + r) * N_ + jc;
            int a0 = __ldcs(ap + lane);
            int a1 = __ldcs(ap + lane + 32);
            float p0 = (a0 > 0) ? fmaxf(A[r] * B0, Ap[r] * Bp0) : 0.f;
            float p1 = (a1 > 0) ? fmaxf(A[r] * B1, Ap[r] * Bp1) : 0.f;
            lp[r] += p0 + p1;
            ps[w][lane][r]      = p0;
            ps[w][lane + 32][r] = p1;
        }
        __syncwarp();

        // consume: rank-64 update, rows paired in f32x2
        #pragma unroll 16
        for (int jj = 0; jj < TJ; ++jj) {
            float2 hv = *(const float2*)&h_s[jj][2 * lane];
            ULL hd0 = pack2(hv.x, hv.x);
            ULL hd1 = pack2(hv.y, hv.y);
            ulonglong2 pA = *(const ulonglong2*)&ps[w][jj][0];
            ulonglong2 pB = *(const ulonglong2*)&ps[w][jj][4];
            ffma2(acc[0][0], pA.x, hd0); ffma2(acc[0][1], pA.x, hd1);
            ffma2(acc[1][0], pA.y, hd0); ffma2(acc[1][1], pA.y, hd1);
            ffma2(acc[2][0], pB.x, hd0); ffma2(acc[2][1], pB.x, hd1);
            ffma2(acc[3][0], pB.y, hd0); ffma2(acc[3][1], pB.y, hd1);
        }
        __syncwarp();
    }

    // row-sum reduce (once) + partial writes
    #pragma unroll
    for (int r = 0; r < 8; ++r) {
        float v = lp[r];
        #pragma unroll
        for (int off = 16; off; off >>= 1) v += __shfl_xor_sync(0xffffffffu, v, off);
        lp[r] = v;
        if (lane == 0) g_l[s][ibase + r] = v;
    }
    #pragma unroll
    for (int k = 0; k < 4; ++k) {
        float2 a0 = unpack2(acc[k][0]);   // f0: (row 2k, row 2k+1)
        float2 a1 = unpack2(acc[k][1]);   // f1
        float* o0 = g_acc[s] + (size_t)(ibase + 2 * k)     * F_ + 2 * lane;
        float* o1 = g_acc[s] + (size_t)(ibase + 2 * k + 1) * F_ + 2 * lane;
        *(float2*)o0 = make_float2(a0.x, a1.x);
        *(float2*)o1 = make_float2(a0.y, a1.y);
    }
}

// K5: combine splits, normalize, ELU
__global__ void combine_kernel(float* __restrict__ out) {
    int idx = blockIdx.x * 256 + threadIdx.x;   // over 16384*32 float2
    int row = idx >> 5;
    int fo = (idx & 31) * 2;
    float inv = 1.f / (g_l[0][row] + g_l[1][row]);
    size_t o = (size_t)row * F_ + fo;
    float2 u = *(const float2*)(g_acc[0] + o);
    float2 v = *(const float2*)(g_acc[1] + o);
    float o0 = (u.x + v.x) * inv;
    float o1 = (u.y + v.y) * inv;
    o0 = (o0 > 0.f) ? o0 : (__expf(o0) - 1.f);
    o1 = (o1 > 0.f) ? o1 : (__expf(o1) - 1.f);
    *(float2*)(out + o) = make_float2(o0, o1);
}

extern "C" void kernel_launch(void* const* d_in, const int* in_sizes, int n_in,
                              void* d_out, int out_size)
{
    const float* x   = (const float*)d_in[0];
    const int*   adj = (const int*)  d_in[1];
    const float* W   = (const float*)d_in[2];
    const float* a   = (const float*)d_in[3];
    float* out = (float*)d_out;

    prep_kernel<<<(B_ * N_) / 16, 1024>>>(x, W, a);
    cmax_kernel<<<B_, 256>>>();
    factors_kernel<<<(B_ * N_) / 256, 256>>>();
    attn_kernel<<<256 * SPLITS, 256>>>(adj);
    combine_kernel<<<(B_ * N_ * 32) / 256, 256>>>(out);
}

// round 5
// speedup vs baseline: 2.4760x; 1.4870x over previous
#include <cuda_runtime.h>
#include <cuda_bf16.h>
#include <cstdint>

static constexpr int B_ = 8;
static constexpr int N_ = 2048;
static constexpr int F_ = 64;
static constexpr float ALPHA_ = 0.2f;
static constexpr int SPLITS = 2;
static constexpr int JS = N_ / SPLITS;   // 1024

// -------- scratch (no cudaMalloc allowed) --------
__device__ float g_h[B_ * N_ * F_];
__device__ float g_s1[B_ * N_];
__device__ float g_s2[B_ * N_];
__device__ float g_c[B_];      // max s2
__device__ float g_c2[B_];     // 8th largest s2
__device__ float g_A [B_ * N_];
__device__ float g_Ap[B_ * N_];
__device__ float g_B [B_ * N_];
__device__ float g_Bp[B_ * N_];
__device__ __nv_bfloat16 g_hT_hi[B_ * F_ * N_];   // [b][f][n]
__device__ __nv_bfloat16 g_hT_lo[B_ * F_ * N_];
__device__ float g_acc[SPLITS][B_ * N_ * F_];
__device__ float g_l  [SPLITS][B_ * N_];
__device__ int g_nbad;
__device__ int g_bad[B_ * N_];

__device__ __forceinline__ uint32_t smem_u32(const void* p) {
    uint32_t a;
    asm("{ .reg .u64 t; cvta.to.shared.u64 t, %1; cvt.u32.u64 %0, t; }" : "=r"(a) : "l"(p));
    return a;
}

#define LDSM4(r, addr) \
    asm volatile("ldmatrix.sync.aligned.m8n8.x4.shared.b16 {%0,%1,%2,%3}, [%4];" \
        : "=r"((r)[0]), "=r"((r)[1]), "=r"((r)[2]), "=r"((r)[3]) : "r"(addr))

#define MMA_BF16(C, a, b0, b1) \
    asm volatile("mma.sync.aligned.m16n8k16.row.col.f32.bf16.bf16.f32 " \
        "{%0,%1,%2,%3}, {%4,%5,%6,%7}, {%8,%9}, {%0,%1,%2,%3};" \
        : "+f"((C)[0]), "+f"((C)[1]), "+f"((C)[2]), "+f"((C)[3]) \
        : "r"((a)[0]), "r"((a)[1]), "r"((a)[2]), "r"((a)[3]), "r"(b0), "r"(b1))

// ---------------------------------------------------------------------------
// K1: h = x@W ; s1,s2 ; transposed bf16 hi/lo copies of h
// ---------------------------------------------------------------------------
__global__ void __launch_bounds__(1024) prep_kernel(
    const float* __restrict__ x, const float* __restrict__ W, const float* __restrict__ a)
{
    __shared__ float W_s[F_ * F_];
    __shared__ float x_s[16][F_];
    __shared__ float h_sh[16][F_ + 1];
    __shared__ float red[16][2][2];

    int t = threadIdx.x, tx = t & 63, ty = t >> 6;
    int row0 = blockIdx.x * 16;
    int row = row0 + ty;

    #pragma unroll
    for (int k = 0; k < 4; ++k) W_s[t + k * 1024] = W[t + k * 1024];
    x_s[ty][tx] = x[(size_t)row * F_ + tx];
    __syncthreads();

    float h = 0.f;
    #pragma unroll
    for (int k = 0; k < F_; ++k) h = fmaf(x_s[ty][k], W_s[k * F_ + tx], h);
    g_h[(size_t)row * F_ + tx] = h;
    h_sh[ty][tx] = h;

    float v1 = h * a[tx];
    float v2 = h * a[F_ + tx];
    #pragma unroll
    for (int off = 16; off; off >>= 1) {
        v1 += __shfl_xor_sync(0xffffffffu, v1, off);
        v2 += __shfl_xor_sync(0xffffffffu, v2, off);
    }
    if ((tx & 31) == 0) { red[ty][tx >> 5][0] = v1; red[ty][tx >> 5][1] = v2; }
    __syncthreads();
    if (tx == 0) {
        g_s1[row] = red[ty][0][0] + red[ty][1][0];
        g_s2[row] = red[ty][0][1] + red[ty][1][1];
    }

    int f = t >> 4, rr = t & 15;
    float v = h_sh[rr][f];
    __nv_bfloat16 hi = __float2bfloat16(v);
    float lov = v - __bfloat162float(hi);
    int b = row0 >> 11;
    size_t o = ((size_t)(b * F_ + f)) * N_ + (row0 & (N_ - 1)) + rr;
    g_hT_hi[o] = hi;
    g_hT_lo[o] = __float2bfloat16(lov);
}

// ---------------------------------------------------------------------------
// K2: per-batch max + 8th-largest of s2 ; reset bad counter
// ---------------------------------------------------------------------------
__global__ void __launch_bounds__(256) ctopk_kernel() {
    __shared__ float s2s[N_];
    __shared__ float red[8];
    int b = blockIdx.x, t = threadIdx.x;
    if (b == 0 && t == 0) g_nbad = 0;
    for (int i = t; i < N_; i += 256) s2s[i] = g_s2[b * N_ + i];
    __syncthreads();
    float m1 = -3.4e38f, mk = -3.4e38f;
    for (int k = 0; k < 8; ++k) {
        float m = -3.4e38f;
        for (int i = t; i < N_; i += 256) m = fmaxf(m, s2s[i]);
        #pragma unroll
        for (int off = 16; off; off >>= 1) m = fmaxf(m, __shfl_xor_sync(0xffffffffu, m, off));
        if ((t & 31) == 0) red[t >> 5] = m;
        __syncthreads();
        float mm = red[0];
        #pragma unroll
        for (int q = 1; q < 8; ++q) mm = fmaxf(mm, red[q]);
        if (k == 0) m1 = mm;
        mk = mm;
        for (int i = t; i < N_; i += 256) if (s2s[i] == mm) s2s[i] = -3.4e38f;
        __syncthreads();
    }
    if (t == 0) { g_c[b] = m1; g_c2[b] = mk; }
}

// ---------------------------------------------------------------------------
// K3: exact lrelu/exp factors with range-safe normalizer
// ---------------------------------------------------------------------------
__global__ void factors_kernel() {
    int i = blockIdx.x * 256 + threadIdx.x;
    int b = i >> 11;
    float c = g_c[b], c2 = g_c2[b];
    float s1 = g_s1[i];
    float u  = s1 + c;   // upper-bound arg
    float u2 = s1 + c2;  // typical-max arg
    float lr_u  = (u  > 0.f) ? u  : ALPHA_ * u;
    float lr_u2 = (u2 > 0.f) ? u2 : ALPHA_ * u2;
    float m = fmaxf(lr_u2, lr_u - 60.f);
    g_A [i] = expf(u - m);
    g_Ap[i] = expf(ALPHA_ * u - m);
    float v = g_s2[i] - c;
    g_B [i] = expf(v);
    g_Bp[i] = expf(ALPHA_ * v);
}

// ---------------------------------------------------------------------------
// K4: attention partials via HMMA (mma.sync bf16, 3-pass hi/lo split).
// 512 blocks = 256 row-tiles(64) x 2 j-splits. 128 thr = 4 warps x 16 rows.
// ---------------------------------------------------------------------------
__global__ void __launch_bounds__(128, 4) attn_kernel(const int* __restrict__ adj)
{
    __shared__ __align__(16) char Phi[64 * 128], Plo[64 * 128];
    __shared__ __align__(16) char Hhi[64 * 128], Hlo[64 * 128];
    __shared__ float sA[64], sAp[64];

    int t = threadIdx.x, w = t >> 5, lane = t & 31;
    int tile = blockIdx.x & 255;
    int s = blockIdx.x >> 8;
    int i0 = tile * 64;
    int b = i0 >> 11;
    int m0 = w * 16;
    int j0 = s * JS;

    if (t < 64) { sA[t] = g_A[i0 + t]; sAp[t] = g_Ap[i0 + t]; }

    uint32_t phi_s = smem_u32(Phi), plo_s = smem_u32(Plo);
    uint32_t hhi_s = smem_u32(Hhi), hlo_s = smem_u32(Hlo);

    float C[8][4];
    #pragma unroll
    for (int g = 0; g < 8; ++g)
        #pragma unroll
        for (int q = 0; q < 4; ++q) C[g][q] = 0.f;
    float lp[16];
    #pragma unroll
    for (int r = 0; r < 16; ++r) lp[r] = 0.f;

    for (int ci = 0; ci < JS / 64; ++ci) {
        int jc = j0 + ci * 64;
        __syncthreads();

        // ---- H chunk: 64 f-rows x 64 j (bf16, 128B rows, SW128 swizzle) ----
        {
            int q = t & 7;           // 16B chunk within row
            int fb = t >> 3;         // 16 rows per pass
            #pragma unroll
            for (int pass = 0; pass < 4; ++pass) {
                int f = fb + pass * 16;
                size_t src = ((size_t)(b * F_ + f)) * N_ + jc + q * 8;
                uint32_t boff = (uint32_t)f * 128 + (uint32_t)q * 16;
                uint32_t sw = boff ^ (((uint32_t)(f & 7)) << 4);
                *(uint4*)(Hhi + sw) = *(const uint4*)(g_hT_hi + src);
                *(uint4*)(Hlo + sw) = *(const uint4*)(g_hT_lo + src);
            }
        }

        // ---- P production: own 16 rows, lane covers j = 2lane, 2lane+1 ----
        float2 Bv  = *(const float2*)(g_B  + b * N_ + jc + 2 * lane);
        float2 Bpv = *(const float2*)(g_Bp + b * N_ + jc + 2 * lane);
        #pragma unroll
        for (int r = 0; r < 16; ++r) {
            int row = m0 + r;
            int2 av = __ldcs((const int2*)(adj + (size_t)(i0 + row) * N_ + jc) + lane);
            float Ar = sA[row], Apr = sAp[row];
            float p0 = (av.x > 0) ? fmaxf(Ar * Bv.x, Apr * Bpv.x) : 0.f;
            float p1 = (av.y > 0) ? fmaxf(Ar * Bv.y, Apr * Bpv.y) : 0.f;
            lp[r] += p0 + p1;
            __nv_bfloat162 h2 = __float22bfloat162_rn(make_float2(p0, p1));
            float l0 = p0 - __bfloat162float(__low2bfloat16(h2));
            float l1 = p1 - __bfloat162float(__high2bfloat16(h2));
            __nv_bfloat162 l2 = __float22bfloat162_rn(make_float2(l0, l1));
            uint32_t boff = (uint32_t)row * 128 + (uint32_t)lane * 4;
            uint32_t sw = boff ^ (((uint32_t)(row & 7)) << 4);
            *(uint32_t*)(Phi + sw) = *(uint32_t*)&h2;
            *(uint32_t*)(Plo + sw) = *(uint32_t*)&l2;
        }
        __syncthreads();

        // ---- MMA: 4 k-steps x 8 n-groups x 3 passes ----
        #pragma unroll
        for (int ks = 0; ks < 4; ++ks) {
            uint32_t ahi[4], alo[4];
            {
                int arow = m0 + (lane & 15);
                uint32_t boff = (uint32_t)arow * 128 + (uint32_t)ks * 32 + ((uint32_t)(lane >> 4)) * 16;
                uint32_t sw = boff ^ (((uint32_t)(arow & 7)) << 4);
                LDSM4(ahi, phi_s + sw);
                LDSM4(alo, plo_s + sw);
            }
            #pragma unroll
            for (int g2 = 0; g2 < 4; ++g2) {
                uint32_t bhi[4], blo[4];
                int nrow = g2 * 16 + (lane & 15);
                uint32_t boff = (uint32_t)nrow * 128 + (uint32_t)ks * 32 + ((uint32_t)(lane >> 4)) * 16;
                uint32_t sw = boff ^ (((uint32_t)(nrow & 7)) << 4);
                LDSM4(bhi, hhi_s + sw);
                LDSM4(blo, hlo_s + sw);
                MMA_BF16(C[g2 * 2],     ahi, bhi[0], bhi[2]);
                MMA_BF16(C[g2 * 2 + 1], ahi, bhi[1], bhi[3]);
                MMA_BF16(C[g2 * 2],     ahi, blo[0], blo[2]);
                MMA_BF16(C[g2 * 2 + 1], ahi, blo[1], blo[3]);
                MMA_BF16(C[g2 * 2],     alo, bhi[0], bhi[2]);
                MMA_BF16(C[g2 * 2 + 1], alo, bhi[1], bhi[3]);
            }
        }
    }

    // ---- denominators: reduce once ----
    #pragma unroll
    for (int r = 0; r < 16; ++r) {
        float v = lp[r];
        #pragma unroll
        for (int off = 16; off; off >>= 1) v += __shfl_xor_sync(0xffffffffu, v, off);
        if (lane == 0) g_l[s][i0 + m0 + r] = v;
    }

    // ---- C frags -> g_acc: lane holds rows (m0+lane/4, +8), cols (lane%4)*2 ----
    {
        int r0 = i0 + m0 + (lane >> 2);
        int cp = (lane & 3) * 2;
        #pragma unroll
        for (int g = 0; g < 8; ++g) {
            float* o = g_acc[s] + (size_t)r0 * F_ + g * 8 + cp;
            *(float2*)o = make_float2(C[g][0], C[g][1]);
            *(float2*)(o + 8 * F_) = make_float2(C[g][2], C[g][3]);
        }
    }
}

// ---------------------------------------------------------------------------
// K5: combine splits, normalize, ELU, flag bad rows
// ---------------------------------------------------------------------------
__global__ void combine_kernel(float* __restrict__ out) {
    int idx = blockIdx.x * 256 + threadIdx.x;   // B*N*32 threads
    int row = idx >> 5;
    int fo = (idx & 31) * 2;
    float l = g_l[0][row] + g_l[1][row];
    if ((idx & 31) == 0 && !(l >= 1e-20f)) {
        int si = atomicAdd(&g_nbad, 1);
        g_bad[si] = row;
    }
    float inv = 1.f / l;
    size_t o = (size_t)row * F_ + fo;
    float2 u = *(const float2*)(g_acc[0] + o);
    float2 v = *(const float2*)(g_acc[1] + o);
    float o0 = (u.x + v.x) * inv;
    float o1 = (u.y + v.y) * inv;
    o0 = (o0 > 0.f) ? o0 : (__expf(o0) - 1.f);
    o1 = (o1 > 0.f) ? o1 : (__expf(o1) - 1.f);
    *(float2*)(out + o) = make_float2(o0, o1);
}

// ---------------------------------------------------------------------------
// K6: exact fp32 recompute of flagged rows
// ---------------------------------------------------------------------------
__global__ void __launch_bounds__(256) fallback_kernel(
    const int* __restrict__ adj, float* __restrict__ out)
{
    __shared__ float p_s[N_];
    __shared__ float red[4][64];
    __shared__ float lred[8];
    int t = threadIdx.x, w = t >> 5, lane = t & 31;
    int nb = g_nbad;
    for (int k = blockIdx.x; k < nb; k += gridDim.x) {
        int row = g_bad[k];
        int b = row >> 11;
        float A = g_A[row], Ap = g_Ap[row];
        float lpv = 0.f;
        for (int j = t; j < N_; j += 256) {
            int av = adj[(size_t)row * N_ + j];
            float p = (av > 0) ? fmaxf(A * g_B[b * N_ + j], Ap * g_Bp[b * N_ + j]) : 0.f;
            p_s[j] = p;
            lpv += p;
        }
        #pragma unroll
        for (int off = 16; off; off >>= 1) lpv += __shfl_xor_sync(0xffffffffu, lpv, off);
        if (lane == 0) lred[w] = lpv;
        __syncthreads();
        float l = 0.f;
        #pragma unroll
        for (int q = 0; q < 8; ++q) l += lred[q];
        int f = t & 63, seg = t >> 6;
        float acc = 0.f;
        const float* hb = g_h + ((size_t)b * N_ + seg * 512) * F_ + f;
        for (int j = 0; j < 512; ++j) acc = fmaf(p_s[seg * 512 + j], hb[(size_t)j * F_], acc);
        red[seg][f] = acc;
        __syncthreads();
        if (t < 64) {
            float v = (red[0][t] + red[1][t] + red[2][t] + red[3][t]) / l;
            out[(size_t)row * F_ + t] = (v > 0.f) ? v : (__expf(v) - 1.f);
        }
        __syncthreads();
    }
}

extern "C" void kernel_launch(void* const* d_in, const int* in_sizes, int n_in,
                              void* d_out, int out_size)
{
    const float* x   = (const float*)d_in[0];
    const int*   adj = (const int*)  d_in[1];
    const float* W   = (const float*)d_in[2];
    const float* a   = (const float*)d_in[3];
    float* out = (float*)d_out;

    prep_kernel<<<(B_ * N_) / 16, 1024>>>(x, W, a);
    ctopk_kernel<<<B_, 256>>>();
    factors_kernel<<<(B_ * N_) / 256, 256>>>();
    attn_kernel<<<256 * SPLITS, 128>>>(adj);
    combine_kernel<<<(B_ * N_ * 32) / 256, 256>>>(out);
    fallback_kernel<<<64, 256>>>(adj, out);
}

// round 6
// speedup vs baseline: 2.6021x; 1.0509x over previous
#include <cuda_runtime.h>
#include <cuda_bf16.h>
#include <cstdint>

static constexpr int B_ = 8;
static constexpr int N_ = 2048;
static constexpr int F_ = 64;
static constexpr float ALPHA_ = 0.2f;
static constexpr int SPLITS = 2;
static constexpr int JS = N_ / SPLITS;   // 1024

// -------- scratch (no cudaMalloc allowed) --------
__device__ float g_h[B_ * N_ * F_];
__device__ float g_s1[B_ * N_];
__device__ float g_s2[B_ * N_];
__device__ float g_A [B_ * N_];
__device__ float g_Ap[B_ * N_];
__device__ float g_B [B_ * N_];
__device__ float g_Bp[B_ * N_];
__device__ __nv_bfloat16 g_hT_hi[B_ * F_ * N_];   // [b][f][n]
__device__ __nv_bfloat16 g_hT_lo[B_ * F_ * N_];
__device__ float g_acc[SPLITS][B_ * N_ * F_];
__device__ float g_l  [SPLITS][B_ * N_];
__device__ int g_nbad;
__device__ int g_bad[B_ * N_];

__device__ __forceinline__ uint32_t smem_u32(const void* p) {
    uint32_t a;
    asm("{ .reg .u64 t; cvta.to.shared.u64 t, %1; cvt.u32.u64 %0, t; }" : "=r"(a) : "l"(p));
    return a;
}

#define LDSM4(r, addr) \
    asm volatile("ldmatrix.sync.aligned.m8n8.x4.shared.b16 {%0,%1,%2,%3}, [%4];" \
        : "=r"((r)[0]), "=r"((r)[1]), "=r"((r)[2]), "=r"((r)[3]) : "r"(addr))

#define MMA_BF16(C, a, b0, b1) \
    asm volatile("mma.sync.aligned.m16n8k16.row.col.f32.bf16.bf16.f32 " \
        "{%0,%1,%2,%3}, {%4,%5,%6,%7}, {%8,%9}, {%0,%1,%2,%3};" \
        : "+f"((C)[0]), "+f"((C)[1]), "+f"((C)[2]), "+f"((C)[3]) \
        : "r"((a)[0]), "r"((a)[1]), "r"((a)[2]), "r"((a)[3]), "r"(b0), "r"(b1))

#define CP_ASYNC16(dst, src) \
    asm volatile("cp.async.cg.shared.global [%0], [%1], 16;" :: "r"(dst), "l"(src))
#define CP_COMMIT() asm volatile("cp.async.commit_group;" ::: "memory")
#define CP_WAIT0()  asm volatile("cp.async.wait_group 0;" ::: "memory")

// ---------------------------------------------------------------------------
// K1: h = x@W ; s1,s2 ; transposed bf16 hi/lo copies of h
// ---------------------------------------------------------------------------
__global__ void __launch_bounds__(1024) prep_kernel(
    const float* __restrict__ x, const float* __restrict__ W, const float* __restrict__ a)
{
    __shared__ float W_s[F_ * F_];
    __shared__ float x_s[16][F_];
    __shared__ float h_sh[16][F_ + 1];
    __shared__ float red[16][2][2];

    int t = threadIdx.x, tx = t & 63, ty = t >> 6;
    int row0 = blockIdx.x * 16;
    int row = row0 + ty;

    #pragma unroll
    for (int k = 0; k < 4; ++k) W_s[t + k * 1024] = W[t + k * 1024];
    x_s[ty][tx] = x[(size_t)row * F_ + tx];
    __syncthreads();

    float h = 0.f;
    #pragma unroll
    for (int k = 0; k < F_; ++k) h = fmaf(x_s[ty][k], W_s[k * F_ + tx], h);
    g_h[(size_t)row * F_ + tx] = h;
    h_sh[ty][tx] = h;

    float v1 = h * a[tx];
    float v2 = h * a[F_ + tx];
    #pragma unroll
    for (int off = 16; off; off >>= 1) {
        v1 += __shfl_xor_sync(0xffffffffu, v1, off);
        v2 += __shfl_xor_sync(0xffffffffu, v2, off);
    }
    if ((tx & 31) == 0) { red[ty][tx >> 5][0] = v1; red[ty][tx >> 5][1] = v2; }
    __syncthreads();
    if (tx == 0) {
        g_s1[row] = red[ty][0][0] + red[ty][1][0];
        g_s2[row] = red[ty][0][1] + red[ty][1][1];
    }

    int f = t >> 4, rr = t & 15;
    float v = h_sh[rr][f];
    __nv_bfloat16 hi = __float2bfloat16(v);
    float lov = v - __bfloat162float(hi);
    int b = row0 >> 11;
    size_t o = ((size_t)(b * F_ + f)) * N_ + (row0 & (N_ - 1)) + rr;
    g_hT_hi[o] = hi;
    g_hT_lo[o] = __float2bfloat16(lov);
}

// ---------------------------------------------------------------------------
// K2: per-batch c (max of warp maxes) / c2 (min of warp maxes) + factors
// ---------------------------------------------------------------------------
__global__ void __launch_bounds__(256) factors_kernel() {
    __shared__ float red[8];
    int b = blockIdx.x, t = threadIdx.x, w = t >> 5, lane = t & 31;
    if (b == 0 && t == 0) g_nbad = 0;

    float m = -3.4e38f;
    for (int i = t; i < N_; i += 256) m = fmaxf(m, g_s2[b * N_ + i]);
    #pragma unroll
    for (int off = 16; off; off >>= 1) m = fmaxf(m, __shfl_xor_sync(0xffffffffu, m, off));
    if (lane == 0) red[w] = m;
    __syncthreads();
    float c = -3.4e38f, c2 = 3.4e38f;
    #pragma unroll
    for (int q = 0; q < 8; ++q) { c = fmaxf(c, red[q]); c2 = fminf(c2, red[q]); }

    for (int i = t; i < N_; i += 256) {
        int gi = b * N_ + i;
        float s1 = g_s1[gi];
        float u  = s1 + c;
        float u2 = s1 + c2;
        float lr_u  = (u  > 0.f) ? u  : ALPHA_ * u;
        float lr_u2 = (u2 > 0.f) ? u2 : ALPHA_ * u2;
        float mm = fmaxf(lr_u2, lr_u - 60.f);
        g_A [gi] = expf(u - mm);
        g_Ap[gi] = expf(ALPHA_ * u - mm);
        float v = g_s2[gi] - c;
        g_B [gi] = expf(v);
        g_Bp[gi] = expf(ALPHA_ * v);
    }
}

// ---------------------------------------------------------------------------
// K3: attention partials via HMMA with cp.async-pipelined adj.
// 512 blocks = 256 row-tiles(64) x 2 j-splits; 256 thr = 8 warps.
// Produce: warp w -> rows w*8..w*8+7. MMA: warp w -> rows (w&3)*16, f-half w>>2.
// ---------------------------------------------------------------------------
static constexpr uint32_t OFF_PHI = 0;
static constexpr uint32_t OFF_PLO = 8192;
static constexpr uint32_t OFF_HHI = 16384;
static constexpr uint32_t OFF_HLO = 24576;
static constexpr uint32_t OFF_ADJ = 32768;      // 2 x 16384
static constexpr uint32_t OFF_SA  = 65536;
static constexpr uint32_t OFF_SAP = 65792;
static constexpr uint32_t DSMEM   = 66048;

__global__ void __launch_bounds__(256, 3) attn_kernel(const int* __restrict__ adj)
{
    extern __shared__ __align__(128) char sm[];
    uint32_t sb = smem_u32(sm);

    int t = threadIdx.x, w = t >> 5, lane = t & 31;
    int tile = blockIdx.x & 255;
    int s = blockIdx.x >> 8;
    int i0 = tile * 64;
    int b = i0 >> 11;
    int j0 = s * JS;

    float* sA  = (float*)(sm + OFF_SA);
    float* sAp = (float*)(sm + OFF_SAP);
    if (t < 64) { sA[t] = g_A[i0 + t]; sAp[t] = g_Ap[i0 + t]; }

    float C[4][4];
    #pragma unroll
    for (int g = 0; g < 4; ++g)
        #pragma unroll
        for (int q = 0; q < 4; ++q) C[g][q] = 0.f;
    float lp[8];
    #pragma unroll
    for (int r = 0; r < 8; ++r) lp[r] = 0.f;

    // prologue: prefetch adj chunk 0
    {
        #pragma unroll
        for (int k = 0; k < 4; ++k) {
            int u = t + k * 256;
            int row = u >> 4, seg = u & 15;
            const int* src = adj + (size_t)(i0 + row) * N_ + j0 + seg * 4;
            CP_ASYNC16(sb + OFF_ADJ + (uint32_t)row * 256 + (uint32_t)seg * 16, src);
        }
        CP_COMMIT();
    }

    for (int ci = 0; ci < JS / 64; ++ci) {
        int jc = j0 + ci * 64;
        uint32_t abuf = OFF_ADJ + (uint32_t)(ci & 1) * 16384;

        CP_WAIT0();
        __syncthreads();   // adj[ci] visible to all; prev MMA done with P/H

        if (ci + 1 < JS / 64) {
            uint32_t nbuf = OFF_ADJ + (uint32_t)((ci + 1) & 1) * 16384;
            #pragma unroll
            for (int k = 0; k < 4; ++k) {
                int u = t + k * 256;
                int row = u >> 4, seg = u & 15;
                const int* src = adj + (size_t)(i0 + row) * N_ + jc + 64 + seg * 4;
                CP_ASYNC16(sb + nbuf + (uint32_t)row * 256 + (uint32_t)seg * 16, src);
            }
            CP_COMMIT();
        }

        // ---- H chunk: 64 f-rows x 64 j bf16 hi/lo (128B rows, swizzled) ----
        #pragma unroll
        for (int pass = 0; pass < 2; ++pass) {
            int u = t + pass * 256;
            int f = u >> 3, q = u & 7;
            size_t src = ((size_t)(b * F_ + f)) * N_ + jc + q * 8;
            uint32_t boff = (uint32_t)f * 128 + (uint32_t)q * 16;
            uint32_t sw = boff ^ (((uint32_t)(f & 7)) << 4);
            *(uint4*)(sm + OFF_HHI + sw) = *(const uint4*)(g_hT_hi + src);
            *(uint4*)(sm + OFF_HLO + sw) = *(const uint4*)(g_hT_lo + src);
        }

        // ---- P production: warp w rows w*8..+7, lane j = 2lane,2lane+1 ----
        {
            float2 Bv  = *(const float2*)(g_B  + b * N_ + jc + 2 * lane);
            float2 Bpv = *(const float2*)(g_Bp + b * N_ + jc + 2 * lane);
            #pragma unroll
            for (int rr = 0; rr < 8; ++rr) {
                int row = w * 8 + rr;
                int2 av = *(const int2*)(sm + abuf + (uint32_t)row * 256 + (uint32_t)lane * 8);
                float Ar = sA[row], Apr = sAp[row];
                float p0 = (av.x > 0) ? fmaxf(Ar * Bv.x, Apr * Bpv.x) : 0.f;
                float p1 = (av.y > 0) ? fmaxf(Ar * Bv.y, Apr * Bpv.y) : 0.f;
                lp[rr] += p0 + p1;
                __nv_bfloat162 h2 = __float22bfloat162_rn(make_float2(p0, p1));
                float l0 = p0 - __bfloat162float(__low2bfloat16(h2));
                float l1 = p1 - __bfloat162float(__high2bfloat16(h2));
                __nv_bfloat162 l2 = __float22bfloat162_rn(make_float2(l0, l1));
                uint32_t boff = (uint32_t)row * 128 + (uint32_t)lane * 4;
                uint32_t sw = boff ^ (((uint32_t)(row & 7)) << 4);
                *(uint32_t*)(sm + OFF_PHI + sw) = *(uint32_t*)&h2;
                *(uint32_t*)(sm + OFF_PLO + sw) = *(uint32_t*)&l2;
            }
        }
        __syncthreads();

        // ---- MMA: warp w -> rows (w&3)*16, f-half (w>>2)*32 ----
        {
            int m0 = (w & 3) * 16;
            int f0 = (w >> 2) * 32;
            #pragma unroll
            for (int ks = 0; ks < 4; ++ks) {
                uint32_t ahi[4], alo[4];
                int arow = m0 + (lane & 15);
                uint32_t aoff = (uint32_t)arow * 128 + (uint32_t)ks * 32 + ((uint32_t)(lane >> 4)) * 16;
                uint32_t asw = aoff ^ (((uint32_t)(arow & 7)) << 4);
                LDSM4(ahi, sb + OFF_PHI + asw);
                LDSM4(alo, sb + OFF_PLO + asw);
                #pragma unroll
                for (int g2 = 0; g2 < 2; ++g2) {
                    uint32_t bhi[4], blo[4];
                    int nrow = f0 + g2 * 16 + (lane & 15);
                    uint32_t boff = (uint32_t)nrow * 128 + (uint32_t)ks * 32 + ((uint32_t)(lane >> 4)) * 16;
                    uint32_t bsw = boff ^ (((uint32_t)(nrow & 7)) << 4);
                    LDSM4(bhi, sb + OFF_HHI + bsw);
                    LDSM4(blo, sb + OFF_HLO + bsw);
                    MMA_BF16(C[g2 * 2],     ahi, bhi[0], bhi[2]);
                    MMA_BF16(C[g2 * 2 + 1], ahi, bhi[1], bhi[3]);
                    MMA_BF16(C[g2 * 2],     ahi, blo[0], blo[2]);
                    MMA_BF16(C[g2 * 2 + 1], ahi, blo[1], blo[3]);
                    MMA_BF16(C[g2 * 2],     alo, bhi[0], bhi[2]);
                    MMA_BF16(C[g2 * 2 + 1], alo, bhi[1], bhi[3]);
                }
            }
        }
    }

    // ---- denominators ----
    #pragma unroll
    for (int rr = 0; rr < 8; ++rr) {
        float v = lp[rr];
        #pragma unroll
        for (int off = 16; off; off >>= 1) v += __shfl_xor_sync(0xffffffffu, v, off);
        if (lane == 0) g_l[s][i0 + w * 8 + rr] = v;
    }

    // ---- C frags -> g_acc ----
    {
        int r0 = i0 + (w & 3) * 16 + (lane >> 2);
        int f0 = (w >> 2) * 32 + (lane & 3) * 2;
        #pragma unroll
        for (int g = 0; g < 4; ++g) {
            float* o = g_acc[s] + (size_t)r0 * F_ + f0 + g * 8;
            *(float2*)o = make_float2(C[g][0], C[g][1]);
            *(float2*)(o + 8 * F_) = make_float2(C[g][2], C[g][3]);
        }
    }
}

// ---------------------------------------------------------------------------
// K4: combine splits, normalize, ELU, flag bad rows
// ---------------------------------------------------------------------------
__global__ void combine_kernel(float* __restrict__ out) {
    int idx = blockIdx.x * 256 + threadIdx.x;
    int row = idx >> 5;
    int fo = (idx & 31) * 2;
    float l = g_l[0][row] + g_l[1][row];
    if ((idx & 31) == 0 && !(l >= 1e-20f)) {
        int si = atomicAdd(&g_nbad, 1);
        g_bad[si] = row;
    }
    float inv = 1.f / l;
    size_t o = (size_t)row * F_ + fo;
    float2 u = *(const float2*)(g_acc[0] + o);
    float2 v = *(const float2*)(g_acc[1] + o);
    float o0 = (u.x + v.x) * inv;
    float o1 = (u.y + v.y) * inv;
    o0 = (o0 > 0.f) ? o0 : (__expf(o0) - 1.f);
    o1 = (o1 > 0.f) ? o1 : (__expf(o1) - 1.f);
    *(float2*)(out + o) = make_float2(o0, o1);
}

// ---------------------------------------------------------------------------
// K5: exact fp32 recompute of flagged rows
// ---------------------------------------------------------------------------
__global__ void __launch_bounds__(256) fallback_kernel(
    const int* __restrict__ adj, float* __restrict__ out)
{
    __shared__ float p_s[N_];
    __shared__ float red[4][64];
    __shared__ float lred[8];
    int t = threadIdx.x, w = t >> 5, lane = t & 31;
    int nb = g_nbad;
    for (int k = blockIdx.x; k < nb; k += gridDim.x) {
        int row = g_bad[k];
        int b = row >> 11;
        float A = g_A[row], Ap = g_Ap[row];
        float lpv = 0.f;
        for (int j = t; j < N_; j += 256) {
            int av = adj[(size_t)row * N_ + j];
            float p = (av > 0) ? fmaxf(A * g_B[b * N_ + j], Ap * g_Bp[b * N_ + j]) : 0.f;
            p_s[j] = p;
            lpv += p;
        }
        #pragma unroll
        for (int off = 16; off; off >>= 1) lpv += __shfl_xor_sync(0xffffffffu, lpv, off);
        if (lane == 0) lred[w] = lpv;
        __syncthreads();
        float l = 0.f;
        #pragma unroll
        for (int q = 0; q < 8; ++q) l += lred[q];
        int f = t & 63, seg = t >> 6;
        float acc = 0.f;
        const float* hb = g_h + ((size_t)b * N_ + seg * 512) * F_ + f;
        for (int j = 0; j < 512; ++j) acc = fmaf(p_s[seg * 512 + j], hb[(size_t)j * F_], acc);
        red[seg][f] = acc;
        __syncthreads();
        if (t < 64) {
            float v = (red[0][t] + red[1][t] + red[2][t] + red[3][t]) / l;
            out[(size_t)row * F_ + t] = (v > 0.f) ? v : (__expf(v) - 1.f);
        }
        __syncthreads();
    }
}

extern "C" void kernel_launch(void* const* d_in, const int* in_sizes, int n_in,
                              void* d_out, int out_size)
{
    const float* x   = (const float*)d_in[0];
    const int*   adj = (const int*)  d_in[1];
    const float* W   = (const float*)d_in[2];
    const float* a   = (const float*)d_in[3];
    float* out = (float*)d_out;

    cudaFuncSetAttribute(attn_kernel, cudaFuncAttributeMaxDynamicSharedMemorySize, DSMEM);

    prep_kernel<<<(B_ * N_) / 16, 1024>>>(x, W, a);
    factors_kernel<<<B_, 256>>>();
    attn_kernel<<<256 * SPLITS, 256, DSMEM>>>(adj);
    combine_kernel<<<(B_ * N_ * 32) / 256, 256>>>(out);
    fallback_kernel<<<64, 256>>>(adj, out);
}

// round 7
// speedup vs baseline: 2.7401x; 1.0530x over previous
#include <cuda_runtime.h>
#include <cuda_bf16.h>
#include <cstdint>

static constexpr int B_ = 8;
static constexpr int N_ = 2048;
static constexpr int F_ = 64;
static constexpr float ALPHA_ = 0.2f;
static constexpr int SPLITS = 2;
static constexpr int JS = N_ / SPLITS;   // 1024
static constexpr int NCH = JS / 64;      // 16 chunks per block

// -------- scratch (no cudaMalloc allowed) --------
__device__ float g_h[B_ * N_ * F_];
__device__ float g_s1[B_ * N_];
__device__ float g_s2[B_ * N_];
__device__ float g_A [B_ * N_];
__device__ float g_Ap[B_ * N_];
__device__ float g_B [B_ * N_];
__device__ float g_Bp[B_ * N_];
__device__ __nv_bfloat16 g_hT_hi[B_ * F_ * N_];   // [b][f][n]
__device__ __nv_bfloat16 g_hT_lo[B_ * F_ * N_];
__device__ float g_acc[SPLITS][B_ * N_ * F_];
__device__ float g_l  [SPLITS][B_ * N_];
__device__ int g_nbad;
__device__ int g_bad[B_ * N_];

__device__ __forceinline__ uint32_t smem_u32(const void* p) {
    uint32_t a;
    asm("{ .reg .u64 t; cvta.to.shared.u64 t, %1; cvt.u32.u64 %0, t; }" : "=r"(a) : "l"(p));
    return a;
}

#define LDSM4(r, addr) \
    asm volatile("ldmatrix.sync.aligned.m8n8.x4.shared.b16 {%0,%1,%2,%3}, [%4];" \
        : "=r"((r)[0]), "=r"((r)[1]), "=r"((r)[2]), "=r"((r)[3]) : "r"(addr))

#define MMA_BF16(C, a, b0, b1) \
    asm volatile("mma.sync.aligned.m16n8k16.row.col.f32.bf16.bf16.f32 " \
        "{%0,%1,%2,%3}, {%4,%5,%6,%7}, {%8,%9}, {%0,%1,%2,%3};" \
        : "+f"((C)[0]), "+f"((C)[1]), "+f"((C)[2]), "+f"((C)[3]) \
        : "r"((a)[0]), "r"((a)[1]), "r"((a)[2]), "r"((a)[3]), "r"(b0), "r"(b1))

// ---------------------------------------------------------------------------
// K1: h = x@W ; s1,s2 ; transposed bf16 hi/lo copies of h
// ---------------------------------------------------------------------------
__global__ void __launch_bounds__(1024) prep_kernel(
    const float* __restrict__ x, const float* __restrict__ W, const float* __restrict__ a)
{
    __shared__ float W_s[F_ * F_];
    __shared__ float x_s[16][F_];
    __shared__ float h_sh[16][F_ + 1];
    __shared__ float red[16][2][2];

    int t = threadIdx.x, tx = t & 63, ty = t >> 6;
    int row0 = blockIdx.x * 16;
    int row = row0 + ty;

    #pragma unroll
    for (int k = 0; k < 4; ++k) W_s[t + k * 1024] = W[t + k * 1024];
    x_s[ty][tx] = x[(size_t)row * F_ + tx];
    __syncthreads();

    float h = 0.f;
    #pragma unroll
    for (int k = 0; k < F_; ++k) h = fmaf(x_s[ty][k], W_s[k * F_ + tx], h);
    g_h[(size_t)row * F_ + tx] = h;
    h_sh[ty][tx] = h;

    float v1 = h * a[tx];
    float v2 = h * a[F_ + tx];
    #pragma unroll
    for (int off = 16; off; off >>= 1) {
        v1 += __shfl_xor_sync(0xffffffffu, v1, off);
        v2 += __shfl_xor_sync(0xffffffffu, v2, off);
    }
    if ((tx & 31) == 0) { red[ty][tx >> 5][0] = v1; red[ty][tx >> 5][1] = v2; }
    __syncthreads();
    if (tx == 0) {
        g_s1[row] = red[ty][0][0] + red[ty][1][0];
        g_s2[row] = red[ty][0][1] + red[ty][1][1];
    }

    int f = t >> 4, rr = t & 15;
    float v = h_sh[rr][f];
    __nv_bfloat16 hi = __float2bfloat16(v);
    float lov = v - __bfloat162float(hi);
    int b = row0 >> 11;
    size_t o = ((size_t)(b * F_ + f)) * N_ + (row0 & (N_ - 1)) + rr;
    g_hT_hi[o] = hi;
    g_hT_lo[o] = __float2bfloat16(lov);
}

// ---------------------------------------------------------------------------
// K2: per-batch c (max of warp maxes) / c2 (min of warp maxes) + factors
// ---------------------------------------------------------------------------
__global__ void __launch_bounds__(256) factors_kernel() {
    __shared__ float red[8];
    int b = blockIdx.x, t = threadIdx.x, w = t >> 5, lane = t & 31;
    if (b == 0 && t == 0) g_nbad = 0;

    float m = -3.4e38f;
    for (int i = t; i < N_; i += 256) m = fmaxf(m, g_s2[b * N_ + i]);
    #pragma unroll
    for (int off = 16; off; off >>= 1) m = fmaxf(m, __shfl_xor_sync(0xffffffffu, m, off));
    if (lane == 0) red[w] = m;
    __syncthreads();
    float c = -3.4e38f, c2 = 3.4e38f;
    #pragma unroll
    for (int q = 0; q < 8; ++q) { c = fmaxf(c, red[q]); c2 = fminf(c2, red[q]); }

    for (int i = t; i < N_; i += 256) {
        int gi = b * N_ + i;
        float s1 = g_s1[gi];
        float u  = s1 + c;
        float u2 = s1 + c2;
        float lr_u  = (u  > 0.f) ? u  : ALPHA_ * u;
        float lr_u2 = (u2 > 0.f) ? u2 : ALPHA_ * u2;
        float mm = fmaxf(lr_u2, lr_u - 60.f);
        g_A [gi] = expf(u - mm);
        g_Ap[gi] = expf(ALPHA_ * u - mm);
        float v = g_s2[gi] - c;
        g_B [gi] = expf(v);
        g_Bp[gi] = expf(ALPHA_ * v);
    }
}

// ---------------------------------------------------------------------------
// K3: attention partials via HMMA, single-barrier software pipeline.
// 512 blocks = 256 row-tiles(64) x 2 j-splits; 256 thr = 8 warps.
// iter i: produce(i)->buf[i&1]; prefetch(i+1) to regs; bar; MMA(i).
// ---------------------------------------------------------------------------
static constexpr uint32_t STG    = 32768;   // per-stage: Phi 8K | Plo 8K | Hhi 8K | Hlo 8K
static constexpr uint32_t O_PHI  = 0;
static constexpr uint32_t O_PLO  = 8192;
static constexpr uint32_t O_HHI  = 16384;
static constexpr uint32_t O_HLO  = 24576;
static constexpr uint32_t OFF_B  = 65536;   // 4KB
static constexpr uint32_t OFF_BP = 69632;   // 4KB
static constexpr uint32_t OFF_A  = 73728;   // 256B
static constexpr uint32_t OFF_AP = 73984;   // 256B
static constexpr uint32_t DSMEM  = 74240;

__global__ void __launch_bounds__(256) attn_kernel(const int* __restrict__ adj)
{
    extern __shared__ __align__(128) char sm[];
    uint32_t sb = smem_u32(sm);

    int t = threadIdx.x, w = t >> 5, lane = t & 31;
    int tile = blockIdx.x & 255;
    int s = blockIdx.x >> 8;
    int i0 = tile * 64;
    int b = i0 >> 11;
    int j0 = s * JS;

    float* sA  = (float*)(sm + OFF_A);
    float* sAp = (float*)(sm + OFF_AP);
    float* sB  = (float*)(sm + OFF_B);
    float* sBp = (float*)(sm + OFF_BP);
    if (t < 64) { sA[t] = g_A[i0 + t]; sAp[t] = g_Ap[i0 + t]; }
    #pragma unroll
    for (int k = 0; k < 4; ++k) {   // 1024 floats each from g_B/g_Bp
        int u = t + k * 256;
        sB [u] = g_B [b * N_ + j0 + u];
        sBp[u] = g_Bp[b * N_ + j0 + u];
    }
    __syncthreads();

    float C[4][4];
    #pragma unroll
    for (int g = 0; g < 4; ++g)
        #pragma unroll
        for (int q = 0; q < 4; ++q) C[g][q] = 0.f;
    float lp[8];
    #pragma unroll
    for (int r = 0; r < 8; ++r) lp[r] = 0.f;

    // ---- prefetch registers for chunk 0 ----
    int2  apre[8];
    uint4 hhp[2], hlp[2];
    {
        int jc = j0;
        #pragma unroll
        for (int rr = 0; rr < 8; ++rr)
            apre[rr] = ((const int2*)(adj + (size_t)(i0 + w * 8 + rr) * N_ + jc))[lane];
        #pragma unroll
        for (int pass = 0; pass < 2; ++pass) {
            int u = t + pass * 256;
            int f = u >> 3, q = u & 7;
            size_t src = ((size_t)(b * F_ + f)) * N_ + jc + q * 8;
            hhp[pass] = *(const uint4*)(g_hT_hi + src);
            hlp[pass] = *(const uint4*)(g_hT_lo + src);
        }
    }

    for (int ci = 0; ci < NCH; ++ci) {
        uint32_t stg = sb + (uint32_t)(ci & 1) * STG;
        char*    stgp = sm + (uint32_t)(ci & 1) * STG;

        // ---- produce chunk ci from prefetched regs ----
        {
            // H tiles
            #pragma unroll
            for (int pass = 0; pass < 2; ++pass) {
                int u = t + pass * 256;
                int f = u >> 3, q = u & 7;
                uint32_t boff = (uint32_t)f * 128 + (uint32_t)q * 16;
                uint32_t sw = boff ^ (((uint32_t)(f & 7)) << 4);
                *(uint4*)(stgp + O_HHI + sw) = hhp[pass];
                *(uint4*)(stgp + O_HLO + sw) = hlp[pass];
            }
            // P tiles
            float2 Bv  = *(const float2*)(sB  + ci * 64 + 2 * lane);
            float2 Bpv = *(const float2*)(sBp + ci * 64 + 2 * lane);
            #pragma unroll
            for (int rr = 0; rr < 8; ++rr) {
                int row = w * 8 + rr;
                int2 av = apre[rr];
                float Ar = sA[row], Apr = sAp[row];
                float p0 = (av.x > 0) ? fmaxf(Ar * Bv.x, Apr * Bpv.x) : 0.f;
                float p1 = (av.y > 0) ? fmaxf(Ar * Bv.y, Apr * Bpv.y) : 0.f;
                lp[rr] += p0 + p1;
                __nv_bfloat162 h2 = __float22bfloat162_rn(make_float2(p0, p1));
                float l0 = p0 - __bfloat162float(__low2bfloat16(h2));
                float l1 = p1 - __bfloat162float(__high2bfloat16(h2));
                __nv_bfloat162 l2 = __float22bfloat162_rn(make_float2(l0, l1));
                uint32_t boff = (uint32_t)row * 128 + (uint32_t)lane * 4;
                uint32_t sw = boff ^ (((uint32_t)(row & 7)) << 4);
                *(uint32_t*)(stgp + O_PHI + sw) = *(uint32_t*)&h2;
                *(uint32_t*)(stgp + O_PLO + sw) = *(uint32_t*)&l2;
            }
        }

        // ---- prefetch chunk ci+1 (latency hidden behind bar + MMA) ----
        if (ci + 1 < NCH) {
            int jn = j0 + (ci + 1) * 64;
            #pragma unroll
            for (int rr = 0; rr < 8; ++rr)
                apre[rr] = ((const int2*)(adj + (size_t)(i0 + w * 8 + rr) * N_ + jn))[lane];
            #pragma unroll
            for (int pass = 0; pass < 2; ++pass) {
                int u = t + pass * 256;
                int f = u >> 3, q = u & 7;
                size_t src = ((size_t)(b * F_ + f)) * N_ + jn + q * 8;
                hhp[pass] = *(const uint4*)(g_hT_hi + src);
                hlp[pass] = *(const uint4*)(g_hT_lo + src);
            }
        }

        __syncthreads();

        // ---- MMA chunk ci: warp w -> rows (w&3)*16, f-half (w>>2)*32 ----
        {
            int m0 = (w & 3) * 16;
            int f0 = (w >> 2) * 32;
            #pragma unroll
            for (int ks = 0; ks < 4; ++ks) {
                uint32_t ahi[4], alo[4];
                int arow = m0 + (lane & 15);
                uint32_t aoff = (uint32_t)arow * 128 + (uint32_t)ks * 32 + ((uint32_t)(lane >> 4)) * 16;
                uint32_t asw = aoff ^ (((uint32_t)(arow & 7)) << 4);
                LDSM4(ahi, stg + O_PHI + asw);
                LDSM4(alo, stg + O_PLO + asw);
                #pragma unroll
                for (int g2 = 0; g2 < 2; ++g2) {
                    uint32_t bhi[4], blo[4];
                    int nrow = f0 + g2 * 16 + (lane & 15);
                    uint32_t boff = (uint32_t)nrow * 128 + (uint32_t)ks * 32 + ((uint32_t)(lane >> 4)) * 16;
                    uint32_t bsw = boff ^ (((uint32_t)(nrow & 7)) << 4);
                    LDSM4(bhi, stg + O_HHI + bsw);
                    LDSM4(blo, stg + O_HLO + bsw);
                    MMA_BF16(C[g2 * 2],     ahi, bhi[0], bhi[2]);
                    MMA_BF16(C[g2 * 2 + 1], ahi, bhi[1], bhi[3]);
                    MMA_BF16(C[g2 * 2],     ahi, blo[0], blo[2]);
                    MMA_BF16(C[g2 * 2 + 1], ahi, blo[1], blo[3]);
                    MMA_BF16(C[g2 * 2],     alo, bhi[0], bhi[2]);
                    MMA_BF16(C[g2 * 2 + 1], alo, bhi[1], bhi[3]);
                }
            }
        }
    }

    // ---- denominators ----
    #pragma unroll
    for (int rr = 0; rr < 8; ++rr) {
        float v = lp[rr];
        #pragma unroll
        for (int off = 16; off; off >>= 1) v += __shfl_xor_sync(0xffffffffu, v, off);
        if (lane == 0) g_l[s][i0 + w * 8 + rr] = v;
    }

    // ---- C frags -> g_acc ----
    {
        int r0 = i0 + (w & 3) * 16 + (lane >> 2);
        int f0 = (w >> 2) * 32 + (lane & 3) * 2;
        #pragma unroll
        for (int g = 0; g < 4; ++g) {
            float* o = g_acc[s] + (size_t)r0 * F_ + f0 + g * 8;
            *(float2*)o = make_float2(C[g][0], C[g][1]);
            *(float2*)(o + 8 * F_) = make_float2(C[g][2], C[g][3]);
        }
    }
}

// ---------------------------------------------------------------------------
// K4: combine splits, normalize, ELU, flag bad rows
// ---------------------------------------------------------------------------
__global__ void combine_kernel(float* __restrict__ out) {
    int idx = blockIdx.x * 256 + threadIdx.x;
    int row = idx >> 5;
    int fo = (idx & 31) * 2;
    float l = g_l[0][row] + g_l[1][row];
    if ((idx & 31) == 0 && !(l >= 1e-20f)) {
        int si = atomicAdd(&g_nbad, 1);
        g_bad[si] = row;
    }
    float inv = 1.f / l;
    size_t o = (size_t)row * F_ + fo;
    float2 u = *(const float2*)(g_acc[0] + o);
    float2 v = *(const float2*)(g_acc[1] + o);
    float o0 = (u.x + v.x) * inv;
    float o1 = (u.y + v.y) * inv;
    o0 = (o0 > 0.f) ? o0 : (__expf(o0) - 1.f);
    o1 = (o1 > 0.f) ? o1 : (__expf(o1) - 1.f);
    *(float2*)(out + o) = make_float2(o0, o1);
}

// ---------------------------------------------------------------------------
// K5: exact fp32 recompute of flagged rows
// ---------------------------------------------------------------------------
__global__ void __launch_bounds__(256) fallback_kernel(
    const int* __restrict__ adj, float* __restrict__ out)
{
    __shared__ float p_s[N_];
    __shared__ float red[4][64];
    __shared__ float lred[8];
    int t = threadIdx.x, w = t >> 5, lane = t & 31;
    int nb = g_nbad;
    for (int k = blockIdx.x; k < nb; k += gridDim.x) {
        int row = g_bad[k];
        int b = row >> 11;
        float A = g_A[row], Ap = g_Ap[row];
        float lpv = 0.f;
        for (int j = t; j < N_; j += 256) {
            int av = adj[(size_t)row * N_ + j];
            float p = (av > 0) ? fmaxf(A * g_B[b * N_ + j], Ap * g_Bp[b * N_ + j]) : 0.f;
            p_s[j] = p;
            lpv += p;
        }
        #pragma unroll
        for (int off = 16; off; off >>= 1) lpv += __shfl_xor_sync(0xffffffffu, lpv, off);
        if (lane == 0) lred[w] = lpv;
        __syncthreads();
        float l = 0.f;
        #pragma unroll
        for (int q = 0; q < 8; ++q) l += lred[q];
        int f = t & 63, seg = t >> 6;
        float acc = 0.f;
        const float* hb = g_h + ((size_t)b * N_ + seg * 512) * F_ + f;
        for (int j = 0; j < 512; ++j) acc = fmaf(p_s[seg * 512 + j], hb[(size_t)j * F_], acc);
        red[seg][f] = acc;
        __syncthreads();
        if (t < 64) {
            float v = (red[0][t] + red[1][t] + red[2][t] + red[3][t]) / l;
            out[(size_t)row * F_ + t] = (v > 0.f) ? v : (__expf(v) - 1.f);
        }
        __syncthreads();
    }
}

extern "C" void kernel_launch(void* const* d_in, const int* in_sizes, int n_in,
                              void* d_out, int out_size)
{
    const float* x   = (const float*)d_in[0];
    const int*   adj = (const int*)  d_in[1];
    const float* W   = (const float*)d_in[2];
    const float* a   = (const float*)d_in[3];
    float* out = (float*)d_out;

    cudaFuncSetAttribute(attn_kernel, cudaFuncAttributeMaxDynamicSharedMemorySize, DSMEM);

    prep_kernel<<<(B_ * N_) / 16, 1024>>>(x, W, a);
    factors_kernel<<<B_, 256>>>();
    attn_kernel<<<256 * SPLITS, 256, DSMEM>>>(adj);
    combine_kernel<<<(B_ * N_ * 32) / 256, 256>>>(out);
    fallback_kernel<<<64, 256>>>(adj, out);
}

// round 8
// speedup vs baseline: 2.8535x; 1.0414x over previous
#include <cuda_runtime.h>
#include <cuda_bf16.h>
#include <cstdint>

static constexpr int B_ = 8;
static constexpr int N_ = 2048;
static constexpr int F_ = 64;
static constexpr float ALPHA_ = 0.2f;
static constexpr int SPLITS = 2;
static constexpr int JS = N_ / SPLITS;   // 1024
static constexpr int NCH = JS / 64;      // 16
static constexpr int TI = 128;           // rows per block

// -------- scratch (no cudaMalloc allowed) --------
__device__ float g_h[B_ * N_ * F_];
__device__ float g_s1[B_ * N_];
__device__ float g_s2[B_ * N_];
__device__ float g_A [B_ * N_];
__device__ float g_Ap[B_ * N_];
__device__ float g_B [B_ * N_];
__device__ float g_Bp[B_ * N_];
__device__ __nv_bfloat16 g_hT_hi[B_ * F_ * N_];   // [b][f][n]
__device__ __nv_bfloat16 g_hT_lo[B_ * F_ * N_];
__device__ float g_acc[SPLITS][B_ * N_ * F_];
__device__ float g_l  [SPLITS][B_ * N_];
__device__ int g_nbad;
__device__ int g_bad[B_ * N_];

__device__ __forceinline__ uint32_t smem_u32(const void* p) {
    uint32_t a;
    asm("{ .reg .u64 t; cvta.to.shared.u64 t, %1; cvt.u32.u64 %0, t; }" : "=r"(a) : "l"(p));
    return a;
}

#define LDSM4(r, addr) \
    asm volatile("ldmatrix.sync.aligned.m8n8.x4.shared.b16 {%0,%1,%2,%3}, [%4];" \
        : "=r"((r)[0]), "=r"((r)[1]), "=r"((r)[2]), "=r"((r)[3]) : "r"(addr))

#define MMA_BF16(C, a, b0, b1) \
    asm volatile("mma.sync.aligned.m16n8k16.row.col.f32.bf16.bf16.f32 " \
        "{%0,%1,%2,%3}, {%4,%5,%6,%7}, {%8,%9}, {%0,%1,%2,%3};" \
        : "+f"((C)[0]), "+f"((C)[1]), "+f"((C)[2]), "+f"((C)[3]) \
        : "r"((a)[0]), "r"((a)[1]), "r"((a)[2]), "r"((a)[3]), "r"(b0), "r"(b1))

#define CP16(dst, src) \
    asm volatile("cp.async.cg.shared.global [%0], [%1], 16;" :: "r"(dst), "l"(src))
#define CP_COMMIT() asm volatile("cp.async.commit_group;" ::: "memory")
#define CP_WAIT0()  asm volatile("cp.async.wait_group 0;" ::: "memory")

// ---------------------------------------------------------------------------
// K1: h = x@W ; s1,s2 ; transposed bf16 hi/lo copies of h
// ---------------------------------------------------------------------------
__global__ void __launch_bounds__(1024) prep_kernel(
    const float* __restrict__ x, const float* __restrict__ W, const float* __restrict__ a)
{
    __shared__ float W_s[F_ * F_];
    __shared__ float x_s[16][F_];
    __shared__ float h_sh[16][F_ + 1];
    __shared__ float red[16][2][2];

    int t = threadIdx.x, tx = t & 63, ty = t >> 6;
    int row0 = blockIdx.x * 16;
    int row = row0 + ty;

    #pragma unroll
    for (int k = 0; k < 4; ++k) W_s[t + k * 1024] = W[t + k * 1024];
    x_s[ty][tx] = x[(size_t)row * F_ + tx];
    __syncthreads();

    float h = 0.f;
    #pragma unroll
    for (int k = 0; k < F_; ++k) h = fmaf(x_s[ty][k], W_s[k * F_ + tx], h);
    g_h[(size_t)row * F_ + tx] = h;
    h_sh[ty][tx] = h;

    float v1 = h * a[tx];
    float v2 = h * a[F_ + tx];
    #pragma unroll
    for (int off = 16; off; off >>= 1) {
        v1 += __shfl_xor_sync(0xffffffffu, v1, off);
        v2 += __shfl_xor_sync(0xffffffffu, v2, off);
    }
    if ((tx & 31) == 0) { red[ty][tx >> 5][0] = v1; red[ty][tx >> 5][1] = v2; }
    __syncthreads();
    if (tx == 0) {
        g_s1[row] = red[ty][0][0] + red[ty][1][0];
        g_s2[row] = red[ty][0][1] + red[ty][1][1];
    }

    int f = t >> 4, rr = t & 15;
    float v = h_sh[rr][f];
    __nv_bfloat16 hi = __float2bfloat16(v);
    float lov = v - __bfloat162float(hi);
    int b = row0 >> 11;
    size_t o = ((size_t)(b * F_ + f)) * N_ + (row0 & (N_ - 1)) + rr;
    g_hT_hi[o] = hi;
    g_hT_lo[o] = __float2bfloat16(lov);
}

// ---------------------------------------------------------------------------
// K2: per-batch c (max of warp maxes) / c2 (min of warp maxes) + factors
// ---------------------------------------------------------------------------
__global__ void __launch_bounds__(256) factors_kernel() {
    __shared__ float red[8];
    int b = blockIdx.x, t = threadIdx.x, w = t >> 5, lane = t & 31;
    if (b == 0 && t == 0) g_nbad = 0;

    float m = -3.4e38f;
    for (int i = t; i < N_; i += 256) m = fmaxf(m, g_s2[b * N_ + i]);
    #pragma unroll
    for (int off = 16; off; off >>= 1) m = fmaxf(m, __shfl_xor_sync(0xffffffffu, m, off));
    if (lane == 0) red[w] = m;
    __syncthreads();
    float c = -3.4e38f, c2 = 3.4e38f;
    #pragma unroll
    for (int q = 0; q < 8; ++q) { c = fmaxf(c, red[q]); c2 = fminf(c2, red[q]); }

    for (int i = t; i < N_; i += 256) {
        int gi = b * N_ + i;
        float s1 = g_s1[gi];
        float u  = s1 + c;
        float u2 = s1 + c2;
        float lr_u  = (u  > 0.f) ? u  : ALPHA_ * u;
        float lr_u2 = (u2 > 0.f) ? u2 : ALPHA_ * u2;
        float mm = fmaxf(lr_u2, lr_u - 60.f);
        g_A [gi] = expf(u - mm);
        g_Ap[gi] = expf(ALPHA_ * u - mm);
        float v = g_s2[gi] - c;
        g_B [gi] = expf(v);
        g_Bp[gi] = expf(ALPHA_ * v);
    }
}

// ---------------------------------------------------------------------------
// K3: attention partials via HMMA. 256 blocks = 128 tiles(128 rows) x 2 splits.
// 256 thr = 8 warps. produce: warp w rows w*16..+15, thread = 4 rows x 8 j.
// MMA: warp w -> m 32 rows (w&3)*32, f-half (w>>2)*32. H via cp.async.
// ---------------------------------------------------------------------------
static constexpr uint32_t STG    = 49152;   // Phi 16K | Plo 16K | Hhi 8K | Hlo 8K
static constexpr uint32_t O_PHI  = 0;
static constexpr uint32_t O_PLO  = 16384;
static constexpr uint32_t O_HHI  = 32768;
static constexpr uint32_t O_HLO  = 40960;
static constexpr uint32_t OFF_B  = 98304;   // 4KB (JS floats)
static constexpr uint32_t OFF_BP = 102400;  // 4KB
static constexpr uint32_t OFF_A  = 106496;  // 512B
static constexpr uint32_t OFF_AP = 107008;  // 512B
static constexpr uint32_t DSMEM  = 107520;

__global__ void __launch_bounds__(256, 2) attn_kernel(const int* __restrict__ adj)
{
    extern __shared__ __align__(128) char sm[];
    uint32_t sb = smem_u32(sm);

    int t = threadIdx.x, w = t >> 5, lane = t & 31;
    int tile = blockIdx.x & 127;
    int s = blockIdx.x >> 7;
    int i0 = tile * TI;
    int b = i0 >> 11;
    int j0 = s * JS;

    float* sA  = (float*)(sm + OFF_A);
    float* sAp = (float*)(sm + OFF_AP);
    float* sB  = (float*)(sm + OFF_B);
    float* sBp = (float*)(sm + OFF_BP);
    if (t < 128) { sA[t] = g_A[i0 + t]; sAp[t] = g_Ap[i0 + t]; }
    #pragma unroll
    for (int k = 0; k < 4; ++k) {
        int u = t + k * 256;
        sB [u] = g_B [b * N_ + j0 + u];
        sBp[u] = g_Bp[b * N_ + j0 + u];
    }

    // produce-role indices: 4 rows x 8 j per thread
    int q4 = lane >> 3;          // row quarter 0..3
    int jg = lane & 7;           // j-group (8 j)
    int rbase = w * 16 + q4 * 4; // first of 4 rows

    float C[2][4][4];
    #pragma unroll
    for (int mt = 0; mt < 2; ++mt)
        #pragma unroll
        for (int g = 0; g < 4; ++g)
            #pragma unroll
            for (int qq = 0; qq < 4; ++qq) C[mt][g][qq] = 0.f;
    float lp[4] = {0.f, 0.f, 0.f, 0.f};

    // ---- prologue: H(0) via cp.async, adj(0) to regs ----
    {
        #pragma unroll
        for (int pass = 0; pass < 2; ++pass) {
            int u = t + pass * 256;
            int f = u >> 3, qq = u & 7;
            size_t src = ((size_t)(b * F_ + f)) * N_ + j0 + qq * 8;
            uint32_t sw = ((uint32_t)f * 128 + (uint32_t)qq * 16) ^ (((uint32_t)(f & 7)) << 4);
            CP16(sb + O_HHI + sw, g_hT_hi + src);
            CP16(sb + O_HLO + sw, g_hT_lo + src);
        }
        CP_COMMIT();
    }
    int4 apre[4][2];
    #pragma unroll
    for (int rr = 0; rr < 4; ++rr) {
        const int4* p = (const int4*)(adj + (size_t)(i0 + rbase + rr) * N_ + j0 + jg * 8);
        apre[rr][0] = p[0];
        apre[rr][1] = p[1];
    }
    __syncthreads();   // consts visible

    for (int ci = 0; ci < NCH; ++ci) {
        uint32_t stg = sb + (uint32_t)(ci & 1) * STG;
        char*   stgp = sm + (uint32_t)(ci & 1) * STG;

        // ---- produce P(ci): 4 rows x 8 j, STS.128 ----
        {
            float4 Bv0  = *(const float4*)(sB  + ci * 64 + jg * 8);
            float4 Bv1  = *(const float4*)(sB  + ci * 64 + jg * 8 + 4);
            float4 Bp0  = *(const float4*)(sBp + ci * 64 + jg * 8);
            float4 Bp1  = *(const float4*)(sBp + ci * 64 + jg * 8 + 4);
            #pragma unroll
            for (int rr = 0; rr < 4; ++rr) {
                int R = rbase + rr;
                float Ar = sA[R], Apr = sAp[R];
                int4 a0 = apre[rr][0], a1 = apre[rr][1];
                float p0 = (a0.x > 0) ? fmaxf(Ar * Bv0.x, Apr * Bp0.x) : 0.f;
                float p1 = (a0.y > 0) ? fmaxf(Ar * Bv0.y, Apr * Bp0.y) : 0.f;
                float p2 = (a0.z > 0) ? fmaxf(Ar * Bv0.z, Apr * Bp0.z) : 0.f;
                float p3 = (a0.w > 0) ? fmaxf(Ar * Bv0.w, Apr * Bp0.w) : 0.f;
                float p4 = (a1.x > 0) ? fmaxf(Ar * Bv1.x, Apr * Bp1.x) : 0.f;
                float p5 = (a1.y > 0) ? fmaxf(Ar * Bv1.y, Apr * Bp1.y) : 0.f;
                float p6 = (a1.z > 0) ? fmaxf(Ar * Bv1.z, Apr * Bp1.z) : 0.f;
                float p7 = (a1.w > 0) ? fmaxf(Ar * Bv1.w, Apr * Bp1.w) : 0.f;
                lp[rr] += ((p0 + p1) + (p2 + p3)) + ((p4 + p5) + (p6 + p7));

                __nv_bfloat162 h01 = __float22bfloat162_rn(make_float2(p0, p1));
                __nv_bfloat162 h23 = __float22bfloat162_rn(make_float2(p2, p3));
                __nv_bfloat162 h45 = __float22bfloat162_rn(make_float2(p4, p5));
                __nv_bfloat162 h67 = __float22bfloat162_rn(make_float2(p6, p7));
                __nv_bfloat162 l01 = __float22bfloat162_rn(make_float2(
                    p0 - __bfloat162float(__low2bfloat16(h01)), p1 - __bfloat162float(__high2bfloat16(h01))));
                __nv_bfloat162 l23 = __float22bfloat162_rn(make_float2(
                    p2 - __bfloat162float(__low2bfloat16(h23)), p3 - __bfloat162float(__high2bfloat16(h23))));
                __nv_bfloat162 l45 = __float22bfloat162_rn(make_float2(
                    p4 - __bfloat162float(__low2bfloat16(h45)), p5 - __bfloat162float(__high2bfloat16(h45))));
                __nv_bfloat162 l67 = __float22bfloat162_rn(make_float2(
                    p6 - __bfloat162float(__low2bfloat16(h67)), p7 - __bfloat162float(__high2bfloat16(h67))));

                uint32_t boff = (uint32_t)R * 128 + (uint32_t)jg * 16;
                uint32_t sw = boff ^ (((uint32_t)(R & 7)) << 4);
                uint4 hv = make_uint4(*(uint32_t*)&h01, *(uint32_t*)&h23, *(uint32_t*)&h45, *(uint32_t*)&h67);
                uint4 lv = make_uint4(*(uint32_t*)&l01, *(uint32_t*)&l23, *(uint32_t*)&l45, *(uint32_t*)&l67);
                *(uint4*)(stgp + O_PHI + sw) = hv;
                *(uint4*)(stgp + O_PLO + sw) = lv;
            }
        }

        // ---- prefetch adj(ci+1) into regs ----
        if (ci + 1 < NCH) {
            int jn = j0 + (ci + 1) * 64;
            #pragma unroll
            for (int rr = 0; rr < 4; ++rr) {
                const int4* p = (const int4*)(adj + (size_t)(i0 + rbase + rr) * N_ + jn + jg * 8);
                apre[rr][0] = p[0];
                apre[rr][1] = p[1];
            }
        }

        CP_WAIT0();        // H(ci) landed (this thread's copies)
        __syncthreads();   // all P(ci) + H(ci) visible; prev MMA done

        // ---- issue H(ci+1) cp.async (overlaps MMA + next produce) ----
        if (ci + 1 < NCH) {
            uint32_t nstg = sb + (uint32_t)((ci + 1) & 1) * STG;
            int jn = j0 + (ci + 1) * 64;
            #pragma unroll
            for (int pass = 0; pass < 2; ++pass) {
                int u = t + pass * 256;
                int f = u >> 3, qq = u & 7;
                size_t src = ((size_t)(b * F_ + f)) * N_ + jn + qq * 8;
                uint32_t sw = ((uint32_t)f * 128 + (uint32_t)qq * 16) ^ (((uint32_t)(f & 7)) << 4);
                CP16(nstg + O_HHI + sw, g_hT_hi + src);
                CP16(nstg + O_HLO + sw, g_hT_lo + src);
            }
            CP_COMMIT();
        }

        // ---- MMA(ci): m0=(w&3)*32, f0=(w>>2)*32 ----
        {
            int m0 = (w & 3) * 32;
            int f0 = (w >> 2) * 32;
            #pragma unroll
            for (int ks = 0; ks < 4; ++ks) {
                uint32_t bhi[2][4], blo[2][4];
                #pragma unroll
                for (int nb = 0; nb < 2; ++nb) {
                    int nrow = f0 + nb * 16 + (lane & 15);
                    uint32_t boff = (uint32_t)nrow * 128 + (uint32_t)ks * 32 + ((uint32_t)(lane >> 4)) * 16;
                    uint32_t bsw = boff ^ (((uint32_t)(nrow & 7)) << 4);
                    LDSM4(bhi[nb], stg + O_HHI + bsw);
                    LDSM4(blo[nb], stg + O_HLO + bsw);
                }
                #pragma unroll
                for (int mt = 0; mt < 2; ++mt) {
                    uint32_t ahi[4], alo[4];
                    int arow = m0 + mt * 16 + (lane & 15);
                    uint32_t aoff = (uint32_t)arow * 128 + (uint32_t)ks * 32 + ((uint32_t)(lane >> 4)) * 16;
                    uint32_t asw = aoff ^ (((uint32_t)(arow & 7)) << 4);
                    LDSM4(ahi, stg + O_PHI + asw);
                    LDSM4(alo, stg + O_PLO + asw);
                    #pragma unroll
                    for (int nb = 0; nb < 2; ++nb) {
                        MMA_BF16(C[mt][nb * 2],     ahi, bhi[nb][0], bhi[nb][2]);
                        MMA_BF16(C[mt][nb * 2 + 1], ahi, bhi[nb][1], bhi[nb][3]);
                        MMA_BF16(C[mt][nb * 2],     ahi, blo[nb][0], blo[nb][2]);
                        MMA_BF16(C[mt][nb * 2 + 1], ahi, blo[nb][1], blo[nb][3]);
                        MMA_BF16(C[mt][nb * 2],     alo, bhi[nb][0], bhi[nb][2]);
                        MMA_BF16(C[mt][nb * 2 + 1], alo, bhi[nb][1], bhi[nb][3]);
                    }
                }
            }
        }
    }

    // ---- denominators: sum over 8 j-lanes of each row group ----
    #pragma unroll
    for (int rr = 0; rr < 4; ++rr) {
        float v = lp[rr];
        v += __shfl_xor_sync(0xffffffffu, v, 1);
        v += __shfl_xor_sync(0xffffffffu, v, 2);
        v += __shfl_xor_sync(0xffffffffu, v, 4);
        if (jg == 0) g_l[s][i0 + rbase + rr] = v;
    }

    // ---- C frags -> g_acc ----
    {
        int f0 = (w >> 2) * 32 + (lane & 3) * 2;
        #pragma unroll
        for (int mt = 0; mt < 2; ++mt) {
            int r0 = i0 + (w & 3) * 32 + mt * 16 + (lane >> 2);
            #pragma unroll
            for (int g = 0; g < 4; ++g) {
                float* o = g_acc[s] + (size_t)r0 * F_ + f0 + g * 8;
                *(float2*)o = make_float2(C[mt][g][0], C[mt][g][1]);
                *(float2*)(o + 8 * F_) = make_float2(C[mt][g][2], C[mt][g][3]);
            }
        }
    }
}

// ---------------------------------------------------------------------------
// K4: combine splits, normalize, ELU, flag bad rows
// ---------------------------------------------------------------------------
__global__ void combine_kernel(float* __restrict__ out) {
    int idx = blockIdx.x * 256 + threadIdx.x;
    int row = idx >> 5;
    int fo = (idx & 31) * 2;
    float l = g_l[0][row] + g_l[1][row];
    if ((idx & 31) == 0 && !(l >= 1e-20f)) {
        int si = atomicAdd(&g_nbad, 1);
        g_bad[si] = row;
    }
    float inv = 1.f / l;
    size_t o = (size_t)row * F_ + fo;
    float2 u = *(const float2*)(g_acc[0] + o);
    float2 v = *(const float2*)(g_acc[1] + o);
    float o0 = (u.x + v.x) * inv;
    float o1 = (u.y + v.y) * inv;
    o0 = (o0 > 0.f) ? o0 : (__expf(o0) - 1.f);
    o1 = (o1 > 0.f) ? o1 : (__expf(o1) - 1.f);
    *(float2*)(out + o) = make_float2(o0, o1);
}

// ---------------------------------------------------------------------------
// K5: exact fp32 recompute of flagged rows
// ---------------------------------------------------------------------------
__global__ void __launch_bounds__(256) fallback_kernel(
    const int* __restrict__ adj, float* __restrict__ out)
{
    __shared__ float p_s[N_];
    __shared__ float red[4][64];
    __shared__ float lred[8];
    int t = threadIdx.x, w = t >> 5, lane = t & 31;
    int nb = g_nbad;
    for (int k = blockIdx.x; k < nb; k += gridDim.x) {
        int row = g_bad[k];
        int b = row >> 11;
        float A = g_A[row], Ap = g_Ap[row];
        float lpv = 0.f;
        for (int j = t; j < N_; j += 256) {
            int av = adj[(size_t)row * N_ + j];
            float p = (av > 0) ? fmaxf(A * g_B[b * N_ + j], Ap * g_Bp[b * N_ + j]) : 0.f;
            p_s[j] = p;
            lpv += p;
        }
        #pragma unroll
        for (int off = 16; off; off >>= 1) lpv += __shfl_xor_sync(0xffffffffu, lpv, off);
        if (lane == 0) lred[w] = lpv;
        __syncthreads();
        float l = 0.f;
        #pragma unroll
        for (int q = 0; q < 8; ++q) l += lred[q];
        int f = t & 63, seg = t >> 6;
        float acc = 0.f;
        const float* hb = g_h + ((size_t)b * N_ + seg * 512) * F_ + f;
        for (int j = 0; j < 512; ++j) acc = fmaf(p_s[seg * 512 + j], hb[(size_t)j * F_], acc);
        red[seg][f] = acc;
        __syncthreads();
        if (t < 64) {
            float v = (red[0][t] + red[1][t] + red[2][t] + red[3][t]) / l;
            out[(size_t)row * F_ + t] = (v > 0.f) ? v : (__expf(v) - 1.f);
        }
        __syncthreads();
    }
}

extern "C" void kernel_launch(void* const* d_in, const int* in_sizes, int n_in,
                              void* d_out, int out_size)
{
    const float* x   = (const float*)d_in[0];
    const int*   adj = (const int*)  d_in[1];
    const float* W   = (const float*)d_in[2];
    const float* a   = (const float*)d_in[3];
    float* out = (float*)d_out;

    cudaFuncSetAttribute(attn_kernel, cudaFuncAttributeMaxDynamicSharedMemorySize, DSMEM);

    prep_kernel<<<(B_ * N_) / 16, 1024>>>(x, W, a);
    factors_kernel<<<B_, 256>>>();
    attn_kernel<<<(B_ * N_ / TI) * SPLITS, 256, DSMEM>>>(adj);
    combine_kernel<<<(B_ * N_ * 32) / 256, 256>>>(out);
    fallback_kernel<<<64, 256>>>(adj, out);
}

// round 9
// speedup vs baseline: 2.8997x; 1.0162x over previous
#include <cuda_runtime.h>
#include <cuda_bf16.h>
#include <cstdint>

static constexpr int B_ = 8;
static constexpr int N_ = 2048;
static constexpr int F_ = 64;
static constexpr float ALPHA_ = 0.2f;
static constexpr int SPLITS = 2;
static constexpr int JS = N_ / SPLITS;   // 1024
static constexpr int NCH = JS / 64;      // 16
static constexpr int TI = 128;           // rows per block

// -------- scratch (no cudaMalloc allowed) --------
__device__ float g_h[B_ * N_ * F_];
__device__ float g_s1[B_ * N_];
__device__ float g_s2[B_ * N_];
__device__ float g_A [B_ * N_];
__device__ float g_Ap[B_ * N_];
__device__ float g_B [B_ * N_];
__device__ float g_Bp[B_ * N_];
__device__ __nv_bfloat16 g_hT_hi[B_ * F_ * N_];   // [b][f][n]
__device__ __nv_bfloat16 g_hT_lo[B_ * F_ * N_];
__device__ float g_acc[SPLITS][B_ * N_ * F_];
__device__ float g_l  [SPLITS][B_ * N_];
__device__ int g_nbad;
__device__ int g_bad[B_ * N_];

__device__ __forceinline__ uint32_t smem_u32(const void* p) {
    uint32_t a;
    asm("{ .reg .u64 t; cvta.to.shared.u64 t, %1; cvt.u32.u64 %0, t; }" : "=r"(a) : "l"(p));
    return a;
}

#define LDSM4(r, addr) \
    asm volatile("ldmatrix.sync.aligned.m8n8.x4.shared.b16 {%0,%1,%2,%3}, [%4];" \
        : "=r"((r)[0]), "=r"((r)[1]), "=r"((r)[2]), "=r"((r)[3]) : "r"(addr))

#define MMA_BF16(C, a, b0, b1) \
    asm volatile("mma.sync.aligned.m16n8k16.row.col.f32.bf16.bf16.f32 " \
        "{%0,%1,%2,%3}, {%4,%5,%6,%7}, {%8,%9}, {%0,%1,%2,%3};" \
        : "+f"((C)[0]), "+f"((C)[1]), "+f"((C)[2]), "+f"((C)[3]) \
        : "r"((a)[0]), "r"((a)[1]), "r"((a)[2]), "r"((a)[3]), "r"(b0), "r"(b1))

#define CP16(dst, src) \
    asm volatile("cp.async.cg.shared.global [%0], [%1], 16;" :: "r"(dst), "l"(src))
#define CP_COMMIT() asm volatile("cp.async.commit_group;" ::: "memory")
#define CP_WAIT0()  asm volatile("cp.async.wait_group 0;" ::: "memory")

// ---------------------------------------------------------------------------
// K1: h = x@W ; s1,s2 ; transposed bf16 hi/lo copies of h
// ---------------------------------------------------------------------------
__global__ void __launch_bounds__(1024) prep_kernel(
    const float* __restrict__ x, const float* __restrict__ W, const float* __restrict__ a)
{
    __shared__ float W_s[F_ * F_];
    __shared__ float x_s[16][F_];
    __shared__ float h_sh[16][F_ + 1];
    __shared__ float red[16][2][2];

    int t = threadIdx.x, tx = t & 63, ty = t >> 6;
    int row0 = blockIdx.x * 16;
    int row = row0 + ty;

    #pragma unroll
    for (int k = 0; k < 4; ++k) W_s[t + k * 1024] = W[t + k * 1024];
    x_s[ty][tx] = x[(size_t)row * F_ + tx];
    __syncthreads();

    float h = 0.f;
    #pragma unroll
    for (int k = 0; k < F_; ++k) h = fmaf(x_s[ty][k], W_s[k * F_ + tx], h);
    g_h[(size_t)row * F_ + tx] = h;
    h_sh[ty][tx] = h;

    float v1 = h * a[tx];
    float v2 = h * a[F_ + tx];
    #pragma unroll
    for (int off = 16; off; off >>= 1) {
        v1 += __shfl_xor_sync(0xffffffffu, v1, off);
        v2 += __shfl_xor_sync(0xffffffffu, v2, off);
    }
    if ((tx & 31) == 0) { red[ty][tx >> 5][0] = v1; red[ty][tx >> 5][1] = v2; }
    __syncthreads();
    if (tx == 0) {
        g_s1[row] = red[ty][0][0] + red[ty][1][0];
        g_s2[row] = red[ty][0][1] + red[ty][1][1];
    }

    int f = t >> 4, rr = t & 15;
    float v = h_sh[rr][f];
    __nv_bfloat16 hi = __float2bfloat16(v);
    float lov = v - __bfloat162float(hi);
    int b = row0 >> 11;
    size_t o = ((size_t)(b * F_ + f)) * N_ + (row0 & (N_ - 1)) + rr;
    g_hT_hi[o] = hi;
    g_hT_lo[o] = __float2bfloat16(lov);
}

// ---------------------------------------------------------------------------
// K2: per-batch c (max of warp maxes) / c2 (min of warp maxes) + factors
// ---------------------------------------------------------------------------
__global__ void __launch_bounds__(256) factors_kernel() {
    __shared__ float red[8];
    int b = blockIdx.x, t = threadIdx.x, w = t >> 5, lane = t & 31;

    float m = -3.4e38f;
    for (int i = t; i < N_; i += 256) m = fmaxf(m, g_s2[b * N_ + i]);
    #pragma unroll
    for (int off = 16; off; off >>= 1) m = fmaxf(m, __shfl_xor_sync(0xffffffffu, m, off));
    if (lane == 0) red[w] = m;
    __syncthreads();
    float c = -3.4e38f, c2 = 3.4e38f;
    #pragma unroll
    for (int q = 0; q < 8; ++q) { c = fmaxf(c, red[q]); c2 = fminf(c2, red[q]); }

    for (int i = t; i < N_; i += 256) {
        int gi = b * N_ + i;
        float s1 = g_s1[gi];
        float u  = s1 + c;
        float u2 = s1 + c2;
        float lr_u  = (u  > 0.f) ? u  : ALPHA_ * u;
        float lr_u2 = (u2 > 0.f) ? u2 : ALPHA_ * u2;
        float mm = fmaxf(lr_u2, lr_u - 60.f);
        g_A [gi] = expf(u - mm);
        g_Ap[gi] = expf(ALPHA_ * u - mm);
        float v = g_s2[gi] - c;
        g_B [gi] = expf(v);
        g_Bp[gi] = expf(ALPHA_ * v);
    }
}

// K2b: reset bad counter (also makes attn the 4th launch for ncu capture)
__global__ void reset_kernel() { if (threadIdx.x == 0) g_nbad = 0; }

// ---------------------------------------------------------------------------
// K3: attention partials via HMMA. 256 blocks = 128 tiles(128 rows) x 2 splits.
// 512 thr = 16 warps, 2 blocks/SM (32 warps resident).
// produce: warp w rows w*8..+7; thread = 2 rows x 8 j (direct __ldcs adj).
// MMA: warp w -> m 16 rows (w&7)*16, f-half (w>>3)*32. H via cp.async.
// ---------------------------------------------------------------------------
static constexpr uint32_t STG    = 49152;   // Phi 16K | Plo 16K | Hhi 8K | Hlo 8K
static constexpr uint32_t O_PHI  = 0;
static constexpr uint32_t O_PLO  = 16384;
static constexpr uint32_t O_HHI  = 32768;
static constexpr uint32_t O_HLO  = 40960;
static constexpr uint32_t OFF_B  = 98304;   // 4KB (JS floats)
static constexpr uint32_t OFF_BP = 102400;  // 4KB
static constexpr uint32_t OFF_A  = 106496;  // 512B
static constexpr uint32_t OFF_AP = 107008;  // 512B
static constexpr uint32_t DSMEM  = 107520;

__global__ void __launch_bounds__(512, 2) attn_kernel(const int* __restrict__ adj)
{
    extern __shared__ __align__(128) char sm[];
    uint32_t sb = smem_u32(sm);

    int t = threadIdx.x, w = t >> 5, lane = t & 31;
    int tile = blockIdx.x & 127;
    int s = blockIdx.x >> 7;
    int i0 = tile * TI;
    int b = i0 >> 11;
    int j0 = s * JS;

    float* sA  = (float*)(sm + OFF_A);
    float* sAp = (float*)(sm + OFF_AP);
    float* sB  = (float*)(sm + OFF_B);
    float* sBp = (float*)(sm + OFF_BP);
    if (t < 128) { sA[t] = g_A[i0 + t]; sAp[t] = g_Ap[i0 + t]; }
    #pragma unroll
    for (int k = 0; k < 2; ++k) {
        int u = t + k * 512;
        sB [u] = g_B [b * N_ + j0 + u];
        sBp[u] = g_Bp[b * N_ + j0 + u];
    }

    // produce-role indices: 2 rows x 8 j per thread
    int rg = lane >> 3;            // row pair 0..3
    int jg = lane & 7;             // j-group (8 j)
    int rbase = w * 8 + rg * 2;    // first of 2 rows

    float C[4][4];
    #pragma unroll
    for (int g = 0; g < 4; ++g)
        #pragma unroll
        for (int qq = 0; qq < 4; ++qq) C[g][qq] = 0.f;
    float lp[2] = {0.f, 0.f};

    // ---- prologue: H(0) via cp.async ----
    {
        int f = t >> 3, qq = t & 7;
        size_t src = ((size_t)(b * F_ + f)) * N_ + j0 + qq * 8;
        uint32_t sw = ((uint32_t)f * 128 + (uint32_t)qq * 16) ^ (((uint32_t)(f & 7)) << 4);
        CP16(sb + O_HHI + sw, g_hT_hi + src);
        CP16(sb + O_HLO + sw, g_hT_lo + src);
        CP_COMMIT();
    }
    __syncthreads();   // consts visible

    for (int ci = 0; ci < NCH; ++ci) {
        uint32_t stg = sb + (uint32_t)(ci & 1) * STG;
        char*   stgp = sm + (uint32_t)(ci & 1) * STG;
        int jc = j0 + ci * 64;

        // ---- produce P(ci): 2 rows x 8 j, adj direct __ldcs ----
        {
            float4 Bv0  = *(const float4*)(sB  + ci * 64 + jg * 8);
            float4 Bv1  = *(const float4*)(sB  + ci * 64 + jg * 8 + 4);
            float4 Bp0  = *(const float4*)(sBp + ci * 64 + jg * 8);
            float4 Bp1  = *(const float4*)(sBp + ci * 64 + jg * 8 + 4);
            #pragma unroll
            for (int rr = 0; rr < 2; ++rr) {
                int R = rbase + rr;
                const int4* ap = (const int4*)(adj + (size_t)(i0 + R) * N_ + jc + jg * 8);
                int4 a0 = __ldcs(ap);
                int4 a1 = __ldcs(ap + 1);
                float Ar = sA[R], Apr = sAp[R];
                float p0 = (a0.x > 0) ? fmaxf(Ar * Bv0.x, Apr * Bp0.x) : 0.f;
                float p1 = (a0.y > 0) ? fmaxf(Ar * Bv0.y, Apr * Bp0.y) : 0.f;
                float p2 = (a0.z > 0) ? fmaxf(Ar * Bv0.z, Apr * Bp0.z) : 0.f;
                float p3 = (a0.w > 0) ? fmaxf(Ar * Bv0.w, Apr * Bp0.w) : 0.f;
                float p4 = (a1.x > 0) ? fmaxf(Ar * Bv1.x, Apr * Bp1.x) : 0.f;
                float p5 = (a1.y > 0) ? fmaxf(Ar * Bv1.y, Apr * Bp1.y) : 0.f;
                float p6 = (a1.z > 0) ? fmaxf(Ar * Bv1.z, Apr * Bp1.z) : 0.f;
                float p7 = (a1.w > 0) ? fmaxf(Ar * Bv1.w, Apr * Bp1.w) : 0.f;
                lp[rr] += ((p0 + p1) + (p2 + p3)) + ((p4 + p5) + (p6 + p7));

                __nv_bfloat162 h01 = __float22bfloat162_rn(make_float2(p0, p1));
                __nv_bfloat162 h23 = __float22bfloat162_rn(make_float2(p2, p3));
                __nv_bfloat162 h45 = __float22bfloat162_rn(make_float2(p4, p5));
                __nv_bfloat162 h67 = __float22bfloat162_rn(make_float2(p6, p7));
                __nv_bfloat162 l01 = __float22bfloat162_rn(make_float2(
                    p0 - __bfloat162float(__low2bfloat16(h01)), p1 - __bfloat162float(__high2bfloat16(h01))));
                __nv_bfloat162 l23 = __float22bfloat162_rn(make_float2(
                    p2 - __bfloat162float(__low2bfloat16(h23)), p3 - __bfloat162float(__high2bfloat16(h23))));
                __nv_bfloat162 l45 = __float22bfloat162_rn(make_float2(
                    p4 - __bfloat162float(__low2bfloat16(h45)), p5 - __bfloat162float(__high2bfloat16(h45))));
                __nv_bfloat162 l67 = __float22bfloat162_rn(make_float2(
                    p6 - __bfloat162float(__low2bfloat16(h67)), p7 - __bfloat162float(__high2bfloat16(h67))));

                uint32_t boff = (uint32_t)R * 128 + (uint32_t)jg * 16;
                uint32_t sw = boff ^ (((uint32_t)(R & 7)) << 4);
                *(uint4*)(stgp + O_PHI + sw) =
                    make_uint4(*(uint32_t*)&h01, *(uint32_t*)&h23, *(uint32_t*)&h45, *(uint32_t*)&h67);
                *(uint4*)(stgp + O_PLO + sw) =
                    make_uint4(*(uint32_t*)&l01, *(uint32_t*)&l23, *(uint32_t*)&l45, *(uint32_t*)&l67);
            }
        }

        CP_WAIT0();        // H(ci) landed (this thread's copies)
        __syncthreads();   // all P(ci)+H(ci) visible; prev MMA done with old stage

        // ---- issue H(ci+1) cp.async (overlaps MMA) ----
        if (ci + 1 < NCH) {
            uint32_t nstg = sb + (uint32_t)((ci + 1) & 1) * STG;
            int jn = jc + 64;
            int f = t >> 3, qq = t & 7;
            size_t src = ((size_t)(b * F_ + f)) * N_ + jn + qq * 8;
            uint32_t sw = ((uint32_t)f * 128 + (uint32_t)qq * 16) ^ (((uint32_t)(f & 7)) << 4);
            CP16(nstg + O_HHI + sw, g_hT_hi + src);
            CP16(nstg + O_HLO + sw, g_hT_lo + src);
            CP_COMMIT();
        }

        // ---- MMA(ci): m0=(w&7)*16, f0=(w>>3)*32 ----
        {
            int m0 = (w & 7) * 16;
            int f0 = (w >> 3) * 32;
            #pragma unroll
            for (int ks = 0; ks < 4; ++ks) {
                uint32_t ahi[4], alo[4];
                int arow = m0 + (lane & 15);
                uint32_t aoff = (uint32_t)arow * 128 + (uint32_t)ks * 32 + ((uint32_t)(lane >> 4)) * 16;
                uint32_t asw = aoff ^ (((uint32_t)(arow & 7)) << 4);
                LDSM4(ahi, stg + O_PHI + asw);
                LDSM4(alo, stg + O_PLO + asw);
                #pragma unroll
                for (int nb = 0; nb < 2; ++nb) {
                    uint32_t bhi[4], blo[4];
                    int nrow = f0 + nb * 16 + (lane & 15);
                    uint32_t boff = (uint32_t)nrow * 128 + (uint32_t)ks * 32 + ((uint32_t)(lane >> 4)) * 16;
                    uint32_t bsw = boff ^ (((uint32_t)(nrow & 7)) << 4);
                    LDSM4(bhi, stg + O_HHI + bsw);
                    LDSM4(blo, stg + O_HLO + bsw);
                    MMA_BF16(C[nb * 2],     ahi, bhi[0], bhi[2]);
                    MMA_BF16(C[nb * 2 + 1], ahi, bhi[1], bhi[3]);
                    MMA_BF16(C[nb * 2],     ahi, blo[0], blo[2]);
                    MMA_BF16(C[nb * 2 + 1], ahi, blo[1], blo[3]);
                    MMA_BF16(C[nb * 2],     alo, bhi[0], bhi[2]);
                    MMA_BF16(C[nb * 2 + 1], alo, bhi[1], bhi[3]);
                }
            }
        }
    }

    // ---- denominators: sum over 8 j-lanes ----
    #pragma unroll
    for (int rr = 0; rr < 2; ++rr) {
        float v = lp[rr];
        v += __shfl_xor_sync(0xffffffffu, v, 1);
        v += __shfl_xor_sync(0xffffffffu, v, 2);
        v += __shfl_xor_sync(0xffffffffu, v, 4);
        if (jg == 0) g_l[s][i0 + rbase + rr] = v;
    }

    // ---- C frags -> g_acc ----
    {
        int r0 = i0 + (w & 7) * 16 + (lane >> 2);
        int f0 = (w >> 3) * 32 + (lane & 3) * 2;
        #pragma unroll
        for (int g = 0; g < 4; ++g) {
            float* o = g_acc[s] + (size_t)r0 * F_ + f0 + g * 8;
            *(float2*)o = make_float2(C[g][0], C[g][1]);
            *(float2*)(o + 8 * F_) = make_float2(C[g][2], C[g][3]);
        }
    }
}

// ---------------------------------------------------------------------------
// K4: combine splits, normalize, ELU, flag bad rows
// ---------------------------------------------------------------------------
__global__ void combine_kernel(float* __restrict__ out) {
    int idx = blockIdx.x * 256 + threadIdx.x;
    int row = idx >> 5;
    int fo = (idx & 31) * 2;
    float l = g_l[0][row] + g_l[1][row];
    if ((idx & 31) == 0 && !(l >= 1e-20f)) {
        int si = atomicAdd(&g_nbad, 1);
        g_bad[si] = row;
    }
    float inv = 1.f / l;
    size_t o = (size_t)row * F_ + fo;
    float2 u = *(const float2*)(g_acc[0] + o);
    float2 v = *(const float2*)(g_acc[1] + o);
    float o0 = (u.x + v.x) * inv;
    float o1 = (u.y + v.y) * inv;
    o0 = (o0 > 0.f) ? o0 : (__expf(o0) - 1.f);
    o1 = (o1 > 0.f) ? o1 : (__expf(o1) - 1.f);
    *(float2*)(out + o) = make_float2(o0, o1);
}

// ---------------------------------------------------------------------------
// K5: exact fp32 recompute of flagged rows
// ---------------------------------------------------------------------------
__global__ void __launch_bounds__(256) fallback_kernel(
    const int* __restrict__ adj, float* __restrict__ out)
{
    __shared__ float p_s[N_];
    __shared__ float red[4][64];
    __shared__ float lred[8];
    int t = threadIdx.x, w = t >> 5, lane = t & 31;
    int nb = g_nbad;
    for (int k = blockIdx.x; k < nb; k += gridDim.x) {
        int row = g_bad[k];
        int b = row >> 11;
        float A = g_A[row], Ap = g_Ap[row];
        float lpv = 0.f;
        for (int j = t; j < N_; j += 256) {
            int av = adj[(size_t)row * N_ + j];
            float p = (av > 0) ? fmaxf(A * g_B[b * N_ + j], Ap * g_Bp[b * N_ + j]) : 0.f;
            p_s[j] = p;
            lpv += p;
        }
        #pragma unroll
        for (int off = 16; off; off >>= 1) lpv += __shfl_xor_sync(0xffffffffu, lpv, off);
        if (lane == 0) lred[w] = lpv;
        __syncthreads();
        float l = 0.f;
        #pragma unroll
        for (int q = 0; q < 8; ++q) l += lred[q];
        int f = t & 63, seg = t >> 6;
        float acc = 0.f;
        const float* hb = g_h + ((size_t)b * N_ + seg * 512) * F_ + f;
        for (int j = 0; j < 512; ++j) acc = fmaf(p_s[seg * 512 + j], hb[(size_t)j * F_], acc);
        red[seg][f] = acc;
        __syncthreads();
        if (t < 64) {
            float v = (red[0][t] + red[1][t] + red[2][t] + red[3][t]) / l;
            out[(size_t)row * F_ + t] = (v > 0.f) ? v : (__expf(v) - 1.f);
        }
        __syncthreads();
    }
}

extern "C" void kernel_launch(void* const* d_in, const int* in_sizes, int n_in,
                              void* d_out, int out_size)
{
    const float* x   = (const float*)d_in[0];
    const int*   adj = (const int*)  d_in[1];
    const float* W   = (const float*)d_in[2];
    const float* a   = (const float*)d_in[3];
    float* out = (float*)d_out;

    cudaFuncSetAttribute(attn_kernel, cudaFuncAttributeMaxDynamicSharedMemorySize, DSMEM);

    prep_kernel<<<(B_ * N_) / 16, 1024>>>(x, W, a);
    factors_kernel<<<B_, 256>>>();
    reset_kernel<<<1, 32>>>();
    attn_kernel<<<(B_ * N_ / TI) * SPLITS, 512, DSMEM>>>(adj);
    combine_kernel<<<(B_ * N_ * 32) / 256, 256>>>(out);
    fallback_kernel<<<64, 256>>>(adj, out);
}

// round 10
// speedup vs baseline: 3.0098x; 1.0380x over previous
#include <cuda_runtime.h>
#include <cuda_bf16.h>
#include <cstdint>

static constexpr int B_ = 8;
static constexpr int N_ = 2048;
static constexpr int F_ = 64;
static constexpr float ALPHA_ = 0.2f;
static constexpr int SPLITS = 2;
static constexpr int JS = N_ / SPLITS;   // 1024
static constexpr int NCH = JS / 64;      // 16
static constexpr int TI = 128;           // rows per block

// -------- scratch (no cudaMalloc allowed) --------
__device__ float g_h[B_ * N_ * F_];
__device__ float g_s1[B_ * N_];
__device__ float g_s2[B_ * N_];
__device__ float g_A [B_ * N_];
__device__ float g_Ap[B_ * N_];
__device__ float g_B [B_ * N_];
__device__ float g_Bp[B_ * N_];
__device__ __nv_bfloat16 g_hT_hi[B_ * F_ * N_];   // [b][f][n]
__device__ __nv_bfloat16 g_hT_lo[B_ * F_ * N_];
__device__ float g_acc[SPLITS][B_ * N_ * F_];
__device__ float g_l  [SPLITS][B_ * N_];
__device__ int g_nbad;
__device__ int g_bad[B_ * N_];

__device__ __forceinline__ uint32_t smem_u32(const void* p) {
    uint32_t a;
    asm("{ .reg .u64 t; cvta.to.shared.u64 t, %1; cvt.u32.u64 %0, t; }" : "=r"(a) : "l"(p));
    return a;
}

#define LDSM4(r, addr) \
    asm volatile("ldmatrix.sync.aligned.m8n8.x4.shared.b16 {%0,%1,%2,%3}, [%4];" \
        : "=r"((r)[0]), "=r"((r)[1]), "=r"((r)[2]), "=r"((r)[3]) : "r"(addr))

#define MMA_BF16(C, a, b0, b1) \
    asm volatile("mma.sync.aligned.m16n8k16.row.col.f32.bf16.bf16.f32 " \
        "{%0,%1,%2,%3}, {%4,%5,%6,%7}, {%8,%9}, {%0,%1,%2,%3};" \
        : "+f"((C)[0]), "+f"((C)[1]), "+f"((C)[2]), "+f"((C)[3]) \
        : "r"((a)[0]), "r"((a)[1]), "r"((a)[2]), "r"((a)[3]), "r"(b0), "r"(b1))

#define CP16(dst, src) \
    asm volatile("cp.async.cg.shared.global [%0], [%1], 16;" :: "r"(dst), "l"(src))
#define CP_COMMIT() asm volatile("cp.async.commit_group;" ::: "memory")
#define CP_WAIT0()  asm volatile("cp.async.wait_group 0;" ::: "memory")

// ---------------------------------------------------------------------------
// K1: h = x@W ; s1,s2 ; transposed bf16 hi/lo copies of h
// ---------------------------------------------------------------------------
__global__ void __launch_bounds__(1024) prep_kernel(
    const float* __restrict__ x, const float* __restrict__ W, const float* __restrict__ a)
{
    __shared__ float W_s[F_ * F_];
    __shared__ float x_s[16][F_];
    __shared__ float h_sh[16][F_ + 1];
    __shared__ float red[16][2][2];

    int t = threadIdx.x, tx = t & 63, ty = t >> 6;
    int row0 = blockIdx.x * 16;
    int row = row0 + ty;

    #pragma unroll
    for (int k = 0; k < 4; ++k) W_s[t + k * 1024] = W[t + k * 1024];
    x_s[ty][tx] = x[(size_t)row * F_ + tx];
    __syncthreads();

    float h = 0.f;
    #pragma unroll
    for (int k = 0; k < F_; ++k) h = fmaf(x_s[ty][k], W_s[k * F_ + tx], h);
    g_h[(size_t)row * F_ + tx] = h;
    h_sh[ty][tx] = h;

    float v1 = h * a[tx];
    float v2 = h * a[F_ + tx];
    #pragma unroll
    for (int off = 16; off; off >>= 1) {
        v1 += __shfl_xor_sync(0xffffffffu, v1, off);
        v2 += __shfl_xor_sync(0xffffffffu, v2, off);
    }
    if ((tx & 31) == 0) { red[ty][tx >> 5][0] = v1; red[ty][tx >> 5][1] = v2; }
    __syncthreads();
    if (tx == 0) {
        g_s1[row] = red[ty][0][0] + red[ty][1][0];
        g_s2[row] = red[ty][0][1] + red[ty][1][1];
    }

    int f = t >> 4, rr = t & 15;
    float v = h_sh[rr][f];
    __nv_bfloat16 hi = __float2bfloat16(v);
    float lov = v - __bfloat162float(hi);
    int b = row0 >> 11;
    size_t o = ((size_t)(b * F_ + f)) * N_ + (row0 & (N_ - 1)) + rr;
    g_hT_hi[o] = hi;
    g_hT_lo[o] = __float2bfloat16(lov);
}

// ---------------------------------------------------------------------------
// K2: per-batch c (max of warp maxes) / c2 (min of warp maxes) + factors
// ---------------------------------------------------------------------------
__global__ void __launch_bounds__(256) factors_kernel() {
    __shared__ float red[8];
    int b = blockIdx.x, t = threadIdx.x, w = t >> 5, lane = t & 31;

    float m = -3.4e38f;
    for (int i = t; i < N_; i += 256) m = fmaxf(m, g_s2[b * N_ + i]);
    #pragma unroll
    for (int off = 16; off; off >>= 1) m = fmaxf(m, __shfl_xor_sync(0xffffffffu, m, off));
    if (lane == 0) red[w] = m;
    __syncthreads();
    float c = -3.4e38f, c2 = 3.4e38f;
    #pragma unroll
    for (int q = 0; q < 8; ++q) { c = fmaxf(c, red[q]); c2 = fminf(c2, red[q]); }

    for (int i = t; i < N_; i += 256) {
        int gi = b * N_ + i;
        float s1 = g_s1[gi];
        float u  = s1 + c;
        float u2 = s1 + c2;
        float lr_u  = (u  > 0.f) ? u  : ALPHA_ * u;
        float lr_u2 = (u2 > 0.f) ? u2 : ALPHA_ * u2;
        float mm = fmaxf(lr_u2, lr_u - 60.f);
        g_A [gi] = expf(u - mm);
        g_Ap[gi] = expf(ALPHA_ * u - mm);
        float v = g_s2[gi] - c;
        g_B [gi] = expf(v);
        g_Bp[gi] = expf(ALPHA_ * v);
    }
}

// K2b: reset bad counter (keeps attn as the 4th launch for ncu capture)
__global__ void reset_kernel() { if (threadIdx.x == 0) g_nbad = 0; }

// ---------------------------------------------------------------------------
// K3: attention partials via HMMA, warp-specialized.
// 256 blocks = 128 tiles(128 rows) x 2 splits; 512 thr = 16 warps.
// warps 0-7: producers (P bf16 hi/lo -> smem, H cp.async, denominators).
// warps 8-15: consumers (LDSM + MMA, each m32 x f32, C[2][4][4]).
// Producer chunk ci+1 overlaps consumer chunk ci between barriers.
// ---------------------------------------------------------------------------
static constexpr uint32_t STG    = 49152;   // Phi 16K | Plo 16K | Hhi 8K | Hlo 8K
static constexpr uint32_t O_PHI  = 0;
static constexpr uint32_t O_PLO  = 16384;
static constexpr uint32_t O_HHI  = 32768;
static constexpr uint32_t O_HLO  = 40960;
static constexpr uint32_t OFF_B  = 98304;   // 4KB (JS floats)
static constexpr uint32_t OFF_BP = 102400;  // 4KB
static constexpr uint32_t OFF_A  = 106496;  // 512B
static constexpr uint32_t OFF_AP = 107008;  // 512B
static constexpr uint32_t DSMEM  = 107520;

// Producer: stage H(cidx) via cp.async + produce P(cidx) into stage[cidx&1].
// Called only by threads t < 256.
__device__ __forceinline__ void produce_chunk(
    char* sm, uint32_t sb, const int* __restrict__ adj,
    int i0, int b, int j0, int cidx, int t, int w, int lane,
    const float* sA, const float* sAp, const float* sB, const float* sBp,
    float* lp)
{
    uint32_t stg = sb + (uint32_t)(cidx & 1) * STG;
    char*   stgp = sm + (uint32_t)(cidx & 1) * STG;
    int jc = j0 + cidx * 64;

    // H tiles: 64 f-rows x 64 j bf16 hi/lo, swizzled, via cp.async
    {
        int f = t >> 2, qq = t & 3;
        #pragma unroll
        for (int hp = 0; hp < 2; ++hp) {
            int q2 = qq + hp * 4;
            size_t src = ((size_t)(b * F_ + f)) * N_ + jc + q2 * 8;
            uint32_t sw = ((uint32_t)f * 128 + (uint32_t)q2 * 16) ^ (((uint32_t)(f & 7)) << 4);
            CP16(stg + O_HHI + sw, g_hT_hi + src);
            CP16(stg + O_HLO + sw, g_hT_lo + src);
        }
        CP_COMMIT();
    }

    // P tiles: warp w rows w*16..+15; thread: 4 rows x 8 j
    int rbase = w * 16 + (lane >> 3) * 4;
    int jg = lane & 7;
    float4 Bv0 = *(const float4*)(sB  + cidx * 64 + jg * 8);
    float4 Bv1 = *(const float4*)(sB  + cidx * 64 + jg * 8 + 4);
    float4 Bp0 = *(const float4*)(sBp + cidx * 64 + jg * 8);
    float4 Bp1 = *(const float4*)(sBp + cidx * 64 + jg * 8 + 4);
    #pragma unroll
    for (int rr = 0; rr < 4; ++rr) {
        int R = rbase + rr;
        const int4* ap = (const int4*)(adj + (size_t)(i0 + R) * N_ + jc + jg * 8);
        int4 a0 = __ldcs(ap);
        int4 a1 = __ldcs(ap + 1);
        float Ar = sA[R], Apr = sAp[R];
        float p0 = (a0.x > 0) ? fmaxf(Ar * Bv0.x, Apr * Bp0.x) : 0.f;
        float p1 = (a0.y > 0) ? fmaxf(Ar * Bv0.y, Apr * Bp0.y) : 0.f;
        float p2 = (a0.z > 0) ? fmaxf(Ar * Bv0.z, Apr * Bp0.z) : 0.f;
        float p3 = (a0.w > 0) ? fmaxf(Ar * Bv0.w, Apr * Bp0.w) : 0.f;
        float p4 = (a1.x > 0) ? fmaxf(Ar * Bv1.x, Apr * Bp1.x) : 0.f;
        float p5 = (a1.y > 0) ? fmaxf(Ar * Bv1.y, Apr * Bp1.y) : 0.f;
        float p6 = (a1.z > 0) ? fmaxf(Ar * Bv1.z, Apr * Bp1.z) : 0.f;
        float p7 = (a1.w > 0) ? fmaxf(Ar * Bv1.w, Apr * Bp1.w) : 0.f;
        lp[rr] += ((p0 + p1) + (p2 + p3)) + ((p4 + p5) + (p6 + p7));

        __nv_bfloat162 h01 = __float22bfloat162_rn(make_float2(p0, p1));
        __nv_bfloat162 h23 = __float22bfloat162_rn(make_float2(p2, p3));
        __nv_bfloat162 h45 = __float22bfloat162_rn(make_float2(p4, p5));
        __nv_bfloat162 h67 = __float22bfloat162_rn(make_float2(p6, p7));
        __nv_bfloat162 l01 = __float22bfloat162_rn(make_float2(
            p0 - __bfloat162float(__low2bfloat16(h01)), p1 - __bfloat162float(__high2bfloat16(h01))));
        __nv_bfloat162 l23 = __float22bfloat162_rn(make_float2(
            p2 - __bfloat162float(__low2bfloat16(h23)), p3 - __bfloat162float(__high2bfloat16(h23))));
        __nv_bfloat162 l45 = __float22bfloat162_rn(make_float2(
            p4 - __bfloat162float(__low2bfloat16(h45)), p5 - __bfloat162float(__high2bfloat16(h45))));
        __nv_bfloat162 l67 = __float22bfloat162_rn(make_float2(
            p6 - __bfloat162float(__low2bfloat16(h67)), p7 - __bfloat162float(__high2bfloat16(h67))));

        uint32_t boff = (uint32_t)R * 128 + (uint32_t)jg * 16;
        uint32_t sw = boff ^ (((uint32_t)(R & 7)) << 4);
        *(uint4*)(stgp + O_PHI + sw) =
            make_uint4(*(uint32_t*)&h01, *(uint32_t*)&h23, *(uint32_t*)&h45, *(uint32_t*)&h67);
        *(uint4*)(stgp + O_PLO + sw) =
            make_uint4(*(uint32_t*)&l01, *(uint32_t*)&l23, *(uint32_t*)&l45, *(uint32_t*)&l67);
    }
    CP_WAIT0();   // my H copies landed before I hit the barrier
}

__global__ void __launch_bounds__(512, 2) attn_kernel(const int* __restrict__ adj)
{
    extern __shared__ __align__(128) char sm[];
    uint32_t sb = smem_u32(sm);

    int t = threadIdx.x, w = t >> 5, lane = t & 31;
    int tile = blockIdx.x & 127;
    int s = blockIdx.x >> 7;
    int i0 = tile * TI;
    int b = i0 >> 11;
    int j0 = s * JS;

    float* sA  = (float*)(sm + OFF_A);
    float* sAp = (float*)(sm + OFF_AP);
    float* sB  = (float*)(sm + OFF_B);
    float* sBp = (float*)(sm + OFF_BP);
    if (t < 128) { sA[t] = g_A[i0 + t]; sAp[t] = g_Ap[i0 + t]; }
    #pragma unroll
    for (int k = 0; k < 2; ++k) {
        int u = t + k * 512;
        sB [u] = g_B [b * N_ + j0 + u];
        sBp[u] = g_Bp[b * N_ + j0 + u];
    }
    __syncthreads();

    float C[2][4][4];
    #pragma unroll
    for (int mt = 0; mt < 2; ++mt)
        #pragma unroll
        for (int g = 0; g < 4; ++g)
            #pragma unroll
            for (int qq = 0; qq < 4; ++qq) C[mt][g][qq] = 0.f;
    float lp[4] = {0.f, 0.f, 0.f, 0.f};

    // prologue: producers build chunk 0
    if (w < 8)
        produce_chunk(sm, sb, adj, i0, b, j0, 0, t, w, lane, sA, sAp, sB, sBp, lp);
    __syncthreads();

    for (int ci = 0; ci < NCH; ++ci) {
        if (w < 8) {
            if (ci + 1 < NCH)
                produce_chunk(sm, sb, adj, i0, b, j0, ci + 1, t, w, lane, sA, sAp, sB, sBp, lp);
        } else {
            // consumer: MMA(ci); cw = w-8: m0=(cw&3)*32, f0=(cw>>2)*32
            uint32_t stg = sb + (uint32_t)(ci & 1) * STG;
            int cw = w - 8;
            int m0 = (cw & 3) * 32;
            int f0 = (cw >> 2) * 32;
            #pragma unroll
            for (int ks = 0; ks < 4; ++ks) {
                uint32_t ahi[2][4], alo[2][4];
                #pragma unroll
                for (int mt = 0; mt < 2; ++mt) {
                    int arow = m0 + mt * 16 + (lane & 15);
                    uint32_t aoff = (uint32_t)arow * 128 + (uint32_t)ks * 32 + ((uint32_t)(lane >> 4)) * 16;
                    uint32_t asw = aoff ^ (((uint32_t)(arow & 7)) << 4);
                    LDSM4(ahi[mt], stg + O_PHI + asw);
                    LDSM4(alo[mt], stg + O_PLO + asw);
                }
                #pragma unroll
                for (int nb = 0; nb < 2; ++nb) {
                    uint32_t bhi[4], blo[4];
                    int nrow = f0 + nb * 16 + (lane & 15);
                    uint32_t boff = (uint32_t)nrow * 128 + (uint32_t)ks * 32 + ((uint32_t)(lane >> 4)) * 16;
                    uint32_t bsw = boff ^ (((uint32_t)(nrow & 7)) << 4);
                    LDSM4(bhi, stg + O_HHI + bsw);
                    LDSM4(blo, stg + O_HLO + bsw);
                    #pragma unroll
                    for (int mt = 0; mt < 2; ++mt) {
                        MMA_BF16(C[mt][nb * 2],     ahi[mt], bhi[0], bhi[2]);
                        MMA_BF16(C[mt][nb * 2 + 1], ahi[mt], bhi[1], bhi[3]);
                        MMA_BF16(C[mt][nb * 2],     ahi[mt], blo[0], blo[2]);
                        MMA_BF16(C[mt][nb * 2 + 1], ahi[mt], blo[1], blo[3]);
                        MMA_BF16(C[mt][nb * 2],     alo[mt], bhi[0], bhi[2]);
                        MMA_BF16(C[mt][nb * 2 + 1], alo[mt], bhi[1], bhi[3]);
                    }
                }
            }
        }
        __syncthreads();
    }

    if (w < 8) {
        // denominators: reduce over 8 j-lanes (jg = lane&7)
        int rbase = w * 16 + (lane >> 3) * 4;
        #pragma unroll
        for (int rr = 0; rr < 4; ++rr) {
            float v = lp[rr];
            v += __shfl_xor_sync(0xffffffffu, v, 1);
            v += __shfl_xor_sync(0xffffffffu, v, 2);
            v += __shfl_xor_sync(0xffffffffu, v, 4);
            if ((lane & 7) == 0) g_l[s][i0 + rbase + rr] = v;
        }
    } else {
        // C frags -> g_acc
        int cw = w - 8;
        int f0 = (cw >> 2) * 32 + (lane & 3) * 2;
        #pragma unroll
        for (int mt = 0; mt < 2; ++mt) {
            int r0 = i0 + (cw & 3) * 32 + mt * 16 + (lane >> 2);
            #pragma unroll
            for (int g = 0; g < 4; ++g) {
                float* o = g_acc[s] + (size_t)r0 * F_ + f0 + g * 8;
                *(float2*)o = make_float2(C[mt][g][0], C[mt][g][1]);
                *(float2*)(o + 8 * F_) = make_float2(C[mt][g][2], C[mt][g][3]);
            }
        }
    }
}

// ---------------------------------------------------------------------------
// K4: combine splits, normalize, ELU, flag bad rows (float4 per thread)
// ---------------------------------------------------------------------------
__global__ void combine_kernel(float* __restrict__ out) {
    int idx = blockIdx.x * 256 + threadIdx.x;   // B*N*16 threads
    int row = idx >> 4;
    int fo = (idx & 15) * 4;
    float l = g_l[0][row] + g_l[1][row];
    if ((idx & 15) == 0 && !(l >= 1e-20f)) {
        int si = atomicAdd(&g_nbad, 1);
        g_bad[si] = row;
    }
    float inv = 1.f / l;
    size_t o = (size_t)row * F_ + fo;
    float4 u = *(const float4*)(g_acc[0] + o);
    float4 v = *(const float4*)(g_acc[1] + o);
    float4 r;
    r.x = (u.x + v.x) * inv;
    r.y = (u.y + v.y) * inv;
    r.z = (u.z + v.z) * inv;
    r.w = (u.w + v.w) * inv;
    r.x = (r.x > 0.f) ? r.x : (__expf(r.x) - 1.f);
    r.y = (r.y > 0.f) ? r.y : (__expf(r.y) - 1.f);
    r.z = (r.z > 0.f) ? r.z : (__expf(r.z) - 1.f);
    r.w = (r.w > 0.f) ? r.w : (__expf(r.w) - 1.f);
    *(float4*)(out + o) = r;
}

// ---------------------------------------------------------------------------
// K5: exact fp32 recompute of flagged rows
// ---------------------------------------------------------------------------
__global__ void __launch_bounds__(256) fallback_kernel(
    const int* __restrict__ adj, float* __restrict__ out)
{
    __shared__ float p_s[N_];
    __shared__ float red[4][64];
    __shared__ float lred[8];
    int t = threadIdx.x, w = t >> 5, lane = t & 31;
    int nb = g_nbad;
    for (int k = blockIdx.x; k < nb; k += gridDim.x) {
        int row = g_bad[k];
        int b = row >> 11;
        float A = g_A[row], Ap = g_Ap[row];
        float lpv = 0.f;
        for (int j = t; j < N_; j += 256) {
            int av = adj[(size_t)row * N_ + j];
            float p = (av > 0) ? fmaxf(A * g_B[b * N_ + j], Ap * g_Bp[b * N_ + j]) : 0.f;
            p_s[j] = p;
            lpv += p;
        }
        #pragma unroll
        for (int off = 16; off; off >>= 1) lpv += __shfl_xor_sync(0xffffffffu, lpv, off);
        if (lane == 0) lred[w] = lpv;
        __syncthreads();
        float l = 0.f;
        #pragma unroll
        for (int q = 0; q < 8; ++q) l += lred[q];
        int f = t & 63, seg = t >> 6;
        float acc = 0.f;
        const float* hb = g_h + ((size_t)b * N_ + seg * 512) * F_ + f;
        for (int j = 0; j < 512; ++j) acc = fmaf(p_s[seg * 512 + j], hb[(size_t)j * F_], acc);
        red[seg][f] = acc;
        __syncthreads();
        if (t < 64) {
            float v = (red[0][t] + red[1][t] + red[2][t] + red[3][t]) / l;
            out[(size_t)row * F_ + t] = (v > 0.f) ? v : (__expf(v) - 1.f);
        }
        __syncthreads();
    }
}

extern "C" void kernel_launch(void* const* d_in, const int* in_sizes, int n_in,
                              void* d_out, int out_size)
{
    const float* x   = (const float*)d_in[0];
    const int*   adj = (const int*)  d_in[1];
    const float* W   = (const float*)d_in[2];
    const float* a   = (const float*)d_in[3];
    float* out = (float*)d_out;

    cudaFuncSetAttribute(attn_kernel, cudaFuncAttributeMaxDynamicSharedMemorySize, DSMEM);

    prep_kernel<<<(B_ * N_) / 16, 1024>>>(x, W, a);
    factors_kernel<<<B_, 256>>>();
    reset_kernel<<<1, 32>>>();
    attn_kernel<<<(B_ * N_ / TI) * SPLITS, 512, DSMEM>>>(adj);
    combine_kernel<<<(B_ * N_ * 16) / 256, 256>>>(out);
    fallback_kernel<<<64, 256>>>(adj, out);
}

// round 11
// speedup vs baseline: 3.2165x; 1.0687x over previous
#include <cuda_runtime.h>
#include <cuda_bf16.h>
#include <cstdint>

static constexpr int B_ = 8;
static constexpr int N_ = 2048;
static constexpr int F_ = 64;
static constexpr float ALPHA_ = 0.2f;
static constexpr int SPLITS = 2;
static constexpr int JS = N_ / SPLITS;   // 1024
static constexpr int NCH = JS / 64;      // 16
static constexpr int TI = 128;           // rows per block

// -------- scratch (no cudaMalloc allowed) --------
__device__ float g_h[B_ * N_ * F_];
__device__ float g_s1[B_ * N_];
__device__ float g_s2[B_ * N_];
__device__ float g_A [B_ * N_];
__device__ float g_Ap[B_ * N_];
__device__ float g_B [B_ * N_];
__device__ float g_Bp[B_ * N_];
__device__ __nv_bfloat16 g_hT_hi[B_ * F_ * N_];   // [b][f][n]
__device__ __nv_bfloat16 g_hT_lo[B_ * F_ * N_];
__device__ float g_acc[SPLITS][B_ * N_ * F_];
__device__ float g_l  [SPLITS][B_ * N_];
__device__ int g_nbad;
__device__ int g_bad[B_ * N_];

__device__ __forceinline__ uint32_t smem_u32(const void* p) {
    uint32_t a;
    asm("{ .reg .u64 t; cvta.to.shared.u64 t, %1; cvt.u32.u64 %0, t; }" : "=r"(a) : "l"(p));
    return a;
}

#define LDSM4(r, addr) \
    asm volatile("ldmatrix.sync.aligned.m8n8.x4.shared.b16 {%0,%1,%2,%3}, [%4];" \
        : "=r"((r)[0]), "=r"((r)[1]), "=r"((r)[2]), "=r"((r)[3]) : "r"(addr))

#define MMA_BF16(C, a, b0, b1) \
    asm volatile("mma.sync.aligned.m16n8k16.row.col.f32.bf16.bf16.f32 " \
        "{%0,%1,%2,%3}, {%4,%5,%6,%7}, {%8,%9}, {%0,%1,%2,%3};" \
        : "+f"((C)[0]), "+f"((C)[1]), "+f"((C)[2]), "+f"((C)[3]) \
        : "r"((a)[0]), "r"((a)[1]), "r"((a)[2]), "r"((a)[3]), "r"(b0), "r"(b1))

#define CP16(dst, src) \
    asm volatile("cp.async.cg.shared.global [%0], [%1], 16;" :: "r"(dst), "l"(src))
#define CP_COMMIT() asm volatile("cp.async.commit_group;" ::: "memory")
#define CP_WAIT0()  asm volatile("cp.async.wait_group 0;" ::: "memory")

// named block barriers (512 participants)
#define BAR_SYNC(id)   asm volatile("bar.sync %0, 512;"   :: "r"(id) : "memory")
#define BAR_ARRIVE(id) asm volatile("bar.arrive %0, 512;" :: "r"(id) : "memory")

// ---------------------------------------------------------------------------
// K1: h = x@W ; s1,s2 ; transposed bf16 hi/lo copies of h
// ---------------------------------------------------------------------------
__global__ void __launch_bounds__(1024) prep_kernel(
    const float* __restrict__ x, const float* __restrict__ W, const float* __restrict__ a)
{
    __shared__ float W_s[F_ * F_];
    __shared__ float x_s[16][F_];
    __shared__ float h_sh[16][F_ + 1];
    __shared__ float red[16][2][2];

    int t = threadIdx.x, tx = t & 63, ty = t >> 6;
    int row0 = blockIdx.x * 16;
    int row = row0 + ty;

    #pragma unroll
    for (int k = 0; k < 4; ++k) W_s[t + k * 1024] = W[t + k * 1024];
    x_s[ty][tx] = x[(size_t)row * F_ + tx];
    __syncthreads();

    float h = 0.f;
    #pragma unroll
    for (int k = 0; k < F_; ++k) h = fmaf(x_s[ty][k], W_s[k * F_ + tx], h);
    g_h[(size_t)row * F_ + tx] = h;
    h_sh[ty][tx] = h;

    float v1 = h * a[tx];
    float v2 = h * a[F_ + tx];
    #pragma unroll
    for (int off = 16; off; off >>= 1) {
        v1 += __shfl_xor_sync(0xffffffffu, v1, off);
        v2 += __shfl_xor_sync(0xffffffffu, v2, off);
    }
    if ((tx & 31) == 0) { red[ty][tx >> 5][0] = v1; red[ty][tx >> 5][1] = v2; }
    __syncthreads();
    if (tx == 0) {
        g_s1[row] = red[ty][0][0] + red[ty][1][0];
        g_s2[row] = red[ty][0][1] + red[ty][1][1];
    }

    int f = t >> 4, rr = t & 15;
    float v = h_sh[rr][f];
    __nv_bfloat16 hi = __float2bfloat16(v);
    float lov = v - __bfloat162float(hi);
    int b = row0 >> 11;
    size_t o = ((size_t)(b * F_ + f)) * N_ + (row0 & (N_ - 1)) + rr;
    g_hT_hi[o] = hi;
    g_hT_lo[o] = __float2bfloat16(lov);
}

// ---------------------------------------------------------------------------
// K2: per-batch c (max of warp maxes) / c2 (min of warp maxes) + factors
// ---------------------------------------------------------------------------
__global__ void __launch_bounds__(256) factors_kernel() {
    __shared__ float red[8];
    int b = blockIdx.x, t = threadIdx.x, w = t >> 5, lane = t & 31;

    float m = -3.4e38f;
    for (int i = t; i < N_; i += 256) m = fmaxf(m, g_s2[b * N_ + i]);
    #pragma unroll
    for (int off = 16; off; off >>= 1) m = fmaxf(m, __shfl_xor_sync(0xffffffffu, m, off));
    if (lane == 0) red[w] = m;
    __syncthreads();
    float c = -3.4e38f, c2 = 3.4e38f;
    #pragma unroll
    for (int q = 0; q < 8; ++q) { c = fmaxf(c, red[q]); c2 = fminf(c2, red[q]); }

    for (int i = t; i < N_; i += 256) {
        int gi = b * N_ + i;
        float s1 = g_s1[gi];
        float u  = s1 + c;
        float u2 = s1 + c2;
        float lr_u  = (u  > 0.f) ? u  : ALPHA_ * u;
        float lr_u2 = (u2 > 0.f) ? u2 : ALPHA_ * u2;
        float mm = fmaxf(lr_u2, lr_u - 60.f);
        g_A [gi] = expf(u - mm);
        g_Ap[gi] = expf(ALPHA_ * u - mm);
        float v = g_s2[gi] - c;
        g_B [gi] = expf(v);
        g_Bp[gi] = expf(ALPHA_ * v);
    }
}

// K2b: reset bad counter (keeps attn as the 4th launch for ncu capture)
__global__ void reset_kernel() { if (threadIdx.x == 0) g_nbad = 0; }

// ---------------------------------------------------------------------------
// K3: attention partials via HMMA, warp-specialized, named-barrier pipeline.
// 256 blocks = 128 tiles(128 rows) x 2 splits; 512 thr = 16 warps.
// warps 0-7: producers (P truncation-split -> smem, H cp.async, denominators).
// warps 8-15: consumers (LDSM + MMA, each m32 x f32, C[2][4][4]).
// FULL_s (id 1+s): producers arrive, consumers sync.
// EMPTY_s (id 3+s): consumers arrive, producers sync before stage reuse.
// ---------------------------------------------------------------------------
static constexpr uint32_t STG    = 49152;   // Phi 16K | Plo 16K | Hhi 8K | Hlo 8K
static constexpr uint32_t O_PHI  = 0;
static constexpr uint32_t O_PLO  = 16384;
static constexpr uint32_t O_HHI  = 32768;
static constexpr uint32_t O_HLO  = 40960;
static constexpr uint32_t OFF_B  = 98304;   // 4KB (JS floats)
static constexpr uint32_t OFF_BP = 102400;  // 4KB
static constexpr uint32_t OFF_A  = 106496;  // 512B
static constexpr uint32_t OFF_AP = 107008;  // 512B
static constexpr uint32_t DSMEM  = 107520;

// truncation split: hi = trunc-bf16(p) (p >= 0), lo = p - hi exact, RN on lo
__device__ __forceinline__ uint32_t prmt_hi(uint32_t u0, uint32_t u1) {
    uint32_t r;
    asm("prmt.b32 %0, %1, %2, 0x7632;" : "=r"(r) : "r"(u0), "r"(u1));
    return r;
}

// Producer: stage H(cidx) via cp.async + produce P(cidx) into stage[cidx&1].
// Called only by threads t < 256.
__device__ __forceinline__ void produce_chunk(
    char* sm, uint32_t sb, const int* __restrict__ adj,
    int i0, int b, int j0, int cidx, int t, int w, int lane,
    const float* sA, const float* sAp, const float* sB, const float* sBp,
    float* lp)
{
    uint32_t stg = sb + (uint32_t)(cidx & 1) * STG;
    char*   stgp = sm + (uint32_t)(cidx & 1) * STG;
    int jc = j0 + cidx * 64;

    // H tiles: 64 f-rows x 64 j bf16 hi/lo, swizzled, via cp.async
    {
        int f = t >> 2, qq = t & 3;
        #pragma unroll
        for (int hp = 0; hp < 2; ++hp) {
            int q2 = qq + hp * 4;
            size_t src = ((size_t)(b * F_ + f)) * N_ + jc + q2 * 8;
            uint32_t sw = ((uint32_t)f * 128 + (uint32_t)q2 * 16) ^ (((uint32_t)(f & 7)) << 4);
            CP16(stg + O_HHI + sw, g_hT_hi + src);
            CP16(stg + O_HLO + sw, g_hT_lo + src);
        }
        CP_COMMIT();
    }

    // P tiles: warp w rows w*16..+15; thread: 4 rows x 8 j
    int rbase = w * 16 + (lane >> 3) * 4;
    int jg = lane & 7;
    float4 Bv0 = *(const float4*)(sB  + cidx * 64 + jg * 8);
    float4 Bv1 = *(const float4*)(sB  + cidx * 64 + jg * 8 + 4);
    float4 Bp0 = *(const float4*)(sBp + cidx * 64 + jg * 8);
    float4 Bp1 = *(const float4*)(sBp + cidx * 64 + jg * 8 + 4);
    #pragma unroll
    for (int rr = 0; rr < 4; ++rr) {
        int R = rbase + rr;
        const int4* ap = (const int4*)(adj + (size_t)(i0 + R) * N_ + jc + jg * 8);
        int4 a0 = __ldcs(ap);
        int4 a1 = __ldcs(ap + 1);
        float Ar = sA[R], Apr = sAp[R];
        float p0 = (a0.x > 0) ? fmaxf(Ar * Bv0.x, Apr * Bp0.x) : 0.f;
        float p1 = (a0.y > 0) ? fmaxf(Ar * Bv0.y, Apr * Bp0.y) : 0.f;
        float p2 = (a0.z > 0) ? fmaxf(Ar * Bv0.z, Apr * Bp0.z) : 0.f;
        float p3 = (a0.w > 0) ? fmaxf(Ar * Bv0.w, Apr * Bp0.w) : 0.f;
        float p4 = (a1.x > 0) ? fmaxf(Ar * Bv1.x, Apr * Bp1.x) : 0.f;
        float p5 = (a1.y > 0) ? fmaxf(Ar * Bv1.y, Apr * Bp1.y) : 0.f;
        float p6 = (a1.z > 0) ? fmaxf(Ar * Bv1.z, Apr * Bp1.z) : 0.f;
        float p7 = (a1.w > 0) ? fmaxf(Ar * Bv1.w, Apr * Bp1.w) : 0.f;
        lp[rr] += ((p0 + p1) + (p2 + p3)) + ((p4 + p5) + (p6 + p7));

        uint32_t u0 = __float_as_uint(p0), u1 = __float_as_uint(p1);
        uint32_t u2 = __float_as_uint(p2), u3 = __float_as_uint(p3);
        uint32_t u4 = __float_as_uint(p4), u5 = __float_as_uint(p5);
        uint32_t u6 = __float_as_uint(p6), u7 = __float_as_uint(p7);
        uint32_t h01 = prmt_hi(u0, u1), h23 = prmt_hi(u2, u3);
        uint32_t h45 = prmt_hi(u4, u5), h67 = prmt_hi(u6, u7);
        float lo0 = p0 - __uint_as_float(u0 & 0xFFFF0000u);
        float lo1 = p1 - __uint_as_float(u1 & 0xFFFF0000u);
        float lo2 = p2 - __uint_as_float(u2 & 0xFFFF0000u);
        float lo3 = p3 - __uint_as_float(u3 & 0xFFFF0000u);
        float lo4 = p4 - __uint_as_float(u4 & 0xFFFF0000u);
        float lo5 = p5 - __uint_as_float(u5 & 0xFFFF0000u);
        float lo6 = p6 - __uint_as_float(u6 & 0xFFFF0000u);
        float lo7 = p7 - __uint_as_float(u7 & 0xFFFF0000u);
        __nv_bfloat162 l01 = __float22bfloat162_rn(make_float2(lo0, lo1));
        __nv_bfloat162 l23 = __float22bfloat162_rn(make_float2(lo2, lo3));
        __nv_bfloat162 l45 = __float22bfloat162_rn(make_float2(lo4, lo5));
        __nv_bfloat162 l67 = __float22bfloat162_rn(make_float2(lo6, lo7));

        uint32_t boff = (uint32_t)R * 128 + (uint32_t)jg * 16;
        uint32_t sw = boff ^ (((uint32_t)(R & 7)) << 4);
        *(uint4*)(stgp + O_PHI + sw) = make_uint4(h01, h23, h45, h67);
        *(uint4*)(stgp + O_PLO + sw) =
            make_uint4(*(uint32_t*)&l01, *(uint32_t*)&l23, *(uint32_t*)&l45, *(uint32_t*)&l67);
    }
    CP_WAIT0();   // my H copies landed before FULL arrive
}

__global__ void __launch_bounds__(512, 2) attn_kernel(const int* __restrict__ adj)
{
    extern __shared__ __align__(128) char sm[];
    uint32_t sb = smem_u32(sm);

    int t = threadIdx.x, w = t >> 5, lane = t & 31;
    int tile = blockIdx.x & 127;
    int s = blockIdx.x >> 7;
    int i0 = tile * TI;
    int b = i0 >> 11;
    int j0 = s * JS;

    float* sA  = (float*)(sm + OFF_A);
    float* sAp = (float*)(sm + OFF_AP);
    float* sB  = (float*)(sm + OFF_B);
    float* sBp = (float*)(sm + OFF_BP);
    if (t < 128) { sA[t] = g_A[i0 + t]; sAp[t] = g_Ap[i0 + t]; }
    #pragma unroll
    for (int k = 0; k < 2; ++k) {
        int u = t + k * 512;
        sB [u] = g_B [b * N_ + j0 + u];
        sBp[u] = g_Bp[b * N_ + j0 + u];
    }
    __syncthreads();

    if (w < 8) {
        // ---------------- producers ----------------
        float lp[4] = {0.f, 0.f, 0.f, 0.f};
        for (int c = 0; c < NCH; ++c) {
            if (c >= 2) BAR_SYNC(3 + (c & 1));         // stage free?
            produce_chunk(sm, sb, adj, i0, b, j0, c, t, w, lane, sA, sAp, sB, sBp, lp);
            BAR_ARRIVE(1 + (c & 1));                   // stage full
        }
        // denominators: reduce over 8 j-lanes (jg = lane&7)
        int rbase = w * 16 + (lane >> 3) * 4;
        #pragma unroll
        for (int rr = 0; rr < 4; ++rr) {
            float v = lp[rr];
            v += __shfl_xor_sync(0xffffffffu, v, 1);
            v += __shfl_xor_sync(0xffffffffu, v, 2);
            v += __shfl_xor_sync(0xffffffffu, v, 4);
            if ((lane & 7) == 0) g_l[s][i0 + rbase + rr] = v;
        }
    } else {
        // ---------------- consumers ----------------
        float C[2][4][4];
        #pragma unroll
        for (int mt = 0; mt < 2; ++mt)
            #pragma unroll
            for (int g = 0; g < 4; ++g)
                #pragma unroll
                for (int qq = 0; qq < 4; ++qq) C[mt][g][qq] = 0.f;

        int cw = w - 8;
        int m0 = (cw & 3) * 32;
        int f0 = (cw >> 2) * 32;

        for (int c = 0; c < NCH; ++c) {
            BAR_SYNC(1 + (c & 1));                     // stage full?
            uint32_t stg = sb + (uint32_t)(c & 1) * STG;
            #pragma unroll
            for (int ks = 0; ks < 4; ++ks) {
                uint32_t ahi[2][4], alo[2][4];
                #pragma unroll
                for (int mt = 0; mt < 2; ++mt) {
                    int arow = m0 + mt * 16 + (lane & 15);
                    uint32_t aoff = (uint32_t)arow * 128 + (uint32_t)ks * 32 + ((uint32_t)(lane >> 4)) * 16;
                    uint32_t asw = aoff ^ (((uint32_t)(arow & 7)) << 4);
                    LDSM4(ahi[mt], stg + O_PHI + asw);
                    LDSM4(alo[mt], stg + O_PLO + asw);
                }
                #pragma unroll
                for (int nb = 0; nb < 2; ++nb) {
                    uint32_t bhi[4], blo[4];
                    int nrow = f0 + nb * 16 + (lane & 15);
                    uint32_t boff = (uint32_t)nrow * 128 + (uint32_t)ks * 32 + ((uint32_t)(lane >> 4)) * 16;
                    uint32_t bsw = boff ^ (((uint32_t)(nrow & 7)) << 4);
                    LDSM4(bhi, stg + O_HHI + bsw);
                    LDSM4(blo, stg + O_HLO + bsw);
                    #pragma unroll
                    for (int mt = 0; mt < 2; ++mt) {
                        MMA_BF16(C[mt][nb * 2],     ahi[mt], bhi[0], bhi[2]);
                        MMA_BF16(C[mt][nb * 2 + 1], ahi[mt], bhi[1], bhi[3]);
                        MMA_BF16(C[mt][nb * 2],     ahi[mt], blo[0], blo[2]);
                        MMA_BF16(C[mt][nb * 2 + 1], ahi[mt], blo[1], blo[3]);
                        MMA_BF16(C[mt][nb * 2],     alo[mt], bhi[0], bhi[2]);
                        MMA_BF16(C[mt][nb * 2 + 1], alo[mt], bhi[1], bhi[3]);
                    }
                }
            }
            BAR_ARRIVE(3 + (c & 1));                   // stage empty
        }

        // C frags -> g_acc
        int fo = f0 + (lane & 3) * 2;
        #pragma unroll
        for (int mt = 0; mt < 2; ++mt) {
            int r0 = i0 + m0 + mt * 16 + (lane >> 2);
            #pragma unroll
            for (int g = 0; g < 4; ++g) {
                float* o = g_acc[s] + (size_t)r0 * F_ + fo + g * 8;
                *(float2*)o = make_float2(C[mt][g][0], C[mt][g][1]);
                *(float2*)(o + 8 * F_) = make_float2(C[mt][g][2], C[mt][g][3]);
            }
        }
    }
}

// ---------------------------------------------------------------------------
// K4: combine splits, normalize, ELU, flag bad rows (float4 per thread)
// ---------------------------------------------------------------------------
__global__ void combine_kernel(float* __restrict__ out) {
    int idx = blockIdx.x * 256 + threadIdx.x;   // B*N*16 threads
    int row = idx >> 4;
    int fo = (idx & 15) * 4;
    float l = g_l[0][row] + g_l[1][row];
    if ((idx & 15) == 0 && !(l >= 1e-20f)) {
        int si = atomicAdd(&g_nbad, 1);
        g_bad[si] = row;
    }
    float inv = 1.f / l;
    size_t o = (size_t)row * F_ + fo;
    float4 u = *(const float4*)(g_acc[0] + o);
    float4 v = *(const float4*)(g_acc[1] + o);
    float4 r;
    r.x = (u.x + v.x) * inv;
    r.y = (u.y + v.y) * inv;
    r.z = (u.z + v.z) * inv;
    r.w = (u.w + v.w) * inv;
    r.x = (r.x > 0.f) ? r.x : (__expf(r.x) - 1.f);
    r.y = (r.y > 0.f) ? r.y : (__expf(r.y) - 1.f);
    r.z = (r.z > 0.f) ? r.z : (__expf(r.z) - 1.f);
    r.w = (r.w > 0.f) ? r.w : (__expf(r.w) - 1.f);
    *(float4*)(out + o) = r;
}

// ---------------------------------------------------------------------------
// K5: exact fp32 recompute of flagged rows
// ---------------------------------------------------------------------------
__global__ void __launch_bounds__(256) fallback_kernel(
    const int* __restrict__ adj, float* __restrict__ out)
{
    __shared__ float p_s[N_];
    __shared__ float red[4][64];
    __shared__ float lred[8];
    int t = threadIdx.x, w = t >> 5, lane = t & 31;
    int nb = g_nbad;
    for (int k = blockIdx.x; k < nb; k += gridDim.x) {
        int row = g_bad[k];
        int b = row >> 11;
        float A = g_A[row], Ap = g_Ap[row];
        float lpv = 0.f;
        for (int j = t; j < N_; j += 256) {
            int av = adj[(size_t)row * N_ + j];
            float p = (av > 0) ? fmaxf(A * g_B[b * N_ + j], Ap * g_Bp[b * N_ + j]) : 0.f;
            p_s[j] = p;
            lpv += p;
        }
        #pragma unroll
        for (int off = 16; off; off >>= 1) lpv += __shfl_xor_sync(0xffffffffu, lpv, off);
        if (lane == 0) lred[w] = lpv;
        __syncthreads();
        float l = 0.f;
        #pragma unroll
        for (int q = 0; q < 8; ++q) l += lred[q];
        int f = t & 63, seg = t >> 6;
        float acc = 0.f;
        const float* hb = g_h + ((size_t)b * N_ + seg * 512) * F_ + f;
        for (int j = 0; j < 512; ++j) acc = fmaf(p_s[seg * 512 + j], hb[(size_t)j * F_], acc);
        red[seg][f] = acc;
        __syncthreads();
        if (t < 64) {
            float v = (red[0][t] + red[1][t] + red[2][t] + red[3][t]) / l;
            out[(size_t)row * F_ + t] = (v > 0.f) ? v : (__expf(v) - 1.f);
        }
        __syncthreads();
    }
}

extern "C" void kernel_launch(void* const* d_in, const int* in_sizes, int n_in,
                              void* d_out, int out_size)
{
    const float* x   = (const float*)d_in[0];
    const int*   adj = (const int*)  d_in[1];
    const float* W   = (const float*)d_in[2];
    const float* a   = (const float*)d_in[3];
    float* out = (float*)d_out;

    cudaFuncSetAttribute(attn_kernel, cudaFuncAttributeMaxDynamicSharedMemorySize, DSMEM);

    prep_kernel<<<(B_ * N_) / 16, 1024>>>(x, W, a);
    factors_kernel<<<B_, 256>>>();
    reset_kernel<<<1, 32>>>();
    attn_kernel<<<(B_ * N_ / TI) * SPLITS, 512, DSMEM>>>(adj);
    combine_kernel<<<(B_ * N_ * 16) / 256, 256>>>(out);
    fallback_kernel<<<64, 256>>>(adj, out);
}

// round 12
// speedup vs baseline: 3.2831x; 1.0207x over previous
#include <cuda_runtime.h>
#include <cuda_bf16.h>
#include <cstdint>

static constexpr int B_ = 8;
static constexpr int N_ = 2048;
static constexpr int F_ = 64;
static constexpr float ALPHA_ = 0.2f;
static constexpr int NCH = N_ / 64;      // 32 chunks, full j-range per block
static constexpr int TI = 64;            // rows per block

// -------- scratch (no cudaMalloc allowed) --------
__device__ float g_h[B_ * N_ * F_];
__device__ float g_s1[B_ * N_];
__device__ float g_s2[B_ * N_];
__device__ float g_A [B_ * N_];
__device__ float g_Ap[B_ * N_];
__device__ float g_B [B_ * N_];
__device__ float g_Bp[B_ * N_];
__device__ __nv_bfloat16 g_hT_hi[B_ * F_ * N_];   // [b][f][n]
__device__ __nv_bfloat16 g_hT_lo[B_ * F_ * N_];
__device__ int g_nbad;
__device__ int g_bad[B_ * N_];

__device__ __forceinline__ uint32_t smem_u32(const void* p) {
    uint32_t a;
    asm("{ .reg .u64 t; cvta.to.shared.u64 t, %1; cvt.u32.u64 %0, t; }" : "=r"(a) : "l"(p));
    return a;
}

#define LDSM4(r, addr) \
    asm volatile("ldmatrix.sync.aligned.m8n8.x4.shared.b16 {%0,%1,%2,%3}, [%4];" \
        : "=r"((r)[0]), "=r"((r)[1]), "=r"((r)[2]), "=r"((r)[3]) : "r"(addr))

#define MMA_BF16(C, a, b0, b1) \
    asm volatile("mma.sync.aligned.m16n8k16.row.col.f32.bf16.bf16.f32 " \
        "{%0,%1,%2,%3}, {%4,%5,%6,%7}, {%8,%9}, {%0,%1,%2,%3};" \
        : "+f"((C)[0]), "+f"((C)[1]), "+f"((C)[2]), "+f"((C)[3]) \
        : "r"((a)[0]), "r"((a)[1]), "r"((a)[2]), "r"((a)[3]), "r"(b0), "r"(b1))

#define CP16(dst, src) \
    asm volatile("cp.async.cg.shared.global [%0], [%1], 16;" :: "r"(dst), "l"(src))
#define CP_COMMIT() asm volatile("cp.async.commit_group;" ::: "memory")
#define CP_WAIT0()  asm volatile("cp.async.wait_group 0;" ::: "memory")

// named block barriers (512 participants: 256 arrivals + 256 syncs)
#define BAR_SYNC(id)   asm volatile("bar.sync %0, 512;"   :: "r"(id) : "memory")
#define BAR_ARRIVE(id) asm volatile("bar.arrive %0, 512;" :: "r"(id) : "memory")

// ---------------------------------------------------------------------------
// K1: h = x@W ; s1,s2 ; transposed bf16 hi/lo copies of h
// ---------------------------------------------------------------------------
__global__ void __launch_bounds__(1024) prep_kernel(
    const float* __restrict__ x, const float* __restrict__ W, const float* __restrict__ a)
{
    __shared__ float W_s[F_ * F_];
    __shared__ float x_s[16][F_];
    __shared__ float h_sh[16][F_ + 1];
    __shared__ float red[16][2][2];

    int t = threadIdx.x, tx = t & 63, ty = t >> 6;
    int row0 = blockIdx.x * 16;
    int row = row0 + ty;

    #pragma unroll
    for (int k = 0; k < 4; ++k) W_s[t + k * 1024] = W[t + k * 1024];
    x_s[ty][tx] = x[(size_t)row * F_ + tx];
    __syncthreads();

    float h = 0.f;
    #pragma unroll
    for (int k = 0; k < F_; ++k) h = fmaf(x_s[ty][k], W_s[k * F_ + tx], h);
    g_h[(size_t)row * F_ + tx] = h;
    h_sh[ty][tx] = h;

    float v1 = h * a[tx];
    float v2 = h * a[F_ + tx];
    #pragma unroll
    for (int off = 16; off; off >>= 1) {
        v1 += __shfl_xor_sync(0xffffffffu, v1, off);
        v2 += __shfl_xor_sync(0xffffffffu, v2, off);
    }
    if ((tx & 31) == 0) { red[ty][tx >> 5][0] = v1; red[ty][tx >> 5][1] = v2; }
    __syncthreads();
    if (tx == 0) {
        g_s1[row] = red[ty][0][0] + red[ty][1][0];
        g_s2[row] = red[ty][0][1] + red[ty][1][1];
    }

    int f = t >> 4, rr = t & 15;
    float v = h_sh[rr][f];
    __nv_bfloat16 hi = __float2bfloat16(v);
    float lov = v - __bfloat162float(hi);
    int b = row0 >> 11;
    size_t o = ((size_t)(b * F_ + f)) * N_ + (row0 & (N_ - 1)) + rr;
    g_hT_hi[o] = hi;
    g_hT_lo[o] = __float2bfloat16(lov);
}

// ---------------------------------------------------------------------------
// K2: per-batch c (max of warp maxes) / c2 (min of warp maxes) + factors
// ---------------------------------------------------------------------------
__global__ void __launch_bounds__(256) factors_kernel() {
    __shared__ float red[8];
    int b = blockIdx.x, t = threadIdx.x, w = t >> 5, lane = t & 31;

    float m = -3.4e38f;
    for (int i = t; i < N_; i += 256) m = fmaxf(m, g_s2[b * N_ + i]);
    #pragma unroll
    for (int off = 16; off; off >>= 1) m = fmaxf(m, __shfl_xor_sync(0xffffffffu, m, off));
    if (lane == 0) red[w] = m;
    __syncthreads();
    float c = -3.4e38f, c2 = 3.4e38f;
    #pragma unroll
    for (int q = 0; q < 8; ++q) { c = fmaxf(c, red[q]); c2 = fminf(c2, red[q]); }

    for (int i = t; i < N_; i += 256) {
        int gi = b * N_ + i;
        float s1 = g_s1[gi];
        float u  = s1 + c;
        float u2 = s1 + c2;
        float lr_u  = (u  > 0.f) ? u  : ALPHA_ * u;
        float lr_u2 = (u2 > 0.f) ? u2 : ALPHA_ * u2;
        float mm = fmaxf(lr_u2, lr_u - 60.f);
        g_A [gi] = expf(u - mm);
        g_Ap[gi] = expf(ALPHA_ * u - mm);
        float v = g_s2[gi] - c;
        g_B [gi] = expf(v);
        g_Bp[gi] = expf(ALPHA_ * v);
    }
}

// K2b: reset bad counter (keeps attn as the 4th launch for ncu capture)
__global__ void reset_kernel() { if (threadIdx.x == 0) g_nbad = 0; }

// ---------------------------------------------------------------------------
// K3: attention via HMMA, warp-specialized, 3-stage named-barrier pipeline.
// 256 blocks = 256 tiles(64 rows) x full N; 512 thr = 16 warps.
// warps 0-7: producers (P truncation-split -> smem, H cp.async, denominators).
// warps 8-15: consumers (LDSM + MMA m16 x f32), direct epilogue to out.
// FULL_s (1+s, s=0..2): producers arrive, consumers sync.
// EMPTY_s (4+s): consumers arrive, producers sync before stage reuse.
// L barrier (7): producers publish per-row denominators to smem.
// ---------------------------------------------------------------------------
static constexpr uint32_t STG    = 32768;   // Phi 8K | Plo 8K | Hhi 8K | Hlo 8K
static constexpr uint32_t O_PHI  = 0;
static constexpr uint32_t O_PLO  = 8192;
static constexpr uint32_t O_HHI  = 16384;
static constexpr uint32_t O_HLO  = 24576;
static constexpr uint32_t OFF_A  = 98304;   // 256B (64 floats)
static constexpr uint32_t OFF_AP = 98560;   // 256B
static constexpr uint32_t OFF_L  = 98816;   // 256B
static constexpr uint32_t DSMEM  = 99072;

// truncation split: hi = trunc-bf16(p) (p >= 0), lo = p - hi exact, RN on lo
__device__ __forceinline__ uint32_t prmt_hi(uint32_t u0, uint32_t u1) {
    uint32_t r;
    asm("prmt.b32 %0, %1, %2, 0x7632;" : "=r"(r) : "r"(u0), "r"(u1));
    return r;
}

// Producer: stage H(cidx) via cp.async + produce P(cidx) into stage[cidx%3].
// Called only by threads t < 256.
__device__ __forceinline__ void produce_chunk(
    char* sm, uint32_t sb, const int* __restrict__ adj,
    int i0, int b, int cidx, int t, int w, int lane,
    const float* sA, const float* sAp, float* lp)
{
    int st = cidx % 3;
    uint32_t stg = sb + (uint32_t)st * STG;
    char*   stgp = sm + (uint32_t)st * STG;
    int jc = cidx * 64;

    // H tiles: 64 f-rows x 64 j bf16 hi/lo, swizzled, via cp.async
    {
        int f = t >> 2;
        int q0 = (t & 3) * 2;
        #pragma unroll
        for (int hp = 0; hp < 2; ++hp) {
            int q2 = q0 + hp;
            size_t src = ((size_t)(b * F_ + f)) * N_ + jc + q2 * 8;
            uint32_t sw = ((uint32_t)f * 128 + (uint32_t)q2 * 16) ^ (((uint32_t)(f & 7)) << 4);
            CP16(stg + O_HHI + sw, g_hT_hi + src);
            CP16(stg + O_HLO + sw, g_hT_lo + src);
        }
        CP_COMMIT();
    }

    // P tiles: warp w rows w*8..+7; thread: 2 rows x 8 j
    int rbase = w * 8 + (lane >> 3) * 2;
    int jg = lane & 7;
    const float4* Bg  = (const float4*)(g_B  + b * N_ + jc + jg * 8);
    const float4* Bpg = (const float4*)(g_Bp + b * N_ + jc + jg * 8);
    float4 Bv0 = __ldg(Bg);
    float4 Bv1 = __ldg(Bg + 1);
    float4 Bp0 = __ldg(Bpg);
    float4 Bp1 = __ldg(Bpg + 1);
    #pragma unroll
    for (int rr = 0; rr < 2; ++rr) {
        int R = rbase + rr;
        const int4* ap = (const int4*)(adj + (size_t)(i0 + R) * N_ + jc + jg * 8);
        int4 a0 = __ldcs(ap);
        int4 a1 = __ldcs(ap + 1);
        float Ar = sA[R], Apr = sAp[R];
        float p0 = (a0.x > 0) ? fmaxf(Ar * Bv0.x, Apr * Bp0.x) : 0.f;
        float p1 = (a0.y > 0) ? fmaxf(Ar * Bv0.y, Apr * Bp0.y) : 0.f;
        float p2 = (a0.z > 0) ? fmaxf(Ar * Bv0.z, Apr * Bp0.z) : 0.f;
        float p3 = (a0.w > 0) ? fmaxf(Ar * Bv0.w, Apr * Bp0.w) : 0.f;
        float p4 = (a1.x > 0) ? fmaxf(Ar * Bv1.x, Apr * Bp1.x) : 0.f;
        float p5 = (a1.y > 0) ? fmaxf(Ar * Bv1.y, Apr * Bp1.y) : 0.f;
        float p6 = (a1.z > 0) ? fmaxf(Ar * Bv1.z, Apr * Bp1.z) : 0.f;
        float p7 = (a1.w > 0) ? fmaxf(Ar * Bv1.w, Apr * Bp1.w) : 0.f;
        lp[rr] += ((p0 + p1) + (p2 + p3)) + ((p4 + p5) + (p6 + p7));

        uint32_t u0 = __float_as_uint(p0), u1 = __float_as_uint(p1);
        uint32_t u2 = __float_as_uint(p2), u3 = __float_as_uint(p3);
        uint32_t u4 = __float_as_uint(p4), u5 = __float_as_uint(p5);
        uint32_t u6 = __float_as_uint(p6), u7 = __float_as_uint(p7);
        uint32_t h01 = prmt_hi(u0, u1), h23 = prmt_hi(u2, u3);
        uint32_t h45 = prmt_hi(u4, u5), h67 = prmt_hi(u6, u7);
        float lo0 = p0 - __uint_as_float(u0 & 0xFFFF0000u);
        float lo1 = p1 - __uint_as_float(u1 & 0xFFFF0000u);
        float lo2 = p2 - __uint_as_float(u2 & 0xFFFF0000u);
        float lo3 = p3 - __uint_as_float(u3 & 0xFFFF0000u);
        float lo4 = p4 - __uint_as_float(u4 & 0xFFFF0000u);
        float lo5 = p5 - __uint_as_float(u5 & 0xFFFF0000u);
        float lo6 = p6 - __uint_as_float(u6 & 0xFFFF0000u);
        float lo7 = p7 - __uint_as_float(u7 & 0xFFFF0000u);
        __nv_bfloat162 l01 = __float22bfloat162_rn(make_float2(lo0, lo1));
        __nv_bfloat162 l23 = __float22bfloat162_rn(make_float2(lo2, lo3));
        __nv_bfloat162 l45 = __float22bfloat162_rn(make_float2(lo4, lo5));
        __nv_bfloat162 l67 = __float22bfloat162_rn(make_float2(lo6, lo7));

        uint32_t boff = (uint32_t)R * 128 + (uint32_t)jg * 16;
        uint32_t sw = boff ^ (((uint32_t)(R & 7)) << 4);
        *(uint4*)(stgp + O_PHI + sw) = make_uint4(h01, h23, h45, h67);
        *(uint4*)(stgp + O_PLO + sw) =
            make_uint4(*(uint32_t*)&l01, *(uint32_t*)&l23, *(uint32_t*)&l45, *(uint32_t*)&l67);
    }
    CP_WAIT0();   // my H copies landed before FULL arrive
}

__global__ void __launch_bounds__(512, 2) attn_kernel(
    const int* __restrict__ adj, float* __restrict__ out)
{
    extern __shared__ __align__(128) char sm[];
    uint32_t sb = smem_u32(sm);

    int t = threadIdx.x, w = t >> 5, lane = t & 31;
    int i0 = blockIdx.x * TI;
    int b = i0 >> 11;

    float* sA  = (float*)(sm + OFF_A);
    float* sAp = (float*)(sm + OFF_AP);
    float* sL  = (float*)(sm + OFF_L);
    if (t < 64) { sA[t] = g_A[i0 + t]; sAp[t] = g_Ap[i0 + t]; }
    __syncthreads();

    if (w < 8) {
        // ---------------- producers ----------------
        float lp[2] = {0.f, 0.f};
        for (int c = 0; c < NCH; ++c) {
            if (c >= 3) BAR_SYNC(4 + (c % 3));         // stage free?
            produce_chunk(sm, sb, adj, i0, b, c, t, w, lane, sA, sAp, lp);
            BAR_ARRIVE(1 + (c % 3));                   // stage full
        }
        // denominators: reduce over 8 j-lanes, publish to sL
        int rbase = w * 8 + (lane >> 3) * 2;
        #pragma unroll
        for (int rr = 0; rr < 2; ++rr) {
            float v = lp[rr];
            v += __shfl_xor_sync(0xffffffffu, v, 1);
            v += __shfl_xor_sync(0xffffffffu, v, 2);
            v += __shfl_xor_sync(0xffffffffu, v, 4);
            if ((lane & 7) == 0) {
                sL[rbase + rr] = v;
                if (!(v >= 1e-20f)) {
                    int si = atomicAdd(&g_nbad, 1);
                    g_bad[si] = i0 + rbase + rr;
                }
            }
        }
        BAR_ARRIVE(7);                                 // denominators ready
    } else {
        // ---------------- consumers ----------------
        float C[4][4];
        #pragma unroll
        for (int g = 0; g < 4; ++g)
            #pragma unroll
            for (int qq = 0; qq < 4; ++qq) C[g][qq] = 0.f;

        int cw = w - 8;
        int m0 = (cw & 3) * 16;
        int f0 = (cw >> 2) * 32;

        for (int c = 0; c < NCH; ++c) {
            BAR_SYNC(1 + (c % 3));                     // stage full?
            uint32_t stg = sb + (uint32_t)(c % 3) * STG;
            #pragma unroll
            for (int ks = 0; ks < 4; ++ks) {
                uint32_t ahi[4], alo[4];
                int arow = m0 + (lane & 15);
                uint32_t aoff = (uint32_t)arow * 128 + (uint32_t)ks * 32 + ((uint32_t)(lane >> 4)) * 16;
                uint32_t asw = aoff ^ (((uint32_t)(arow & 7)) << 4);
                LDSM4(ahi, stg + O_PHI + asw);
                LDSM4(alo, stg + O_PLO + asw);
                #pragma unroll
                for (int nb = 0; nb < 2; ++nb) {
                    uint32_t bhi[4], blo[4];
                    int nrow = f0 + nb * 16 + (lane & 15);
                    uint32_t boff = (uint32_t)nrow * 128 + (uint32_t)ks * 32 + ((uint32_t)(lane >> 4)) * 16;
                    uint32_t bsw = boff ^ (((uint32_t)(nrow & 7)) << 4);
                    LDSM4(bhi, stg + O_HHI + bsw);
                    LDSM4(blo, stg + O_HLO + bsw);
                    MMA_BF16(C[nb * 2],     ahi, bhi[0], bhi[2]);
                    MMA_BF16(C[nb * 2 + 1], ahi, bhi[1], bhi[3]);
                    MMA_BF16(C[nb * 2],     ahi, blo[0], blo[2]);
                    MMA_BF16(C[nb * 2 + 1], ahi, blo[1], blo[3]);
                    MMA_BF16(C[nb * 2],     alo, bhi[0], bhi[2]);
                    MMA_BF16(C[nb * 2 + 1], alo, bhi[1], bhi[3]);
                }
            }
            BAR_ARRIVE(4 + (c % 3));                   // stage empty
        }

        BAR_SYNC(7);                                   // denominators ready

        // epilogue: normalize, ELU, write out directly
        int lr0 = m0 + (lane >> 2);
        float inv0 = 1.f / sL[lr0];
        float inv1 = 1.f / sL[lr0 + 8];
        int fo = f0 + (lane & 3) * 2;
        float* o0 = out + (size_t)(i0 + lr0) * F_ + fo;
        float* o1 = o0 + 8 * F_;
        #pragma unroll
        for (int g = 0; g < 4; ++g) {
            float a0 = C[g][0] * inv0, a1 = C[g][1] * inv0;
            float b0 = C[g][2] * inv1, b1 = C[g][3] * inv1;
            a0 = (a0 > 0.f) ? a0 : (__expf(a0) - 1.f);
            a1 = (a1 > 0.f) ? a1 : (__expf(a1) - 1.f);
            b0 = (b0 > 0.f) ? b0 : (__expf(b0) - 1.f);
            b1 = (b1 > 0.f) ? b1 : (__expf(b1) - 1.f);
            *(float2*)(o0 + g * 8) = make_float2(a0, a1);
            *(float2*)(o1 + g * 8) = make_float2(b0, b1);
        }
    }
}

// ---------------------------------------------------------------------------
// K4: exact fp32 recompute of flagged rows
// ---------------------------------------------------------------------------
__global__ void __launch_bounds__(256) fallback_kernel(
    const int* __restrict__ adj, float* __restrict__ out)
{
    __shared__ float p_s[N_];
    __shared__ float red[4][64];
    __shared__ float lred[8];
    int t = threadIdx.x, w = t >> 5, lane = t & 31;
    int nb = g_nbad;
    for (int k = blockIdx.x; k < nb; k += gridDim.x) {
        int row = g_bad[k];
        int b = row >> 11;
        float A = g_A[row], Ap = g_Ap[row];
        float lpv = 0.f;
        for (int j = t; j < N_; j += 256) {
            int av = adj[(size_t)row * N_ + j];
            float p = (av > 0) ? fmaxf(A * g_B[b * N_ + j], Ap * g_Bp[b * N_ + j]) : 0.f;
            p_s[j] = p;
            lpv += p;
        }
        #pragma unroll
        for (int off = 16; off; off >>= 1) lpv += __shfl_xor_sync(0xffffffffu, lpv, off);
        if (lane == 0) lred[w] = lpv;
        __syncthreads();
        float l = 0.f;
        #pragma unroll
        for (int q = 0; q < 8; ++q) l += lred[q];
        int f = t & 63, seg = t >> 6;
        float acc = 0.f;
        const float* hb = g_h + ((size_t)b * N_ + seg * 512) * F_ + f;
        for (int j = 0; j < 512; ++j) acc = fmaf(p_s[seg * 512 + j], hb[(size_t)j * F_], acc);
        red[seg][f] = acc;
        __syncthreads();
        if (t < 64) {
            float v = (red[0][t] + red[1][t] + red[2][t] + red[3][t]) / l;
            out[(size_t)row * F_ + t] = (v > 0.f) ? v : (__expf(v) - 1.f);
        }
        __syncthreads();
    }
}

extern "C" void kernel_launch(void* const* d_in, const int* in_sizes, int n_in,
                              void* d_out, int out_size)
{
    const float* x   = (const float*)d_in[0];
    const int*   adj = (const int*)  d_in[1];
    const float* W   = (const float*)d_in[2];
    const float* a   = (const float*)d_in[3];
    float* out = (float*)d_out;

    cudaFuncSetAttribute(attn_kernel, cudaFuncAttributeMaxDynamicSharedMemorySize, DSMEM);

    prep_kernel<<<(B_ * N_) / 16, 1024>>>(x, W, a);
    factors_kernel<<<B_, 256>>>();
    reset_kernel<<<1, 32>>>();
    attn_kernel<<<B_ * N_ / TI, 512, DSMEM>>>(adj, out);
    fallback_kernel<<<64, 256>>>(adj, out);
}

// round 13
// speedup vs baseline: 3.5176x; 1.0714x over previous
#include <cuda_runtime.h>
#include <cuda_bf16.h>
#include <cstdint>

static constexpr int B_ = 8;
static constexpr int N_ = 2048;
static constexpr int F_ = 64;
static constexpr float ALPHA_ = 0.2f;
static constexpr int NCH = N_ / 64;      // 32 chunks, full j-range per block
static constexpr int TI = 64;            // rows per block

// -------- scratch (no cudaMalloc allowed) --------
__device__ float g_h[B_ * N_ * F_];
__device__ float g_s1[B_ * N_];
__device__ float g_s2[B_ * N_];
__device__ float g_c[B_];
__device__ float g_c2[B_];
__device__ float g_A [B_ * N_];
__device__ float g_Ap[B_ * N_];
__device__ float g_B [B_ * N_];
__device__ float g_Bp[B_ * N_];
__device__ __nv_bfloat16 g_hT_hi[B_ * F_ * N_];   // [b][f][n]
__device__ __nv_bfloat16 g_hT_lo[B_ * F_ * N_];
__device__ int g_nbad;
__device__ int g_bad[B_ * N_];

__device__ __forceinline__ uint32_t smem_u32(const void* p) {
    uint32_t a;
    asm("{ .reg .u64 t; cvta.to.shared.u64 t, %1; cvt.u32.u64 %0, t; }" : "=r"(a) : "l"(p));
    return a;
}

#define LDSM4(r, addr) \
    asm volatile("ldmatrix.sync.aligned.m8n8.x4.shared.b16 {%0,%1,%2,%3}, [%4];" \
        : "=r"((r)[0]), "=r"((r)[1]), "=r"((r)[2]), "=r"((r)[3]) : "r"(addr))

#define MMA_BF16(C, a, b0, b1) \
    asm volatile("mma.sync.aligned.m16n8k16.row.col.f32.bf16.bf16.f32 " \
        "{%0,%1,%2,%3}, {%4,%5,%6,%7}, {%8,%9}, {%0,%1,%2,%3};" \
        : "+f"((C)[0]), "+f"((C)[1]), "+f"((C)[2]), "+f"((C)[3]) \
        : "r"((a)[0]), "r"((a)[1]), "r"((a)[2]), "r"((a)[3]), "r"(b0), "r"(b1))

#define CP16(dst, src) \
    asm volatile("cp.async.cg.shared.global [%0], [%1], 16;" :: "r"(dst), "l"(src))
#define CP_COMMIT() asm volatile("cp.async.commit_group;" ::: "memory")
#define CP_WAIT0()  asm volatile("cp.async.wait_group 0;" ::: "memory")

// named block barriers (384 participants: 256 producer arrivals + 128 consumer syncs)
#define BAR_SYNC(id)   asm volatile("bar.sync %0, 384;"   :: "r"(id) : "memory")
#define BAR_ARRIVE(id) asm volatile("bar.arrive %0, 384;" :: "r"(id) : "memory")

// ---------------------------------------------------------------------------
// K1: h = x@W ; s1,s2 ; transposed bf16 hi/lo copies of h
// ---------------------------------------------------------------------------
__global__ void __launch_bounds__(1024) prep_kernel(
    const float* __restrict__ x, const float* __restrict__ W, const float* __restrict__ a)
{
    __shared__ float W_s[F_ * F_];
    __shared__ float x_s[16][F_];
    __shared__ float h_sh[16][F_ + 1];
    __shared__ float red[16][2][2];

    int t = threadIdx.x, tx = t & 63, ty = t >> 6;
    int row0 = blockIdx.x * 16;
    int row = row0 + ty;

    #pragma unroll
    for (int k = 0; k < 4; ++k) W_s[t + k * 1024] = W[t + k * 1024];
    x_s[ty][tx] = x[(size_t)row * F_ + tx];
    __syncthreads();

    float h = 0.f;
    #pragma unroll
    for (int k = 0; k < F_; ++k) h = fmaf(x_s[ty][k], W_s[k * F_ + tx], h);
    g_h[(size_t)row * F_ + tx] = h;
    h_sh[ty][tx] = h;

    float v1 = h * a[tx];
    float v2 = h * a[F_ + tx];
    #pragma unroll
    for (int off = 16; off; off >>= 1) {
        v1 += __shfl_xor_sync(0xffffffffu, v1, off);
        v2 += __shfl_xor_sync(0xffffffffu, v2, off);
    }
    if ((tx & 31) == 0) { red[ty][tx >> 5][0] = v1; red[ty][tx >> 5][1] = v2; }
    __syncthreads();
    if (tx == 0) {
        g_s1[row] = red[ty][0][0] + red[ty][1][0];
        g_s2[row] = red[ty][0][1] + red[ty][1][1];
    }

    int f = t >> 4, rr = t & 15;
    float v = h_sh[rr][f];
    __nv_bfloat16 hi = __float2bfloat16(v);
    float lov = v - __bfloat162float(hi);
    int b = row0 >> 11;
    size_t o = ((size_t)(b * F_ + f)) * N_ + (row0 & (N_ - 1)) + rr;
    g_hT_hi[o] = hi;
    g_hT_lo[o] = __float2bfloat16(lov);
}

// ---------------------------------------------------------------------------
// K2: per-batch c (max of warp maxes) / c2 (min of warp maxes); reset counter
// ---------------------------------------------------------------------------
__global__ void __launch_bounds__(256) cmax_kernel() {
    __shared__ float red[8];
    int b = blockIdx.x, t = threadIdx.x, w = t >> 5, lane = t & 31;
    if (b == 0 && t == 0) g_nbad = 0;

    float m = -3.4e38f;
    for (int i = t; i < N_; i += 256) m = fmaxf(m, g_s2[b * N_ + i]);
    #pragma unroll
    for (int off = 16; off; off >>= 1) m = fmaxf(m, __shfl_xor_sync(0xffffffffu, m, off));
    if (lane == 0) red[w] = m;
    __syncthreads();
    if (t == 0) {
        float c = -3.4e38f, c2 = 3.4e38f;
        #pragma unroll
        for (int q = 0; q < 8; ++q) { c = fmaxf(c, red[q]); c2 = fminf(c2, red[q]); }
        g_c[b] = c;
        g_c2[b] = c2;
    }
}

// K2b: factor arrays, full-GPU spread (64 blocks, 1 elt/thread)
__global__ void __launch_bounds__(256) factors_kernel() {
    int i = blockIdx.x * 256 + threadIdx.x;
    int b = i >> 11;
    float c = g_c[b], c2 = g_c2[b];
    float s1 = g_s1[i];
    float u  = s1 + c;
    float u2 = s1 + c2;
    float lr_u  = (u  > 0.f) ? u  : ALPHA_ * u;
    float lr_u2 = (u2 > 0.f) ? u2 : ALPHA_ * u2;
    float mm = fmaxf(lr_u2, lr_u - 60.f);
    g_A [i] = expf(u - mm);
    g_Ap[i] = expf(ALPHA_ * u - mm);
    float v = g_s2[i] - c;
    g_B [i] = expf(v);
    g_Bp[i] = expf(ALPHA_ * v);
}

// ---------------------------------------------------------------------------
// K3: attention via HMMA, warp-specialized, 3-stage named-barrier pipeline.
// 256 blocks = 256 tiles(64 rows) x full N; 384 thr = 12 warps.
// warps 0-7: producers (P truncation-split -> smem, H cp.async, denominators).
// warps 8-11: consumers (LDSM + MMA m32 x f32), direct epilogue to out.
// ---------------------------------------------------------------------------
static constexpr uint32_t STG    = 32768;   // Phi 8K | Plo 8K | Hhi 8K | Hlo 8K
static constexpr uint32_t O_PHI  = 0;
static constexpr uint32_t O_PLO  = 8192;
static constexpr uint32_t O_HHI  = 16384;
static constexpr uint32_t O_HLO  = 24576;
static constexpr uint32_t OFF_A  = 98304;   // 256B (64 floats)
static constexpr uint32_t OFF_AP = 98560;   // 256B
static constexpr uint32_t OFF_L  = 98816;   // 256B
static constexpr uint32_t DSMEM  = 99072;

// truncation split: hi = trunc-bf16(p) (p >= 0), lo = p - hi exact, RN on lo
__device__ __forceinline__ uint32_t prmt_hi(uint32_t u0, uint32_t u1) {
    uint32_t r;
    asm("prmt.b32 %0, %1, %2, 0x7632;" : "=r"(r) : "r"(u0), "r"(u1));
    return r;
}

// Producer: stage H(cidx) via cp.async + produce P(cidx) into stage[cidx%3].
// Called only by threads t < 256.
__device__ __forceinline__ void produce_chunk(
    char* sm, uint32_t sb, const int* __restrict__ adj,
    int i0, int b, int cidx, int t, int w, int lane,
    const float* sA, const float* sAp, float* lp)
{
    int st = cidx % 3;
    uint32_t stg = sb + (uint32_t)st * STG;
    char*   stgp = sm + (uint32_t)st * STG;
    int jc = cidx * 64;

    // H tiles: 64 f-rows x 64 j bf16 hi/lo, swizzled, via cp.async
    {
        int f = t >> 2;
        int q0 = (t & 3) * 2;
        #pragma unroll
        for (int hp = 0; hp < 2; ++hp) {
            int q2 = q0 + hp;
            size_t src = ((size_t)(b * F_ + f)) * N_ + jc + q2 * 8;
            uint32_t sw = ((uint32_t)f * 128 + (uint32_t)q2 * 16) ^ (((uint32_t)(f & 7)) << 4);
            CP16(stg + O_HHI + sw, g_hT_hi + src);
            CP16(stg + O_HLO + sw, g_hT_lo + src);
        }
        CP_COMMIT();
    }

    // P tiles: warp w rows w*8..+7; thread: 2 rows x 8 j
    int rbase = w * 8 + (lane >> 3) * 2;
    int jg = lane & 7;
    const float4* Bg  = (const float4*)(g_B  + b * N_ + jc + jg * 8);
    const float4* Bpg = (const float4*)(g_Bp + b * N_ + jc + jg * 8);
    float4 Bv0 = __ldg(Bg);
    float4 Bv1 = __ldg(Bg + 1);
    float4 Bp0 = __ldg(Bpg);
    float4 Bp1 = __ldg(Bpg + 1);
    #pragma unroll
    for (int rr = 0; rr < 2; ++rr) {
        int R = rbase + rr;
        const int4* ap = (const int4*)(adj + (size_t)(i0 + R) * N_ + jc + jg * 8);
        int4 a0 = __ldcs(ap);
        int4 a1 = __ldcs(ap + 1);
        float Ar = sA[R], Apr = sAp[R];
        float p0 = (a0.x > 0) ? fmaxf(Ar * Bv0.x, Apr * Bp0.x) : 0.f;
        float p1 = (a0.y > 0) ? fmaxf(Ar * Bv0.y, Apr * Bp0.y) : 0.f;
        float p2 = (a0.z > 0) ? fmaxf(Ar * Bv0.z, Apr * Bp0.z) : 0.f;
        float p3 = (a0.w > 0) ? fmaxf(Ar * Bv0.w, Apr * Bp0.w) : 0.f;
        float p4 = (a1.x > 0) ? fmaxf(Ar * Bv1.x, Apr * Bp1.x) : 0.f;
        float p5 = (a1.y > 0) ? fmaxf(Ar * Bv1.y, Apr * Bp1.y) : 0.f;
        float p6 = (a1.z > 0) ? fmaxf(Ar * Bv1.z, Apr * Bp1.z) : 0.f;
        float p7 = (a1.w > 0) ? fmaxf(Ar * Bv1.w, Apr * Bp1.w) : 0.f;
        lp[rr] += ((p0 + p1) + (p2 + p3)) + ((p4 + p5) + (p6 + p7));

        uint32_t u0 = __float_as_uint(p0), u1 = __float_as_uint(p1);
        uint32_t u2 = __float_as_uint(p2), u3 = __float_as_uint(p3);
        uint32_t u4 = __float_as_uint(p4), u5 = __float_as_uint(p5);
        uint32_t u6 = __float_as_uint(p6), u7 = __float_as_uint(p7);
        uint32_t h01 = prmt_hi(u0, u1), h23 = prmt_hi(u2, u3);
        uint32_t h45 = prmt_hi(u4, u5), h67 = prmt_hi(u6, u7);
        float lo0 = p0 - __uint_as_float(u0 & 0xFFFF0000u);
        float lo1 = p1 - __uint_as_float(u1 & 0xFFFF0000u);
        float lo2 = p2 - __uint_as_float(u2 & 0xFFFF0000u);
        float lo3 = p3 - __uint_as_float(u3 & 0xFFFF0000u);
        float lo4 = p4 - __uint_as_float(u4 & 0xFFFF0000u);
        float lo5 = p5 - __uint_as_float(u5 & 0xFFFF0000u);
        float lo6 = p6 - __uint_as_float(u6 & 0xFFFF0000u);
        float lo7 = p7 - __uint_as_float(u7 & 0xFFFF0000u);
        __nv_bfloat162 l01 = __float22bfloat162_rn(make_float2(lo0, lo1));
        __nv_bfloat162 l23 = __float22bfloat162_rn(make_float2(lo2, lo3));
        __nv_bfloat162 l45 = __float22bfloat162_rn(make_float2(lo4, lo5));
        __nv_bfloat162 l67 = __float22bfloat162_rn(make_float2(lo6, lo7));

        uint32_t boff = (uint32_t)R * 128 + (uint32_t)jg * 16;
        uint32_t sw = boff ^ (((uint32_t)(R & 7)) << 4);
        *(uint4*)(stgp + O_PHI + sw) = make_uint4(h01, h23, h45, h67);
        *(uint4*)(stgp + O_PLO + sw) =
            make_uint4(*(uint32_t*)&l01, *(uint32_t*)&l23, *(uint32_t*)&l45, *(uint32_t*)&l67);
    }
    CP_WAIT0();   // my H copies landed before FULL arrive
}

__global__ void __launch_bounds__(384, 2) attn_kernel(
    const int* __restrict__ adj, float* __restrict__ out)
{
    extern __shared__ __align__(128) char sm[];
    uint32_t sb = smem_u32(sm);

    int t = threadIdx.x, w = t >> 5, lane = t & 31;
    int i0 = blockIdx.x * TI;
    int b = i0 >> 11;

    float* sA  = (float*)(sm + OFF_A);
    float* sAp = (float*)(sm + OFF_AP);
    float* sL  = (float*)(sm + OFF_L);
    if (t < 64) { sA[t] = g_A[i0 + t]; sAp[t] = g_Ap[i0 + t]; }
    __syncthreads();

    if (w < 8) {
        // ---------------- producers ----------------
        float lp[2] = {0.f, 0.f};
        for (int c = 0; c < NCH; ++c) {
            if (c >= 3) BAR_SYNC(4 + (c % 3));         // stage free?
            produce_chunk(sm, sb, adj, i0, b, c, t, w, lane, sA, sAp, lp);
            BAR_ARRIVE(1 + (c % 3));                   // stage full
        }
        // denominators: reduce over 8 j-lanes, publish to sL
        int rbase = w * 8 + (lane >> 3) * 2;
        #pragma unroll
        for (int rr = 0; rr < 2; ++rr) {
            float v = lp[rr];
            v += __shfl_xor_sync(0xffffffffu, v, 1);
            v += __shfl_xor_sync(0xffffffffu, v, 2);
            v += __shfl_xor_sync(0xffffffffu, v, 4);
            if ((lane & 7) == 0) {
                sL[rbase + rr] = v;
                if (!(v >= 1e-20f)) {
                    int si = atomicAdd(&g_nbad, 1);
                    g_bad[si] = i0 + rbase + rr;
                }
            }
        }
        BAR_ARRIVE(7);                                 // denominators ready
    } else {
        // ---------------- consumers (4 warps, m32 x f32) ----------------
        float C[2][4][4];
        #pragma unroll
        for (int mt = 0; mt < 2; ++mt)
            #pragma unroll
            for (int g = 0; g < 4; ++g)
                #pragma unroll
                for (int qq = 0; qq < 4; ++qq) C[mt][g][qq] = 0.f;

        int cw = w - 8;
        int m0 = (cw & 1) * 32;
        int f0 = (cw >> 1) * 32;

        for (int c = 0; c < NCH; ++c) {
            BAR_SYNC(1 + (c % 3));                     // stage full?
            uint32_t stg = sb + (uint32_t)(c % 3) * STG;
            #pragma unroll
            for (int ks = 0; ks < 4; ++ks) {
                uint32_t ahi[2][4], alo[2][4];
                #pragma unroll
                for (int mt = 0; mt < 2; ++mt) {
                    int arow = m0 + mt * 16 + (lane & 15);
                    uint32_t aoff = (uint32_t)arow * 128 + (uint32_t)ks * 32 + ((uint32_t)(lane >> 4)) * 16;
                    uint32_t asw = aoff ^ (((uint32_t)(arow & 7)) << 4);
                    LDSM4(ahi[mt], stg + O_PHI + asw);
                    LDSM4(alo[mt], stg + O_PLO + asw);
                }
                #pragma unroll
                for (int nb = 0; nb < 2; ++nb) {
                    uint32_t bhi[4], blo[4];
                    int nrow = f0 + nb * 16 + (lane & 15);
                    uint32_t boff = (uint32_t)nrow * 128 + (uint32_t)ks * 32 + ((uint32_t)(lane >> 4)) * 16;
                    uint32_t bsw = boff ^ (((uint32_t)(nrow & 7)) << 4);
                    LDSM4(bhi, stg + O_HHI + bsw);
                    LDSM4(blo, stg + O_HLO + bsw);
                    #pragma unroll
                    for (int mt = 0; mt < 2; ++mt) {
                        MMA_BF16(C[mt][nb * 2],     ahi[mt], bhi[0], bhi[2]);
                        MMA_BF16(C[mt][nb * 2 + 1], ahi[mt], bhi[1], bhi[3]);
                        MMA_BF16(C[mt][nb * 2],     ahi[mt], blo[0], blo[2]);
                        MMA_BF16(C[mt][nb * 2 + 1], ahi[mt], blo[1], blo[3]);
                        MMA_BF16(C[mt][nb * 2],     alo[mt], bhi[0], bhi[2]);
                        MMA_BF16(C[mt][nb * 2 + 1], alo[mt], bhi[1], bhi[3]);
                    }
                }
            }
            BAR_ARRIVE(4 + (c % 3));                   // stage empty
        }

        BAR_SYNC(7);                                   // denominators ready

        // epilogue: normalize, ELU, write out directly
        int fo = f0 + (lane & 3) * 2;
        #pragma unroll
        for (int mt = 0; mt < 2; ++mt) {
            int lr0 = m0 + mt * 16 + (lane >> 2);
            float inv0 = 1.f / sL[lr0];
            float inv1 = 1.f / sL[lr0 + 8];
            float* o0 = out + (size_t)(i0 + lr0) * F_ + fo;
            float* o1 = o0 + 8 * F_;
            #pragma unroll
            for (int g = 0; g < 4; ++g) {
                float a0 = C[mt][g][0] * inv0, a1 = C[mt][g][1] * inv0;
                float b0 = C[mt][g][2] * inv1, b1 = C[mt][g][3] * inv1;
                a0 = (a0 > 0.f) ? a0 : (__expf(a0) - 1.f);
                a1 = (a1 > 0.f) ? a1 : (__expf(a1) - 1.f);
                b0 = (b0 > 0.f) ? b0 : (__expf(b0) - 1.f);
                b1 = (b1 > 0.f) ? b1 : (__expf(b1) - 1.f);
                *(float2*)(o0 + g * 8) = make_float2(a0, a1);
                *(float2*)(o1 + g * 8) = make_float2(b0, b1);
            }
        }
    }
}

// ---------------------------------------------------------------------------
// K4: exact fp32 recompute of flagged rows
// ---------------------------------------------------------------------------
__global__ void __launch_bounds__(256) fallback_kernel(
    const int* __restrict__ adj, float* __restrict__ out)
{
    __shared__ float p_s[N_];
    __shared__ float red[4][64];
    __shared__ float lred[8];
    int t = threadIdx.x, w = t >> 5, lane = t & 31;
    int nb = g_nbad;
    for (int k = blockIdx.x; k < nb; k += gridDim.x) {
        int row = g_bad[k];
        int b = row >> 11;
        float A = g_A[row], Ap = g_Ap[row];
        float lpv = 0.f;
        for (int j = t; j < N_; j += 256) {
            int av = adj[(size_t)row * N_ + j];
            float p = (av > 0) ? fmaxf(A * g_B[b * N_ + j], Ap * g_Bp[b * N_ + j]) : 0.f;
            p_s[j] = p;
            lpv += p;
        }
        #pragma unroll
        for (int off = 16; off; off >>= 1) lpv += __shfl_xor_sync(0xffffffffu, lpv, off);
        if (lane == 0) lred[w] = lpv;
        __syncthreads();
        float l = 0.f;
        #pragma unroll
        for (int q = 0; q < 8; ++q) l += lred[q];
        int f = t & 63, seg = t >> 6;
        float acc = 0.f;
        const float* hb = g_h + ((size_t)b * N_ + seg * 512) * F_ + f;
        for (int j = 0; j < 512; ++j) acc = fmaf(p_s[seg * 512 + j], hb[(size_t)j * F_], acc);
        red[seg][f] = acc;
        __syncthreads();
        if (t < 64) {
            float v = (red[0][t] + red[1][t] + red[2][t] + red[3][t]) / l;
            out[(size_t)row * F_ + t] = (v > 0.f) ? v : (__expf(v) - 1.f);
        }
        __syncthreads();
    }
}

extern "C" void kernel_launch(void* const* d_in, const int* in_sizes, int n_in,
                              void* d_out, int out_size)
{
    const float* x   = (const float*)d_in[0];
    const int*   adj = (const int*)  d_in[1];
    const float* W   = (const float*)d_in[2];
    const float* a   = (const float*)d_in[3];
    float* out = (float*)d_out;

    cudaFuncSetAttribute(attn_kernel, cudaFuncAttributeMaxDynamicSharedMemorySize, DSMEM);

    prep_kernel<<<(B_ * N_) / 16, 1024>>>(x, W, a);
    cmax_kernel<<<B_, 256>>>();
    factors_kernel<<<(B_ * N_) / 256, 256>>>();
    attn_kernel<<<B_ * N_ / TI, 384, DSMEM>>>(adj, out);
    fallback_kernel<<<64, 256>>>(adj, out);
}